// round 1
// baseline (speedup 1.0000x reference)
#include <cuda_runtime.h>
#include <math.h>

#define DIM 768
#define HEADS 12
#define HD 64
#define HIDDEN 3072
#define QKV_N 2304
#define MAX_ROWS 4096
#define SCALE 0.125f

// ---------------- scratch (no allocation allowed) ----------------
__device__ float g_h[MAX_ROWS * DIM];       // LN output (reused for ln1 and ln2)
__device__ float g_qkv[MAX_ROWS * QKV_N];   // qkv projection
__device__ float g_attn[MAX_ROWS * DIM];    // attention output (pre-proj)
__device__ float g_x2[MAX_ROWS * DIM];      // x + attn@proj + b
__device__ float g_ff[MAX_ROWS * HIDDEN];   // gelu(fc1) output

// ---------------- LayerNorm: one block per row ----------------
__global__ __launch_bounds__(256)
void ln_kernel(const float* __restrict__ x, const float* __restrict__ g,
               const float* __restrict__ bta, float* __restrict__ out)
{
    const int row = blockIdx.x;
    const float* xr = x + (size_t)row * DIM;
    const int tid = threadIdx.x;

    float v[3];
    float s = 0.f, s2 = 0.f;
    #pragma unroll
    for (int k = 0; k < 3; k++) {
        float t = xr[tid + 256 * k];
        v[k] = t; s += t; s2 += t * t;
    }
    // warp reduce
    #pragma unroll
    for (int off = 16; off; off >>= 1) {
        s  += __shfl_down_sync(0xffffffffu, s,  off);
        s2 += __shfl_down_sync(0xffffffffu, s2, off);
    }
    __shared__ float red[2][8];
    const int wid = tid >> 5, lid = tid & 31;
    if (lid == 0) { red[0][wid] = s; red[1][wid] = s2; }
    __syncthreads();
    __shared__ float s_mu, s_inv;
    if (tid == 0) {
        float ts = 0.f, ts2 = 0.f;
        #pragma unroll
        for (int w = 0; w < 8; w++) { ts += red[0][w]; ts2 += red[1][w]; }
        float mu = ts * (1.0f / DIM);
        float var = ts2 * (1.0f / DIM) - mu * mu;
        s_mu = mu;
        s_inv = rsqrtf(var + 1e-5f);
    }
    __syncthreads();
    const float mu = s_mu, inv = s_inv;
    float* outr = out + (size_t)row * DIM;
    #pragma unroll
    for (int k = 0; k < 3; k++) {
        int c = tid + 256 * k;
        outr[c] = (v[k] - mu) * inv * g[c] + bta[c];
    }
}

// ---------------- Tiled GEMM: C[M,N] = A[M,K] @ W[K,N] + bias (+epilogue) ----------------
// EPI: 0 = bias only, 1 = bias + residual, 2 = bias + exact GELU
template<int EPI>
__global__ __launch_bounds__(256)
void gemm_kernel(const float* __restrict__ A, const float* __restrict__ W,
                 const float* __restrict__ bias, const float* __restrict__ res,
                 float* __restrict__ C, int M, int N, int K)
{
    __shared__ float As[16][65];   // [k][m], padded against bank conflicts
    __shared__ float Ws[16][64];   // [k][n]
    const int tid = threadIdx.x;
    const int tx = tid & 15, ty = tid >> 4;
    const int m0 = blockIdx.y << 6, n0 = blockIdx.x << 6;

    float acc[4][4];
    #pragma unroll
    for (int i = 0; i < 4; i++)
        #pragma unroll
        for (int j = 0; j < 4; j++) acc[i][j] = 0.f;

    for (int k0 = 0; k0 < K; k0 += 16) {
        #pragma unroll
        for (int it = 0; it < 4; it++) {
            int idx = tid + (it << 8);
            int m = idx >> 4, kk = idx & 15;
            As[kk][m] = A[(size_t)(m0 + m) * K + k0 + kk];
        }
        #pragma unroll
        for (int it = 0; it < 4; it++) {
            int idx = tid + (it << 8);
            int kk = idx >> 6, n = idx & 63;
            Ws[kk][n] = W[(size_t)(k0 + kk) * N + n0 + n];
        }
        __syncthreads();
        #pragma unroll
        for (int kk = 0; kk < 16; kk++) {
            float4 bv = *(const float4*)&Ws[kk][tx << 2];
            float a0 = As[kk][(ty << 2) + 0];
            float a1 = As[kk][(ty << 2) + 1];
            float a2 = As[kk][(ty << 2) + 2];
            float a3 = As[kk][(ty << 2) + 3];
            acc[0][0] = fmaf(a0, bv.x, acc[0][0]); acc[0][1] = fmaf(a0, bv.y, acc[0][1]);
            acc[0][2] = fmaf(a0, bv.z, acc[0][2]); acc[0][3] = fmaf(a0, bv.w, acc[0][3]);
            acc[1][0] = fmaf(a1, bv.x, acc[1][0]); acc[1][1] = fmaf(a1, bv.y, acc[1][1]);
            acc[1][2] = fmaf(a1, bv.z, acc[1][2]); acc[1][3] = fmaf(a1, bv.w, acc[1][3]);
            acc[2][0] = fmaf(a2, bv.x, acc[2][0]); acc[2][1] = fmaf(a2, bv.y, acc[2][1]);
            acc[2][2] = fmaf(a2, bv.z, acc[2][2]); acc[2][3] = fmaf(a2, bv.w, acc[2][3]);
            acc[3][0] = fmaf(a3, bv.x, acc[3][0]); acc[3][1] = fmaf(a3, bv.y, acc[3][1]);
            acc[3][2] = fmaf(a3, bv.z, acc[3][2]); acc[3][3] = fmaf(a3, bv.w, acc[3][3]);
        }
        __syncthreads();
    }

    #pragma unroll
    for (int i = 0; i < 4; i++) {
        int row = m0 + (ty << 2) + i;
        #pragma unroll
        for (int j = 0; j < 4; j++) {
            int col = n0 + (tx << 2) + j;
            float v = acc[i][j] + bias[col];
            if (EPI == 1) v += res[(size_t)row * N + col];
            if (EPI == 2) v = 0.5f * v * (1.0f + erff(v * 0.70710678118654752f));
            C[(size_t)row * N + col] = v;
        }
    }
}

// ---------------- Fused masked attention ----------------
// One thread owns one query row; block = 128 query rows for one (batch, head).
// Online softmax tracking both sum(exp) and sum(exp*mask) so the reference's
// exact renormalization  w = softmax*mask / (sum(softmax*mask) + 1e-8)
// is reproduced: w_ij = e_ij*mask_ij / (l_mask + 1e-8 * l_plain).
#define BM 128
#define BK 64
__global__ __launch_bounds__(128)
void attn_kernel(const float* __restrict__ qkv, const float* __restrict__ elev,
                 const float* __restrict__ barrier, float* __restrict__ out, int Nlen)
{
    __shared__ float Ks[BK][HD];
    __shared__ float Vs[BK][HD];
    __shared__ float es[BK];

    const int bh = blockIdx.x;
    const int b = bh / HEADS, h = bh % HEADS;
    const int tid = threadIdx.x;
    const int i = blockIdx.y * BM + tid;
    const int rowbase = b * Nlen;
    const float bar = *barrier;

    // load this thread's q row into registers
    float q[HD];
    const float4* qp = (const float4*)(qkv + (size_t)(rowbase + i) * QKV_N + h * HD);
    #pragma unroll
    for (int dd = 0; dd < 16; dd++) {
        float4 t = qp[dd];
        q[4 * dd + 0] = t.x; q[4 * dd + 1] = t.y; q[4 * dd + 2] = t.z; q[4 * dd + 3] = t.w;
    }
    const float e_i = elev[rowbase + i];

    float m = -1e30f, lp = 0.f, lm = 0.f;
    float o[HD];
    #pragma unroll
    for (int d = 0; d < HD; d++) o[d] = 0.f;

    for (int j0 = 0; j0 < Nlen; j0 += BK) {
        __syncthreads();
        // stage K/V tile (coalesced float4)
        for (int idx = tid; idx < BK * 16; idx += 128) {
            int r = idx >> 4, c = idx & 15;
            const float4* kp = (const float4*)(qkv + (size_t)(rowbase + j0 + r) * QKV_N + DIM + h * HD);
            const float4* vp = (const float4*)(qkv + (size_t)(rowbase + j0 + r) * QKV_N + 2 * DIM + h * HD);
            ((float4*)&Ks[r][0])[c] = kp[c];
            ((float4*)&Vs[r][0])[c] = vp[c];
        }
        if (tid < BK) es[tid] = elev[rowbase + j0 + tid];
        __syncthreads();

        for (int j = 0; j < BK; j++) {
            float s = 0.f;
            const float4* kr = (const float4*)&Ks[j][0];
            #pragma unroll
            for (int dd = 0; dd < 16; dd++) {
                float4 kv = kr[dd];
                s = fmaf(q[4 * dd + 0], kv.x, s);
                s = fmaf(q[4 * dd + 1], kv.y, s);
                s = fmaf(q[4 * dd + 2], kv.z, s);
                s = fmaf(q[4 * dd + 3], kv.w, s);
            }
            s *= SCALE;
            float diff = es[j] - e_i;
            float mask = 1.0f / (1.0f + __expf(bar * diff));
            mask = fminf(fmaxf(mask, 1e-6f), 1.0f);

            float p;
            if (s > m) {
                float alpha = __expf(m - s);
                lp *= alpha; lm *= alpha;
                #pragma unroll
                for (int d = 0; d < HD; d++) o[d] *= alpha;
                m = s;
                p = 1.0f;
            } else {
                p = __expf(s - m);
            }
            float pm = p * mask;
            lp += p; lm += pm;
            const float4* vr = (const float4*)&Vs[j][0];
            #pragma unroll
            for (int dd = 0; dd < 16; dd++) {
                float4 vv = vr[dd];
                o[4 * dd + 0] = fmaf(pm, vv.x, o[4 * dd + 0]);
                o[4 * dd + 1] = fmaf(pm, vv.y, o[4 * dd + 1]);
                o[4 * dd + 2] = fmaf(pm, vv.z, o[4 * dd + 2]);
                o[4 * dd + 3] = fmaf(pm, vv.w, o[4 * dd + 3]);
            }
        }
    }

    const float inv = 1.0f / (lm + 1e-8f * lp);
    float* op = out + (size_t)(rowbase + i) * DIM + h * HD;
    #pragma unroll
    for (int d = 0; d < HD; d++) op[d] = o[d] * inv;
}

// ---------------- launch ----------------
extern "C" void kernel_launch(void* const* d_in, const int* in_sizes, int n_in,
                              void* d_out, int out_size)
{
    const float* x      = (const float*)d_in[0];
    const float* elev   = (const float*)d_in[1];
    const float* qkv_w  = (const float*)d_in[2];
    const float* qkv_b  = (const float*)d_in[3];
    const float* proj_w = (const float*)d_in[4];
    const float* proj_b = (const float*)d_in[5];
    const float* ln1_g  = (const float*)d_in[6];
    const float* ln1_b  = (const float*)d_in[7];
    const float* ln2_g  = (const float*)d_in[8];
    const float* ln2_b  = (const float*)d_in[9];
    const float* fc1_w  = (const float*)d_in[10];
    const float* fc1_b  = (const float*)d_in[11];
    const float* fc2_w  = (const float*)d_in[12];
    const float* fc2_b  = (const float*)d_in[13];
    const float* barrier= (const float*)d_in[14];
    float* out = (float*)d_out;

    const int rows = in_sizes[0] / DIM;     // B*N
    const int Nlen = 2048;
    const int B = rows / Nlen;

    float *h, *qkv, *attn, *x2, *ff;
    cudaGetSymbolAddress((void**)&h,    g_h);
    cudaGetSymbolAddress((void**)&qkv,  g_qkv);
    cudaGetSymbolAddress((void**)&attn, g_attn);
    cudaGetSymbolAddress((void**)&x2,   g_x2);
    cudaGetSymbolAddress((void**)&ff,   g_ff);

    // 1. LN1
    ln_kernel<<<rows, 256>>>(x, ln1_g, ln1_b, h);
    // 2. QKV projection
    gemm_kernel<0><<<dim3(QKV_N / 64, rows / 64), 256>>>(h, qkv_w, qkv_b, nullptr, qkv, rows, QKV_N, DIM);
    // 3. fused masked attention
    attn_kernel<<<dim3(B * HEADS, Nlen / BM), 128>>>(qkv, elev, barrier, attn, Nlen);
    // 4. out proj + residual
    gemm_kernel<1><<<dim3(DIM / 64, rows / 64), 256>>>(attn, proj_w, proj_b, x, x2, rows, DIM, DIM);
    // 5. LN2
    ln_kernel<<<rows, 256>>>(x2, ln2_g, ln2_b, h);
    // 6. FC1 + exact GELU
    gemm_kernel<2><<<dim3(HIDDEN / 64, rows / 64), 256>>>(h, fc1_w, fc1_b, nullptr, ff, rows, HIDDEN, DIM);
    // 7. FC2 + residual -> output
    gemm_kernel<1><<<dim3(DIM / 64, rows / 64), 256>>>(ff, fc2_w, fc2_b, x2, out, rows, DIM, HIDDEN);
}

// round 2
// speedup vs baseline: 1.0010x; 1.0010x over previous
#include <cuda_runtime.h>
#include <math.h>

#define DIM 768
#define HEADS 12
#define HD 64
#define HIDDEN 3072
#define QKV_N 2304
#define MAX_ROWS 4096
#define SCALE 0.125f

// ---------------- scratch (no allocation allowed) ----------------
__device__ float g_h[MAX_ROWS * DIM];       // LN output (reused for ln1 and ln2)
__device__ float g_qkv[MAX_ROWS * QKV_N];   // qkv projection
__device__ float g_attn[MAX_ROWS * DIM];    // attention output (pre-proj)
__device__ float g_x2[MAX_ROWS * DIM];      // x + attn@proj + b
__device__ float g_ff[MAX_ROWS * HIDDEN];   // gelu(fc1) output

// ---------------- LayerNorm: one block per row ----------------
__global__ __launch_bounds__(256)
void ln_kernel(const float* __restrict__ x, const float* __restrict__ g,
               const float* __restrict__ bta, float* __restrict__ out)
{
    const int row = blockIdx.x;
    const float* xr = x + (size_t)row * DIM;
    const int tid = threadIdx.x;

    float v[3];
    float s = 0.f, s2 = 0.f;
    #pragma unroll
    for (int k = 0; k < 3; k++) {
        float t = xr[tid + 256 * k];
        v[k] = t; s += t; s2 += t * t;
    }
    // warp reduce
    #pragma unroll
    for (int off = 16; off; off >>= 1) {
        s  += __shfl_down_sync(0xffffffffu, s,  off);
        s2 += __shfl_down_sync(0xffffffffu, s2, off);
    }
    __shared__ float red[2][8];
    const int wid = tid >> 5, lid = tid & 31;
    if (lid == 0) { red[0][wid] = s; red[1][wid] = s2; }
    __syncthreads();
    __shared__ float s_mu, s_inv;
    if (tid == 0) {
        float ts = 0.f, ts2 = 0.f;
        #pragma unroll
        for (int w = 0; w < 8; w++) { ts += red[0][w]; ts2 += red[1][w]; }
        float mu = ts * (1.0f / DIM);
        float var = ts2 * (1.0f / DIM) - mu * mu;
        s_mu = mu;
        s_inv = rsqrtf(var + 1e-5f);
    }
    __syncthreads();
    const float mu = s_mu, inv = s_inv;
    float* outr = out + (size_t)row * DIM;
    #pragma unroll
    for (int k = 0; k < 3; k++) {
        int c = tid + 256 * k;
        outr[c] = (v[k] - mu) * inv * g[c] + bta[c];
    }
}

// ---------------- Tiled GEMM: C[M,N] = A[M,K] @ W[K,N] + bias (+epilogue) ----------------
// EPI: 0 = bias only, 1 = bias + residual, 2 = bias + exact GELU
template<int EPI>
__global__ __launch_bounds__(256)
void gemm_kernel(const float* __restrict__ A, const float* __restrict__ W,
                 const float* __restrict__ bias, const float* __restrict__ res,
                 float* __restrict__ C, int M, int N, int K)
{
    __shared__ float As[16][65];   // [k][m], padded against bank conflicts
    __shared__ float Ws[16][64];   // [k][n]
    const int tid = threadIdx.x;
    const int tx = tid & 15, ty = tid >> 4;
    const int m0 = blockIdx.y << 6, n0 = blockIdx.x << 6;

    float acc[4][4];
    #pragma unroll
    for (int i = 0; i < 4; i++)
        #pragma unroll
        for (int j = 0; j < 4; j++) acc[i][j] = 0.f;

    for (int k0 = 0; k0 < K; k0 += 16) {
        #pragma unroll
        for (int it = 0; it < 4; it++) {
            int idx = tid + (it << 8);
            int m = idx >> 4, kk = idx & 15;
            As[kk][m] = A[(size_t)(m0 + m) * K + k0 + kk];
        }
        #pragma unroll
        for (int it = 0; it < 4; it++) {
            int idx = tid + (it << 8);
            int kk = idx >> 6, n = idx & 63;
            Ws[kk][n] = W[(size_t)(k0 + kk) * N + n0 + n];
        }
        __syncthreads();
        #pragma unroll
        for (int kk = 0; kk < 16; kk++) {
            float4 bv = *(const float4*)&Ws[kk][tx << 2];
            float a0 = As[kk][(ty << 2) + 0];
            float a1 = As[kk][(ty << 2) + 1];
            float a2 = As[kk][(ty << 2) + 2];
            float a3 = As[kk][(ty << 2) + 3];
            acc[0][0] = fmaf(a0, bv.x, acc[0][0]); acc[0][1] = fmaf(a0, bv.y, acc[0][1]);
            acc[0][2] = fmaf(a0, bv.z, acc[0][2]); acc[0][3] = fmaf(a0, bv.w, acc[0][3]);
            acc[1][0] = fmaf(a1, bv.x, acc[1][0]); acc[1][1] = fmaf(a1, bv.y, acc[1][1]);
            acc[1][2] = fmaf(a1, bv.z, acc[1][2]); acc[1][3] = fmaf(a1, bv.w, acc[1][3]);
            acc[2][0] = fmaf(a2, bv.x, acc[2][0]); acc[2][1] = fmaf(a2, bv.y, acc[2][1]);
            acc[2][2] = fmaf(a2, bv.z, acc[2][2]); acc[2][3] = fmaf(a2, bv.w, acc[2][3]);
            acc[3][0] = fmaf(a3, bv.x, acc[3][0]); acc[3][1] = fmaf(a3, bv.y, acc[3][1]);
            acc[3][2] = fmaf(a3, bv.z, acc[3][2]); acc[3][3] = fmaf(a3, bv.w, acc[3][3]);
        }
        __syncthreads();
    }

    #pragma unroll
    for (int i = 0; i < 4; i++) {
        int row = m0 + (ty << 2) + i;
        #pragma unroll
        for (int j = 0; j < 4; j++) {
            int col = n0 + (tx << 2) + j;
            float v = acc[i][j] + bias[col];
            if (EPI == 1) v += res[(size_t)row * N + col];
            if (EPI == 2) v = 0.5f * v * (1.0f + erff(v * 0.70710678118654752f));
            C[(size_t)row * N + col] = v;
        }
    }
}

// ---------------- Fused masked attention ----------------
// One thread owns one query row; block = 128 query rows for one (batch, head).
// Online softmax tracking both sum(exp) and sum(exp*mask) so the reference's
// exact renormalization  w = softmax*mask / (sum(softmax*mask) + 1e-8)
// is reproduced: w_ij = e_ij*mask_ij / (l_mask + 1e-8 * l_plain).
#define BM 128
#define BK 64
__global__ __launch_bounds__(128)
void attn_kernel(const float* __restrict__ qkv, const float* __restrict__ elev,
                 const float* __restrict__ barrier, float* __restrict__ out, int Nlen)
{
    __shared__ float Ks[BK][HD];
    __shared__ float Vs[BK][HD];
    __shared__ float es[BK];

    const int bh = blockIdx.x;
    const int b = bh / HEADS, h = bh % HEADS;
    const int tid = threadIdx.x;
    const int i = blockIdx.y * BM + tid;
    const int rowbase = b * Nlen;
    const float bar = *barrier;

    // load this thread's q row into registers
    float q[HD];
    const float4* qp = (const float4*)(qkv + (size_t)(rowbase + i) * QKV_N + h * HD);
    #pragma unroll
    for (int dd = 0; dd < 16; dd++) {
        float4 t = qp[dd];
        q[4 * dd + 0] = t.x; q[4 * dd + 1] = t.y; q[4 * dd + 2] = t.z; q[4 * dd + 3] = t.w;
    }
    const float e_i = elev[rowbase + i];

    float m = -1e30f, lp = 0.f, lm = 0.f;
    float o[HD];
    #pragma unroll
    for (int d = 0; d < HD; d++) o[d] = 0.f;

    for (int j0 = 0; j0 < Nlen; j0 += BK) {
        __syncthreads();
        // stage K/V tile (coalesced float4)
        for (int idx = tid; idx < BK * 16; idx += 128) {
            int r = idx >> 4, c = idx & 15;
            const float4* kp = (const float4*)(qkv + (size_t)(rowbase + j0 + r) * QKV_N + DIM + h * HD);
            const float4* vp = (const float4*)(qkv + (size_t)(rowbase + j0 + r) * QKV_N + 2 * DIM + h * HD);
            ((float4*)&Ks[r][0])[c] = kp[c];
            ((float4*)&Vs[r][0])[c] = vp[c];
        }
        if (tid < BK) es[tid] = elev[rowbase + j0 + tid];
        __syncthreads();

        for (int j = 0; j < BK; j++) {
            float s = 0.f;
            const float4* kr = (const float4*)&Ks[j][0];
            #pragma unroll
            for (int dd = 0; dd < 16; dd++) {
                float4 kv = kr[dd];
                s = fmaf(q[4 * dd + 0], kv.x, s);
                s = fmaf(q[4 * dd + 1], kv.y, s);
                s = fmaf(q[4 * dd + 2], kv.z, s);
                s = fmaf(q[4 * dd + 3], kv.w, s);
            }
            s *= SCALE;
            float diff = es[j] - e_i;
            float mask = 1.0f / (1.0f + __expf(bar * diff));
            mask = fminf(fmaxf(mask, 1e-6f), 1.0f);

            float p;
            if (s > m) {
                float alpha = __expf(m - s);
                lp *= alpha; lm *= alpha;
                #pragma unroll
                for (int d = 0; d < HD; d++) o[d] *= alpha;
                m = s;
                p = 1.0f;
            } else {
                p = __expf(s - m);
            }
            float pm = p * mask;
            lp += p; lm += pm;
            const float4* vr = (const float4*)&Vs[j][0];
            #pragma unroll
            for (int dd = 0; dd < 16; dd++) {
                float4 vv = vr[dd];
                o[4 * dd + 0] = fmaf(pm, vv.x, o[4 * dd + 0]);
                o[4 * dd + 1] = fmaf(pm, vv.y, o[4 * dd + 1]);
                o[4 * dd + 2] = fmaf(pm, vv.z, o[4 * dd + 2]);
                o[4 * dd + 3] = fmaf(pm, vv.w, o[4 * dd + 3]);
            }
        }
    }

    const float inv = 1.0f / (lm + 1e-8f * lp);
    float* op = out + (size_t)(rowbase + i) * DIM + h * HD;
    #pragma unroll
    for (int d = 0; d < HD; d++) op[d] = o[d] * inv;
}

// ---------------- launch ----------------
extern "C" void kernel_launch(void* const* d_in, const int* in_sizes, int n_in,
                              void* d_out, int out_size)
{
    const float* x      = (const float*)d_in[0];
    const float* elev   = (const float*)d_in[1];
    const float* qkv_w  = (const float*)d_in[2];
    const float* qkv_b  = (const float*)d_in[3];
    const float* proj_w = (const float*)d_in[4];
    const float* proj_b = (const float*)d_in[5];
    const float* ln1_g  = (const float*)d_in[6];
    const float* ln1_b  = (const float*)d_in[7];
    const float* ln2_g  = (const float*)d_in[8];
    const float* ln2_b  = (const float*)d_in[9];
    const float* fc1_w  = (const float*)d_in[10];
    const float* fc1_b  = (const float*)d_in[11];
    const float* fc2_w  = (const float*)d_in[12];
    const float* fc2_b  = (const float*)d_in[13];
    const float* barrier= (const float*)d_in[14];
    float* out = (float*)d_out;

    const int rows = in_sizes[0] / DIM;     // B*N
    const int Nlen = 2048;
    const int B = rows / Nlen;

    float *h, *qkv, *attn, *x2, *ff;
    cudaGetSymbolAddress((void**)&h,    g_h);
    cudaGetSymbolAddress((void**)&qkv,  g_qkv);
    cudaGetSymbolAddress((void**)&attn, g_attn);
    cudaGetSymbolAddress((void**)&x2,   g_x2);
    cudaGetSymbolAddress((void**)&ff,   g_ff);

    // 1. LN1
    ln_kernel<<<rows, 256>>>(x, ln1_g, ln1_b, h);
    // 2. QKV projection
    gemm_kernel<0><<<dim3(QKV_N / 64, rows / 64), 256>>>(h, qkv_w, qkv_b, nullptr, qkv, rows, QKV_N, DIM);
    // 3. fused masked attention
    attn_kernel<<<dim3(B * HEADS, Nlen / BM), 128>>>(qkv, elev, barrier, attn, Nlen);
    // 4. out proj + residual
    gemm_kernel<1><<<dim3(DIM / 64, rows / 64), 256>>>(attn, proj_w, proj_b, x, x2, rows, DIM, DIM);
    // 5. LN2
    ln_kernel<<<rows, 256>>>(x2, ln2_g, ln2_b, h);
    // 6. FC1 + exact GELU
    gemm_kernel<2><<<dim3(HIDDEN / 64, rows / 64), 256>>>(h, fc1_w, fc1_b, nullptr, ff, rows, HIDDEN, DIM);
    // 7. FC2 + residual -> output
    gemm_kernel<1><<<dim3(DIM / 64, rows / 64), 256>>>(ff, fc2_w, fc2_b, x2, out, rows, DIM, HIDDEN);
}

// round 3
// speedup vs baseline: 1.7503x; 1.7485x over previous
#include <cuda_runtime.h>
#include <math.h>
#include <stdint.h>

#define DIM 768
#define HEADS 12
#define HD 64
#define HIDDEN 3072
#define QKV_N 2304
#define MAX_ROWS 4096
#define SCALE 0.125f

// ---------------- scratch (no allocation allowed) ----------------
__device__ float g_h[MAX_ROWS * DIM];
__device__ float g_qkv[MAX_ROWS * QKV_N];
__device__ float g_attn[MAX_ROWS * DIM];
__device__ float g_x2[MAX_ROWS * DIM];
__device__ float g_ff[MAX_ROWS * HIDDEN];
// transposed (tf32-rounded) weights: Wt[N][K]
__device__ float g_wt_qkv[DIM * QKV_N];
__device__ float g_wt_proj[DIM * DIM];
__device__ float g_wt_fc1[DIM * HIDDEN];
__device__ float g_wt_fc2[HIDDEN * DIM];

__device__ __forceinline__ float tf32r(float x) {
    uint32_t u;
    asm("cvt.rna.tf32.f32 %0, %1;" : "=r"(u) : "f"(x));
    return __uint_as_float(u);
}

// ---------------- weight transpose + tf32 round ----------------
__global__ __launch_bounds__(256)
void transpose_tf32(const float* __restrict__ W, float* __restrict__ Wt, int K, int N)
{
    __shared__ float t[32][33];
    const int n0 = blockIdx.x * 32, k0 = blockIdx.y * 32;
    const int tx = threadIdx.x & 31, ty = threadIdx.x >> 5;
    #pragma unroll
    for (int i = 0; i < 32; i += 8)
        t[ty + i][tx] = W[(size_t)(k0 + ty + i) * N + n0 + tx];
    __syncthreads();
    #pragma unroll
    for (int i = 0; i < 32; i += 8)
        Wt[(size_t)(n0 + ty + i) * K + k0 + tx] = tf32r(t[tx][ty + i]);
}

// ---------------- LayerNorm: one block per row ----------------
__global__ __launch_bounds__(256)
void ln_kernel(const float* __restrict__ x, const float* __restrict__ g,
               const float* __restrict__ bta, float* __restrict__ out)
{
    const int row = blockIdx.x;
    const float* xr = x + (size_t)row * DIM;
    const int tid = threadIdx.x;

    float v[3];
    float s = 0.f, s2 = 0.f;
    #pragma unroll
    for (int k = 0; k < 3; k++) {
        float t = xr[tid + 256 * k];
        v[k] = t; s += t; s2 += t * t;
    }
    #pragma unroll
    for (int off = 16; off; off >>= 1) {
        s  += __shfl_down_sync(0xffffffffu, s,  off);
        s2 += __shfl_down_sync(0xffffffffu, s2, off);
    }
    __shared__ float red[2][8];
    const int wid = tid >> 5, lid = tid & 31;
    if (lid == 0) { red[0][wid] = s; red[1][wid] = s2; }
    __syncthreads();
    __shared__ float s_mu, s_inv;
    if (tid == 0) {
        float ts = 0.f, ts2 = 0.f;
        #pragma unroll
        for (int w = 0; w < 8; w++) { ts += red[0][w]; ts2 += red[1][w]; }
        float mu = ts * (1.0f / DIM);
        float var = ts2 * (1.0f / DIM) - mu * mu;
        s_mu = mu;
        s_inv = rsqrtf(var + 1e-5f);
    }
    __syncthreads();
    const float mu = s_mu, inv = s_inv;
    float* outr = out + (size_t)row * DIM;
    #pragma unroll
    for (int k = 0; k < 3; k++) {
        int c = tid + 256 * k;
        outr[c] = (v[k] - mu) * inv * g[c] + bta[c];
    }
}

// ---------------- tensor-core GEMM (tf32 mma.sync) ----------------
// C[M,N] = A[M,K] @ W[K,N] + bias (+epilogue), with W pre-transposed as Wt[N][K].
// Block: 128x128x32, 256 threads (8 warps), warp tile 64x32 (4 m16 x 4 n8 mma tiles).
// EPI: 0 = bias, 1 = bias + residual, 2 = bias + exact GELU

#define GBM 128
#define GBN 128
#define GBK 32

template<int EPI>
__global__ __launch_bounds__(256)
void gemm_tc(const float* __restrict__ A, const float* __restrict__ Wt,
             const float* __restrict__ bias, const float* __restrict__ res,
             float* __restrict__ C, int M, int N, int K)
{
    __shared__ float As[GBM * GBK];
    __shared__ float Bs[GBN * GBK];

    const int tid  = threadIdx.x;
    const int lane = tid & 31, warp = tid >> 5;
    const int wm = warp >> 2;            // 0..1
    const int wn = warp & 3;             // 0..3
    const int m0 = blockIdx.y << 7, n0 = blockIdx.x << 7;

    const uint32_t a_base = (uint32_t)__cvta_generic_to_shared(As);
    const uint32_t b_base = (uint32_t)__cvta_generic_to_shared(Bs);

    float acc[4][4][4];
    #pragma unroll
    for (int i = 0; i < 4; i++)
        #pragma unroll
        for (int j = 0; j < 4; j++)
            #pragma unroll
            for (int r = 0; r < 4; r++) acc[i][j][r] = 0.f;

    float4 ra[4], rb[4];

    // --- global loads: tile rows are K-contiguous for both operands ---
    #define LDG_TILE(r, base, row0, k0)                                          \
        _Pragma("unroll")                                                        \
        for (int it = 0; it < 4; it++) {                                         \
            int idx = it * 256 + tid;                                            \
            int rr = idx >> 3, cc = idx & 7;                                     \
            r[it] = *(const float4*)((base) + (size_t)((row0) + rr) * K + (k0) + cc * 4); \
        }

    // --- smem stores: XOR-swizzle 16B units within each 128B row ---
    #define STS_TILE(s, r, CVT)                                                  \
        _Pragma("unroll")                                                        \
        for (int it = 0; it < 4; it++) {                                         \
            int idx = it * 256 + tid;                                            \
            int rr = idx >> 3, cc = idx & 7;                                     \
            float4 v = r[it];                                                    \
            if (CVT) { v.x = tf32r(v.x); v.y = tf32r(v.y); v.z = tf32r(v.z); v.w = tf32r(v.w); } \
            *(float4*)((s) + rr * GBK + ((cc ^ (rr & 7)) << 2)) = v;             \
        }

    LDG_TILE(ra, A,  m0, 0)
    LDG_TILE(rb, Wt, n0, 0)
    STS_TILE(As, ra, 1)
    STS_TILE(Bs, rb, 0)
    __syncthreads();

    // ldmatrix lane addressing (constant across k-steps except f4)
    const int a_row = (lane & 15);          // 0..15 within m-tile
    const int a_cs  = (lane >> 4);          // 0/1 -> k 0-3 / 4-7
    const int b_row = ((lane >> 1) & 8) + (lane & 7);  // 0..15 within n-pair
    const int b_cs  = ((lane >> 3) & 1);

    for (int k0 = 0; k0 < K; k0 += GBK) {
        const bool more = (k0 + GBK) < K;
        if (more) {
            LDG_TILE(ra, A,  m0, k0 + GBK)
            LDG_TILE(rb, Wt, n0, k0 + GBK)
        }

        #pragma unroll
        for (int ks = 0; ks < 4; ks++) {
            uint32_t af[4][4], bf[4][2];
            #pragma unroll
            for (int mt = 0; mt < 4; mt++) {
                int row = (wm << 6) + (mt << 4) + a_row;
                int f4  = (ks << 1) + a_cs;
                uint32_t addr = a_base + ((row * GBK + ((f4 ^ (row & 7)) << 2)) << 2);
                asm volatile("ldmatrix.sync.aligned.m8n8.x4.shared.b16 {%0,%1,%2,%3}, [%4];\n"
                             : "=r"(af[mt][0]), "=r"(af[mt][1]), "=r"(af[mt][2]), "=r"(af[mt][3])
                             : "r"(addr));
            }
            #pragma unroll
            for (int np = 0; np < 2; np++) {
                int row = (wn << 5) + (np << 4) + b_row;
                int f4  = (ks << 1) + b_cs;
                uint32_t addr = b_base + ((row * GBK + ((f4 ^ (row & 7)) << 2)) << 2);
                uint32_t q0, q1, q2, q3;
                asm volatile("ldmatrix.sync.aligned.m8n8.x4.shared.b16 {%0,%1,%2,%3}, [%4];\n"
                             : "=r"(q0), "=r"(q1), "=r"(q2), "=r"(q3)
                             : "r"(addr));
                bf[np * 2 + 0][0] = q0; bf[np * 2 + 0][1] = q1;
                bf[np * 2 + 1][0] = q2; bf[np * 2 + 1][1] = q3;
            }
            #pragma unroll
            for (int mt = 0; mt < 4; mt++)
                #pragma unroll
                for (int nt = 0; nt < 4; nt++) {
                    asm volatile(
                        "mma.sync.aligned.m16n8k8.row.col.f32.tf32.tf32.f32 "
                        "{%0,%1,%2,%3}, {%4,%5,%6,%7}, {%8,%9}, {%0,%1,%2,%3};\n"
                        : "+f"(acc[mt][nt][0]), "+f"(acc[mt][nt][1]),
                          "+f"(acc[mt][nt][2]), "+f"(acc[mt][nt][3])
                        : "r"(af[mt][0]), "r"(af[mt][1]), "r"(af[mt][2]), "r"(af[mt][3]),
                          "r"(bf[nt][0]), "r"(bf[nt][1]));
                }
        }

        if (more) {
            __syncthreads();
            STS_TILE(As, ra, 1)
            STS_TILE(Bs, rb, 0)
            __syncthreads();
        }
    }

    // --- epilogue ---
    const int g = lane >> 2, tg = lane & 3;
    #pragma unroll
    for (int mt = 0; mt < 4; mt++) {
        #pragma unroll
        for (int nt = 0; nt < 4; nt++) {
            int row = m0 + (wm << 6) + (mt << 4) + g;
            int col = n0 + (wn << 5) + (nt << 3) + (tg << 1);
            float b0 = bias[col], b1 = bias[col + 1];
            #pragma unroll
            for (int half = 0; half < 2; half++) {
                int r = row + half * 8;
                float v0 = acc[mt][nt][half * 2 + 0] + b0;
                float v1 = acc[mt][nt][half * 2 + 1] + b1;
                if (EPI == 1) {
                    const float2 rr = *(const float2*)&res[(size_t)r * N + col];
                    v0 += rr.x; v1 += rr.y;
                }
                if (EPI == 2) {
                    v0 = 0.5f * v0 * (1.0f + erff(v0 * 0.70710678118654752f));
                    v1 = 0.5f * v1 * (1.0f + erff(v1 * 0.70710678118654752f));
                }
                *(float2*)&C[(size_t)r * N + col] = make_float2(v0, v1);
            }
        }
    }
    #undef LDG_TILE
    #undef STS_TILE
}

// ---------------- Fused masked attention (unchanged, fp32) ----------------
#define BM 128
#define BK 64
__global__ __launch_bounds__(128)
void attn_kernel(const float* __restrict__ qkv, const float* __restrict__ elev,
                 const float* __restrict__ barrier, float* __restrict__ out, int Nlen)
{
    __shared__ float Ks[BK][HD];
    __shared__ float Vs[BK][HD];
    __shared__ float es[BK];

    const int bh = blockIdx.x;
    const int b = bh / HEADS, h = bh % HEADS;
    const int tid = threadIdx.x;
    const int i = blockIdx.y * BM + tid;
    const int rowbase = b * Nlen;
    const float bar = *barrier;

    float q[HD];
    const float4* qp = (const float4*)(qkv + (size_t)(rowbase + i) * QKV_N + h * HD);
    #pragma unroll
    for (int dd = 0; dd < 16; dd++) {
        float4 t = qp[dd];
        q[4 * dd + 0] = t.x; q[4 * dd + 1] = t.y; q[4 * dd + 2] = t.z; q[4 * dd + 3] = t.w;
    }
    const float e_i = elev[rowbase + i];

    float m = -1e30f, lp = 0.f, lm = 0.f;
    float o[HD];
    #pragma unroll
    for (int d = 0; d < HD; d++) o[d] = 0.f;

    for (int j0 = 0; j0 < Nlen; j0 += BK) {
        __syncthreads();
        for (int idx = tid; idx < BK * 16; idx += 128) {
            int r = idx >> 4, c = idx & 15;
            const float4* kp = (const float4*)(qkv + (size_t)(rowbase + j0 + r) * QKV_N + DIM + h * HD);
            const float4* vp = (const float4*)(qkv + (size_t)(rowbase + j0 + r) * QKV_N + 2 * DIM + h * HD);
            ((float4*)&Ks[r][0])[c] = kp[c];
            ((float4*)&Vs[r][0])[c] = vp[c];
        }
        if (tid < BK) es[tid] = elev[rowbase + j0 + tid];
        __syncthreads();

        for (int j = 0; j < BK; j++) {
            float s = 0.f;
            const float4* kr = (const float4*)&Ks[j][0];
            #pragma unroll
            for (int dd = 0; dd < 16; dd++) {
                float4 kv = kr[dd];
                s = fmaf(q[4 * dd + 0], kv.x, s);
                s = fmaf(q[4 * dd + 1], kv.y, s);
                s = fmaf(q[4 * dd + 2], kv.z, s);
                s = fmaf(q[4 * dd + 3], kv.w, s);
            }
            s *= SCALE;
            float diff = es[j] - e_i;
            float mask = 1.0f / (1.0f + __expf(bar * diff));
            mask = fminf(fmaxf(mask, 1e-6f), 1.0f);

            float p;
            if (s > m) {
                float alpha = __expf(m - s);
                lp *= alpha; lm *= alpha;
                #pragma unroll
                for (int d = 0; d < HD; d++) o[d] *= alpha;
                m = s;
                p = 1.0f;
            } else {
                p = __expf(s - m);
            }
            float pm = p * mask;
            lp += p; lm += pm;
            const float4* vr = (const float4*)&Vs[j][0];
            #pragma unroll
            for (int dd = 0; dd < 16; dd++) {
                float4 vv = vr[dd];
                o[4 * dd + 0] = fmaf(pm, vv.x, o[4 * dd + 0]);
                o[4 * dd + 1] = fmaf(pm, vv.y, o[4 * dd + 1]);
                o[4 * dd + 2] = fmaf(pm, vv.z, o[4 * dd + 2]);
                o[4 * dd + 3] = fmaf(pm, vv.w, o[4 * dd + 3]);
            }
        }
    }

    const float inv = 1.0f / (lm + 1e-8f * lp);
    float* op = out + (size_t)(rowbase + i) * DIM + h * HD;
    #pragma unroll
    for (int d = 0; d < HD; d++) op[d] = o[d] * inv;
}

// ---------------- launch ----------------
extern "C" void kernel_launch(void* const* d_in, const int* in_sizes, int n_in,
                              void* d_out, int out_size)
{
    const float* x      = (const float*)d_in[0];
    const float* elev   = (const float*)d_in[1];
    const float* qkv_w  = (const float*)d_in[2];
    const float* qkv_b  = (const float*)d_in[3];
    const float* proj_w = (const float*)d_in[4];
    const float* proj_b = (const float*)d_in[5];
    const float* ln1_g  = (const float*)d_in[6];
    const float* ln1_b  = (const float*)d_in[7];
    const float* ln2_g  = (const float*)d_in[8];
    const float* ln2_b  = (const float*)d_in[9];
    const float* fc1_w  = (const float*)d_in[10];
    const float* fc1_b  = (const float*)d_in[11];
    const float* fc2_w  = (const float*)d_in[12];
    const float* fc2_b  = (const float*)d_in[13];
    const float* barrier= (const float*)d_in[14];
    float* out = (float*)d_out;

    const int rows = in_sizes[0] / DIM;     // B*N
    const int Nlen = 2048;
    const int B = rows / Nlen;

    float *h, *qkv, *attn, *x2, *ff, *wtq, *wtp, *wt1, *wt2;
    cudaGetSymbolAddress((void**)&h,    g_h);
    cudaGetSymbolAddress((void**)&qkv,  g_qkv);
    cudaGetSymbolAddress((void**)&attn, g_attn);
    cudaGetSymbolAddress((void**)&x2,   g_x2);
    cudaGetSymbolAddress((void**)&ff,   g_ff);
    cudaGetSymbolAddress((void**)&wtq,  g_wt_qkv);
    cudaGetSymbolAddress((void**)&wtp,  g_wt_proj);
    cudaGetSymbolAddress((void**)&wt1,  g_wt_fc1);
    cudaGetSymbolAddress((void**)&wt2,  g_wt_fc2);

    // 0. weight transposes (+ tf32 rounding)
    transpose_tf32<<<dim3(QKV_N / 32, DIM / 32), 256>>>(qkv_w, wtq, DIM, QKV_N);
    transpose_tf32<<<dim3(DIM / 32, DIM / 32), 256>>>(proj_w, wtp, DIM, DIM);
    transpose_tf32<<<dim3(HIDDEN / 32, DIM / 32), 256>>>(fc1_w, wt1, DIM, HIDDEN);
    transpose_tf32<<<dim3(DIM / 32, HIDDEN / 32), 256>>>(fc2_w, wt2, HIDDEN, DIM);

    // 1. LN1
    ln_kernel<<<rows, 256>>>(x, ln1_g, ln1_b, h);
    // 2. QKV projection
    gemm_tc<0><<<dim3(QKV_N / 128, rows / 128), 256>>>(h, wtq, qkv_b, nullptr, qkv, rows, QKV_N, DIM);
    // 3. fused masked attention
    attn_kernel<<<dim3(B * HEADS, Nlen / BM), 128>>>(qkv, elev, barrier, attn, Nlen);
    // 4. out proj + residual
    gemm_tc<1><<<dim3(DIM / 128, rows / 128), 256>>>(attn, wtp, proj_b, x, x2, rows, DIM, DIM);
    // 5. LN2
    ln_kernel<<<rows, 256>>>(x2, ln2_g, ln2_b, h);
    // 6. FC1 + exact GELU
    gemm_tc<2><<<dim3(HIDDEN / 128, rows / 128), 256>>>(h, wt1, fc1_b, nullptr, ff, rows, HIDDEN, DIM);
    // 7. FC2 + residual -> output
    gemm_tc<1><<<dim3(DIM / 128, rows / 128), 256>>>(ff, wt2, fc2_b, x2, out, rows, DIM, HIDDEN);
}

// round 4
// speedup vs baseline: 3.7897x; 2.1652x over previous
#include <cuda_runtime.h>
#include <math.h>
#include <stdint.h>

#define DIM 768
#define HEADS 12
#define HD 64
#define HIDDEN 3072
#define QKV_N 2304
#define MAX_ROWS 4096
#define SCALE 0.125f
#define NLEN 2048

// ---------------- scratch (no allocation allowed) ----------------
__device__ float g_h[MAX_ROWS * DIM];
__device__ float g_qkv[MAX_ROWS * QKV_N];
__device__ float g_attn[MAX_ROWS * DIM];
__device__ float g_x2[MAX_ROWS * DIM];
__device__ float g_ff[MAX_ROWS * HIDDEN];
__device__ float g_vt[2 * HEADS * HD * NLEN];   // V transposed: [bh][d][n]
__device__ float g_wt_qkv[DIM * QKV_N];
__device__ float g_wt_proj[DIM * DIM];
__device__ float g_wt_fc1[DIM * HIDDEN];
__device__ float g_wt_fc2[HIDDEN * DIM];

__device__ __forceinline__ float tf32r(float x) {
    uint32_t u;
    asm("cvt.rna.tf32.f32 %0, %1;" : "=r"(u) : "f"(x));
    return __uint_as_float(u);
}

#define CP_ASYNC16(dst, src) \
    asm volatile("cp.async.cg.shared.global [%0], [%1], 16;\n" :: "r"(dst), "l"(src))
#define CP_COMMIT() asm volatile("cp.async.commit_group;\n" ::: "memory")
#define CP_WAIT1()  asm volatile("cp.async.wait_group 1;\n" ::: "memory")

#define LDSM_X4(r0, r1, r2, r3, addr) \
    asm volatile("ldmatrix.sync.aligned.m8n8.x4.shared.b16 {%0,%1,%2,%3}, [%4];\n" \
                 : "=r"(r0), "=r"(r1), "=r"(r2), "=r"(r3) : "r"(addr))

#define MMA_TF32(d, a, b) \
    asm volatile("mma.sync.aligned.m16n8k8.row.col.f32.tf32.tf32.f32 " \
                 "{%0,%1,%2,%3}, {%4,%5,%6,%7}, {%8,%9}, {%0,%1,%2,%3};\n" \
                 : "+f"(d[0]), "+f"(d[1]), "+f"(d[2]), "+f"(d[3]) \
                 : "r"(a[0]), "r"(a[1]), "r"(a[2]), "r"(a[3]), "r"(b[0]), "r"(b[1]))

// ---------------- weight transpose + tf32 round ----------------
__global__ __launch_bounds__(256)
void transpose_tf32(const float* __restrict__ W, float* __restrict__ Wt, int K, int N)
{
    __shared__ float t[32][33];
    const int n0 = blockIdx.x * 32, k0 = blockIdx.y * 32;
    const int tx = threadIdx.x & 31, ty = threadIdx.x >> 5;
    #pragma unroll
    for (int i = 0; i < 32; i += 8)
        t[ty + i][tx] = W[(size_t)(k0 + ty + i) * N + n0 + tx];
    __syncthreads();
    #pragma unroll
    for (int i = 0; i < 32; i += 8)
        Wt[(size_t)(n0 + ty + i) * K + k0 + tx] = tf32r(t[tx][ty + i]);
}

// ---------------- V transpose: g_qkv -> g_vt[bh][d][n] ----------------
__global__ __launch_bounds__(256)
void transpose_v(const float* __restrict__ qkv, float* __restrict__ vt)
{
    __shared__ float t[32][33];
    const int bh = blockIdx.z;
    const int b = bh / HEADS, h = bh % HEADS;
    const int n0 = blockIdx.x * 32, d0 = blockIdx.y * 32;
    const int tx = threadIdx.x & 31, ty = threadIdx.x >> 5;
    #pragma unroll
    for (int i = 0; i < 32; i += 8)
        t[ty + i][tx] = qkv[(size_t)(b * NLEN + n0 + ty + i) * QKV_N + 2 * DIM + h * HD + d0 + tx];
    __syncthreads();
    #pragma unroll
    for (int i = 0; i < 32; i += 8)
        vt[(size_t)(bh * HD + d0 + ty + i) * NLEN + n0 + tx] = t[tx][ty + i];
}

// ---------------- LayerNorm (writes tf32-rounded output) ----------------
__global__ __launch_bounds__(256)
void ln_kernel(const float* __restrict__ x, const float* __restrict__ g,
               const float* __restrict__ bta, float* __restrict__ out)
{
    const int row = blockIdx.x;
    const float* xr = x + (size_t)row * DIM;
    const int tid = threadIdx.x;

    float v[3];
    float s = 0.f, s2 = 0.f;
    #pragma unroll
    for (int k = 0; k < 3; k++) {
        float t = xr[tid + 256 * k];
        v[k] = t; s += t; s2 += t * t;
    }
    #pragma unroll
    for (int off = 16; off; off >>= 1) {
        s  += __shfl_down_sync(0xffffffffu, s,  off);
        s2 += __shfl_down_sync(0xffffffffu, s2, off);
    }
    __shared__ float red[2][8];
    const int wid = tid >> 5, lid = tid & 31;
    if (lid == 0) { red[0][wid] = s; red[1][wid] = s2; }
    __syncthreads();
    __shared__ float s_mu, s_inv;
    if (tid == 0) {
        float ts = 0.f, ts2 = 0.f;
        #pragma unroll
        for (int w = 0; w < 8; w++) { ts += red[0][w]; ts2 += red[1][w]; }
        float mu = ts * (1.0f / DIM);
        float var = ts2 * (1.0f / DIM) - mu * mu;
        s_mu = mu;
        s_inv = rsqrtf(var + 1e-5f);
    }
    __syncthreads();
    const float mu = s_mu, inv = s_inv;
    float* outr = out + (size_t)row * DIM;
    #pragma unroll
    for (int k = 0; k < 3; k++) {
        int c = tid + 256 * k;
        outr[c] = tf32r((v[k] - mu) * inv * g[c] + bta[c]);
    }
}

// ---------------- tensor-core GEMM, cp.async double-buffered ----------------
// C[M,N] = A[M,K] @ Wt[N,K]^T + bias (+epilogue). A and Wt are pre-rounded tf32.
// EPI: 0 = bias, 1 = bias + residual, 2 = bias + exact GELU. ROUND: tf32-round output.
#define GBM 128
#define GBN 128
#define GBK 32

template<int EPI, int ROUND>
__global__ __launch_bounds__(256)
void gemm_tc(const float* __restrict__ A, const float* __restrict__ Wt,
             const float* __restrict__ bias, const float* __restrict__ res,
             float* __restrict__ C, int M, int N, int K)
{
    extern __shared__ float sm[];
    float* As = sm;                     // 2 x 128x32
    float* Bs = sm + 2 * GBM * GBK;     // 2 x 128x32

    const int tid  = threadIdx.x;
    const int lane = tid & 31, warp = tid >> 5;
    const int wm = warp >> 2, wn = warp & 3;
    const int m0 = blockIdx.y << 7, n0 = blockIdx.x << 7;

    const uint32_t as_base = (uint32_t)__cvta_generic_to_shared(As);
    const uint32_t bs_base = (uint32_t)__cvta_generic_to_shared(Bs);

    float acc[4][4][4];
    #pragma unroll
    for (int i = 0; i < 4; i++)
        #pragma unroll
        for (int j = 0; j < 4; j++)
            #pragma unroll
            for (int r = 0; r < 4; r++) acc[i][j][r] = 0.f;

    #define STAGE(buf, k0)                                                              \
        _Pragma("unroll")                                                               \
        for (int s_ = 0; s_ < 4; s_++) {                                                \
            int idx = s_ * 256 + tid;                                                   \
            int r_ = idx >> 3, c_ = idx & 7;                                            \
            uint32_t sw = ((c_ ^ (r_ & 7)) << 2);                                       \
            CP_ASYNC16(as_base + (((buf) * GBM * GBK + r_ * GBK + sw) << 2),            \
                       A + (size_t)(m0 + r_) * K + (k0) + (c_ << 2));                   \
            CP_ASYNC16(bs_base + (((buf) * GBN * GBK + r_ * GBK + sw) << 2),            \
                       Wt + (size_t)(n0 + r_) * K + (k0) + (c_ << 2));                  \
        }

    STAGE(0, 0)
    CP_COMMIT();

    const int a_row = lane & 15, a_cs = lane >> 4;
    const int b_row = ((lane >> 1) & 8) + (lane & 7), b_cs = (lane >> 3) & 1;
    const int kIters = K >> 5;

    for (int it = 0; it < kIters; it++) {
        const int buf = it & 1;
        if (it + 1 < kIters) { STAGE(buf ^ 1, (it + 1) << 5) }
        CP_COMMIT();
        CP_WAIT1();
        __syncthreads();

        const uint32_t ab = as_base + ((buf * GBM * GBK) << 2);
        const uint32_t bb = bs_base + ((buf * GBN * GBK) << 2);

        #pragma unroll
        for (int ks = 0; ks < 4; ks++) {
            uint32_t af[4][4], bf[4][2];
            #pragma unroll
            for (int mt = 0; mt < 4; mt++) {
                int row = (wm << 6) + (mt << 4) + a_row;
                int f4  = (ks << 1) + a_cs;
                uint32_t addr = ab + ((row * GBK + ((f4 ^ (row & 7)) << 2)) << 2);
                LDSM_X4(af[mt][0], af[mt][1], af[mt][2], af[mt][3], addr);
            }
            #pragma unroll
            for (int np = 0; np < 2; np++) {
                int row = (wn << 5) + (np << 4) + b_row;
                int f4  = (ks << 1) + b_cs;
                uint32_t addr = bb + ((row * GBK + ((f4 ^ (row & 7)) << 2)) << 2);
                uint32_t q0, q1, q2, q3;
                LDSM_X4(q0, q1, q2, q3, addr);
                bf[np * 2 + 0][0] = q0; bf[np * 2 + 0][1] = q1;
                bf[np * 2 + 1][0] = q2; bf[np * 2 + 1][1] = q3;
            }
            #pragma unroll
            for (int mt = 0; mt < 4; mt++)
                #pragma unroll
                for (int nt = 0; nt < 4; nt++)
                    MMA_TF32(acc[mt][nt], af[mt], bf[nt]);
        }
        __syncthreads();
    }
    #undef STAGE

    const int g = lane >> 2, tg = lane & 3;
    #pragma unroll
    for (int mt = 0; mt < 4; mt++) {
        #pragma unroll
        for (int nt = 0; nt < 4; nt++) {
            int row = m0 + (wm << 6) + (mt << 4) + g;
            int col = n0 + (wn << 5) + (nt << 3) + (tg << 1);
            float b0 = bias[col], b1 = bias[col + 1];
            #pragma unroll
            for (int half = 0; half < 2; half++) {
                int r = row + half * 8;
                float v0 = acc[mt][nt][half * 2 + 0] + b0;
                float v1 = acc[mt][nt][half * 2 + 1] + b1;
                if (EPI == 1) {
                    const float2 rr = *(const float2*)&res[(size_t)r * N + col];
                    v0 += rr.x; v1 += rr.y;
                }
                if (EPI == 2) {
                    v0 = 0.5f * v0 * (1.0f + erff(v0 * 0.70710678118654752f));
                    v1 = 0.5f * v1 * (1.0f + erff(v1 * 0.70710678118654752f));
                }
                if (ROUND) { v0 = tf32r(v0); v1 = tf32r(v1); }
                *(float2*)&C[(size_t)r * N + col] = make_float2(v0, v1);
            }
        }
    }
}

// ---------------- tensor-core flash attention ----------------
// CTA: 128 threads = 4 warps; each warp owns 16 q-rows; Q tile = 64 rows.
// Key tile = 64. S = (Q*SCALE) @ K^T via mma tf32; online softmax with dual
// sums lp (plain) / lm (masked) so out = O / (lm + 1e-8*lp) matches reference.
// smem: Ks[64x64] | Vts[64x64] | QP[64x64] (Q staging, then per-warp P) | es[64]
__global__ __launch_bounds__(128)
void attn_tc(const float* __restrict__ qkv, const float* __restrict__ vt,
             const float* __restrict__ elev, const float* __restrict__ barrier,
             float* __restrict__ out)
{
    extern __shared__ float sm[];
    float* Ks  = sm;
    float* Vts = sm + 64 * 64;
    float* QP  = sm + 2 * 64 * 64;
    float* es  = sm + 3 * 64 * 64;

    const int bh = blockIdx.x, b = bh / HEADS, h = bh % HEADS;
    const int q0 = blockIdx.y << 6;
    const int tid = threadIdx.x, lane = tid & 31, warp = tid >> 5;
    const int rowbase = b * NLEN;
    const float bar = *barrier;

    const uint32_t ks_base = (uint32_t)__cvta_generic_to_shared(Ks);
    const uint32_t vt_base = (uint32_t)__cvta_generic_to_shared(Vts);
    const uint32_t qp_base = (uint32_t)__cvta_generic_to_shared(QP);

    // stage Q tile (pre-scaled; values already tf32 so *0.125 is exact)
    #pragma unroll
    for (int it = 0; it < 8; it++) {
        int idx = it * 128 + tid;
        int rr = idx >> 4, cc = idx & 15;
        float4 v = *(const float4*)(qkv + (size_t)(rowbase + q0 + rr) * QKV_N + h * HD + cc * 4);
        v.x *= SCALE; v.y *= SCALE; v.z *= SCALE; v.w *= SCALE;
        *(float4*)(QP + rr * 64 + ((cc ^ (rr & 7)) << 2)) = v;
    }
    __syncthreads();

    const int a_row = lane & 15, a_cs = lane >> 4;
    const int b_row = ((lane >> 1) & 8) + (lane & 7), b_cs = (lane >> 3) & 1;

    // Q fragments (held all kernel). Warp w reads only its own 16 rows,
    // which are exactly the rows it later overwrites with P.
    uint32_t qa[8][4];
    #pragma unroll
    for (int ks = 0; ks < 8; ks++) {
        int row = (warp << 4) + a_row;
        int f4  = (ks << 1) + a_cs;
        uint32_t addr = qp_base + ((row * 64 + ((f4 ^ (row & 7)) << 2)) << 2);
        LDSM_X4(qa[ks][0], qa[ks][1], qa[ks][2], qa[ks][3], addr);
    }

    const int g = lane >> 2, tg = lane & 3;
    const float e_i0 = elev[rowbase + q0 + (warp << 4) + g];
    const float e_i1 = elev[rowbase + q0 + (warp << 4) + g + 8];

    float m0 = -1e30f, m1 = -1e30f;
    float lp0 = 0.f, lm0 = 0.f, lp1 = 0.f, lm1 = 0.f;
    float o[8][4];
    #pragma unroll
    for (int dt = 0; dt < 8; dt++)
        #pragma unroll
        for (int r = 0; r < 4; r++) o[dt][r] = 0.f;

    for (int j0 = 0; j0 < NLEN; j0 += 64) {
        __syncthreads();
        #pragma unroll
        for (int it = 0; it < 8; it++) {
            int idx = it * 128 + tid;
            int rr = idx >> 4, cc = idx & 15;
            uint32_t sw = rr * 64 + ((cc ^ (rr & 7)) << 2);
            *(float4*)(Ks + sw) =
                *(const float4*)(qkv + (size_t)(rowbase + j0 + rr) * QKV_N + DIM + h * HD + cc * 4);
            *(float4*)(Vts + sw) =
                *(const float4*)(vt + (size_t)(bh * HD + rr) * NLEN + j0 + cc * 4);
        }
        if (tid < 64) es[tid] = elev[rowbase + j0 + tid];
        __syncthreads();

        // ---- S = Qs @ Ks^T ----
        float s[8][4];
        #pragma unroll
        for (int nt = 0; nt < 8; nt++)
            #pragma unroll
            for (int r = 0; r < 4; r++) s[nt][r] = 0.f;

        #pragma unroll
        for (int ks = 0; ks < 8; ks++) {
            uint32_t bf[8][2];
            #pragma unroll
            for (int np = 0; np < 4; np++) {
                int row = (np << 4) + b_row;
                int f4  = (ks << 1) + b_cs;
                uint32_t addr = ks_base + ((row * 64 + ((f4 ^ (row & 7)) << 2)) << 2);
                uint32_t t0, t1, t2, t3;
                LDSM_X4(t0, t1, t2, t3, addr);
                bf[np * 2 + 0][0] = t0; bf[np * 2 + 0][1] = t1;
                bf[np * 2 + 1][0] = t2; bf[np * 2 + 1][1] = t3;
            }
            #pragma unroll
            for (int nt = 0; nt < 8; nt++) MMA_TF32(s[nt], qa[ks], bf[nt]);
        }

        // ---- online softmax ----
        float r0 = -1e30f, r1 = -1e30f;
        #pragma unroll
        for (int nt = 0; nt < 8; nt++) {
            r0 = fmaxf(r0, fmaxf(s[nt][0], s[nt][1]));
            r1 = fmaxf(r1, fmaxf(s[nt][2], s[nt][3]));
        }
        r0 = fmaxf(r0, __shfl_xor_sync(0xffffffffu, r0, 1));
        r0 = fmaxf(r0, __shfl_xor_sync(0xffffffffu, r0, 2));
        r1 = fmaxf(r1, __shfl_xor_sync(0xffffffffu, r1, 1));
        r1 = fmaxf(r1, __shfl_xor_sync(0xffffffffu, r1, 2));

        float nm0 = fmaxf(m0, r0), nm1 = fmaxf(m1, r1);
        float al0 = __expf(m0 - nm0), al1 = __expf(m1 - nm1);
        m0 = nm0; m1 = nm1;
        lp0 *= al0; lm0 *= al0; lp1 *= al1; lm1 *= al1;
        #pragma unroll
        for (int dt = 0; dt < 8; dt++) {
            o[dt][0] *= al0; o[dt][1] *= al0;
            o[dt][2] *= al1; o[dt][3] *= al1;
        }

        #pragma unroll
        for (int nt = 0; nt < 8; nt++) {
            int c = (nt << 3) + (tg << 1);
            float ej0 = es[c], ej1 = es[c + 1];
            float mk00 = fminf(fmaxf(1.0f / (1.0f + __expf(bar * (ej0 - e_i0))), 1e-6f), 1.0f);
            float mk01 = fminf(fmaxf(1.0f / (1.0f + __expf(bar * (ej1 - e_i0))), 1e-6f), 1.0f);
            float mk10 = fminf(fmaxf(1.0f / (1.0f + __expf(bar * (ej0 - e_i1))), 1e-6f), 1.0f);
            float mk11 = fminf(fmaxf(1.0f / (1.0f + __expf(bar * (ej1 - e_i1))), 1e-6f), 1.0f);

            float p00 = __expf(s[nt][0] - m0), p01 = __expf(s[nt][1] - m0);
            float p10 = __expf(s[nt][2] - m1), p11 = __expf(s[nt][3] - m1);
            lp0 += p00 + p01; lp1 += p10 + p11;
            float pm00 = p00 * mk00, pm01 = p01 * mk01;
            float pm10 = p10 * mk10, pm11 = p11 * mk11;
            lm0 += pm00 + pm01; lm1 += pm10 + pm11;

            int row0 = (warp << 4) + g;
            uint32_t u0 = row0 * 64 + (((c >> 2) ^ (row0 & 7)) << 2) + (c & 3);
            *(float2*)(QP + u0) = make_float2(tf32r(pm00), tf32r(pm01));
            int row1 = row0 + 8;
            uint32_t u1 = row1 * 64 + (((c >> 2) ^ (row1 & 7)) << 2) + (c & 3);
            *(float2*)(QP + u1) = make_float2(tf32r(pm10), tf32r(pm11));
        }
        __syncwarp();

        // ---- O += P @ Vts^T ----
        #pragma unroll
        for (int ks = 0; ks < 8; ks++) {
            uint32_t pa[4];
            {
                int row = (warp << 4) + a_row;
                int f4  = (ks << 1) + a_cs;
                uint32_t addr = qp_base + ((row * 64 + ((f4 ^ (row & 7)) << 2)) << 2);
                LDSM_X4(pa[0], pa[1], pa[2], pa[3], addr);
            }
            uint32_t vf[8][2];
            #pragma unroll
            for (int np = 0; np < 4; np++) {
                int row = (np << 4) + b_row;
                int f4  = (ks << 1) + b_cs;
                uint32_t addr = vt_base + ((row * 64 + ((f4 ^ (row & 7)) << 2)) << 2);
                uint32_t t0, t1, t2, t3;
                LDSM_X4(t0, t1, t2, t3, addr);
                vf[np * 2 + 0][0] = t0; vf[np * 2 + 0][1] = t1;
                vf[np * 2 + 1][0] = t2; vf[np * 2 + 1][1] = t3;
            }
            #pragma unroll
            for (int dt = 0; dt < 8; dt++) MMA_TF32(o[dt], pa, vf[dt]);
        }
    }

    // final reduce of lp/lm across the quad
    lp0 += __shfl_xor_sync(0xffffffffu, lp0, 1); lp0 += __shfl_xor_sync(0xffffffffu, lp0, 2);
    lm0 += __shfl_xor_sync(0xffffffffu, lm0, 1); lm0 += __shfl_xor_sync(0xffffffffu, lm0, 2);
    lp1 += __shfl_xor_sync(0xffffffffu, lp1, 1); lp1 += __shfl_xor_sync(0xffffffffu, lp1, 2);
    lm1 += __shfl_xor_sync(0xffffffffu, lm1, 1); lm1 += __shfl_xor_sync(0xffffffffu, lm1, 2);
    const float inv0 = 1.0f / (lm0 + 1e-8f * lp0);
    const float inv1 = 1.0f / (lm1 + 1e-8f * lp1);

    const int r0 = rowbase + q0 + (warp << 4) + g;
    #pragma unroll
    for (int dt = 0; dt < 8; dt++) {
        int col = h * HD + (dt << 3) + (tg << 1);
        *(float2*)&out[(size_t)r0 * DIM + col] =
            make_float2(tf32r(o[dt][0] * inv0), tf32r(o[dt][1] * inv0));
        *(float2*)&out[(size_t)(r0 + 8) * DIM + col] =
            make_float2(tf32r(o[dt][2] * inv1), tf32r(o[dt][3] * inv1));
    }
}

// ---------------- launch ----------------
#define GEMM_SMEM (2 * (GBM * GBK + GBN * GBK) * 4)
#define ATTN_SMEM ((3 * 64 * 64 + 64) * 4)

extern "C" void kernel_launch(void* const* d_in, const int* in_sizes, int n_in,
                              void* d_out, int out_size)
{
    const float* x      = (const float*)d_in[0];
    const float* elev   = (const float*)d_in[1];
    const float* qkv_w  = (const float*)d_in[2];
    const float* qkv_b  = (const float*)d_in[3];
    const float* proj_w = (const float*)d_in[4];
    const float* proj_b = (const float*)d_in[5];
    const float* ln1_g  = (const float*)d_in[6];
    const float* ln1_b  = (const float*)d_in[7];
    const float* ln2_g  = (const float*)d_in[8];
    const float* ln2_b  = (const float*)d_in[9];
    const float* fc1_w  = (const float*)d_in[10];
    const float* fc1_b  = (const float*)d_in[11];
    const float* fc2_w  = (const float*)d_in[12];
    const float* fc2_b  = (const float*)d_in[13];
    const float* barrier= (const float*)d_in[14];
    float* out = (float*)d_out;

    const int rows = in_sizes[0] / DIM;     // B*N
    const int B = rows / NLEN;

    float *h, *qkv, *attn, *x2, *ff, *vt, *wtq, *wtp, *wt1, *wt2;
    cudaGetSymbolAddress((void**)&h,    g_h);
    cudaGetSymbolAddress((void**)&qkv,  g_qkv);
    cudaGetSymbolAddress((void**)&attn, g_attn);
    cudaGetSymbolAddress((void**)&x2,   g_x2);
    cudaGetSymbolAddress((void**)&ff,   g_ff);
    cudaGetSymbolAddress((void**)&vt,   g_vt);
    cudaGetSymbolAddress((void**)&wtq,  g_wt_qkv);
    cudaGetSymbolAddress((void**)&wtp,  g_wt_proj);
    cudaGetSymbolAddress((void**)&wt1,  g_wt_fc1);
    cudaGetSymbolAddress((void**)&wt2,  g_wt_fc2);

    cudaFuncSetAttribute(gemm_tc<0,1>, cudaFuncAttributeMaxDynamicSharedMemorySize, GEMM_SMEM);
    cudaFuncSetAttribute(gemm_tc<1,0>, cudaFuncAttributeMaxDynamicSharedMemorySize, GEMM_SMEM);
    cudaFuncSetAttribute(gemm_tc<2,1>, cudaFuncAttributeMaxDynamicSharedMemorySize, GEMM_SMEM);
    cudaFuncSetAttribute(attn_tc,      cudaFuncAttributeMaxDynamicSharedMemorySize, ATTN_SMEM);

    // 0. weight transposes (+ tf32 rounding)
    transpose_tf32<<<dim3(QKV_N / 32, DIM / 32), 256>>>(qkv_w, wtq, DIM, QKV_N);
    transpose_tf32<<<dim3(DIM / 32, DIM / 32), 256>>>(proj_w, wtp, DIM, DIM);
    transpose_tf32<<<dim3(HIDDEN / 32, DIM / 32), 256>>>(fc1_w, wt1, DIM, HIDDEN);
    transpose_tf32<<<dim3(DIM / 32, HIDDEN / 32), 256>>>(fc2_w, wt2, HIDDEN, DIM);

    // 1. LN1 (tf32-rounded out)
    ln_kernel<<<rows, 256>>>(x, ln1_g, ln1_b, h);
    // 2. QKV projection (tf32-rounded out)
    gemm_tc<0,1><<<dim3(QKV_N / 128, rows / 128), 256, GEMM_SMEM>>>(h, wtq, qkv_b, nullptr, qkv, rows, QKV_N, DIM);
    // 3. V transpose for attention PV mma
    transpose_v<<<dim3(NLEN / 32, HD / 32, B * HEADS), 256>>>(qkv, vt);
    // 4. fused masked flash attention (tensor cores)
    attn_tc<<<dim3(B * HEADS, NLEN / 64), 128, ATTN_SMEM>>>(qkv, vt, elev, barrier, attn);
    // 5. out proj + residual (fp32 out)
    gemm_tc<1,0><<<dim3(DIM / 128, rows / 128), 256, GEMM_SMEM>>>(attn, wtp, proj_b, x, x2, rows, DIM, DIM);
    // 6. LN2 (tf32-rounded out)
    ln_kernel<<<rows, 256>>>(x2, ln2_g, ln2_b, h);
    // 7. FC1 + exact GELU (tf32-rounded out)
    gemm_tc<2,1><<<dim3(HIDDEN / 128, rows / 128), 256, GEMM_SMEM>>>(h, wt1, fc1_b, nullptr, ff, rows, HIDDEN, DIM);
    // 8. FC2 + residual -> output (fp32 out)
    gemm_tc<1,0><<<dim3(DIM / 128, rows / 128), 256, GEMM_SMEM>>>(ff, wt2, fc2_b, x2, out, rows, DIM, HIDDEN);
}

// round 5
// speedup vs baseline: 4.2880x; 1.1315x over previous
#include <cuda_runtime.h>
#include <math.h>
#include <stdint.h>

#define DIM 768
#define HEADS 12
#define HD 64
#define HIDDEN 3072
#define QKV_N 2304
#define MAX_ROWS 4096
#define SCALE 0.125f
#define NLEN 2048

// ---------------- scratch (no allocation allowed) ----------------
__device__ float g_h[MAX_ROWS * DIM];
__device__ float g_qkv[MAX_ROWS * QKV_N];
__device__ float g_attn[MAX_ROWS * DIM];
__device__ float g_x2[MAX_ROWS * DIM];
__device__ float g_ff[MAX_ROWS * HIDDEN];
__device__ float g_vt[2 * HEADS * HD * NLEN];   // V transposed: [bh][d][n]
__device__ float g_wt_qkv[DIM * QKV_N];
__device__ float g_wt_proj[DIM * DIM];
__device__ float g_wt_fc1[DIM * HIDDEN];
__device__ float g_wt_fc2[HIDDEN * DIM];

__device__ __forceinline__ float tf32r(float x) {
    uint32_t u;
    asm("cvt.rna.tf32.f32 %0, %1;" : "=r"(u) : "f"(x));
    return __uint_as_float(u);
}
__device__ __forceinline__ float frcp(float x) {
    float r;
    asm("rcp.approx.f32 %0, %1;" : "=f"(r) : "f"(x));
    return r;
}

#define CP_ASYNC16(dst, src) \
    asm volatile("cp.async.cg.shared.global [%0], [%1], 16;\n" :: "r"(dst), "l"(src))
#define CP_COMMIT() asm volatile("cp.async.commit_group;\n" ::: "memory")
#define CP_WAIT1()  asm volatile("cp.async.wait_group 1;\n" ::: "memory")

#define LDSM_X4(r0, r1, r2, r3, addr) \
    asm volatile("ldmatrix.sync.aligned.m8n8.x4.shared.b16 {%0,%1,%2,%3}, [%4];\n" \
                 : "=r"(r0), "=r"(r1), "=r"(r2), "=r"(r3) : "r"(addr))

#define MMA_TF32(d, a, b) \
    asm volatile("mma.sync.aligned.m16n8k8.row.col.f32.tf32.tf32.f32 " \
                 "{%0,%1,%2,%3}, {%4,%5,%6,%7}, {%8,%9}, {%0,%1,%2,%3};\n" \
                 : "+f"(d[0]), "+f"(d[1]), "+f"(d[2]), "+f"(d[3]) \
                 : "r"(a[0]), "r"(a[1]), "r"(a[2]), "r"(a[3]), "r"(b[0]), "r"(b[1]))

// ---------------- weight transpose + tf32 round ----------------
__global__ __launch_bounds__(256)
void transpose_tf32(const float* __restrict__ W, float* __restrict__ Wt, int K, int N)
{
    __shared__ float t[32][33];
    const int n0 = blockIdx.x * 32, k0 = blockIdx.y * 32;
    const int tx = threadIdx.x & 31, ty = threadIdx.x >> 5;
    #pragma unroll
    for (int i = 0; i < 32; i += 8)
        t[ty + i][tx] = W[(size_t)(k0 + ty + i) * N + n0 + tx];
    __syncthreads();
    #pragma unroll
    for (int i = 0; i < 32; i += 8)
        Wt[(size_t)(n0 + ty + i) * K + k0 + tx] = tf32r(t[tx][ty + i]);
}

// ---------------- V transpose: g_qkv -> g_vt[bh][d][n] ----------------
__global__ __launch_bounds__(256)
void transpose_v(const float* __restrict__ qkv, float* __restrict__ vt)
{
    __shared__ float t[32][33];
    const int bh = blockIdx.z;
    const int b = bh / HEADS, h = bh % HEADS;
    const int n0 = blockIdx.x * 32, d0 = blockIdx.y * 32;
    const int tx = threadIdx.x & 31, ty = threadIdx.x >> 5;
    #pragma unroll
    for (int i = 0; i < 32; i += 8)
        t[ty + i][tx] = qkv[(size_t)(b * NLEN + n0 + ty + i) * QKV_N + 2 * DIM + h * HD + d0 + tx];
    __syncthreads();
    #pragma unroll
    for (int i = 0; i < 32; i += 8)
        vt[(size_t)(bh * HD + d0 + ty + i) * NLEN + n0 + tx] = t[tx][ty + i];
}

// ---------------- LayerNorm (writes tf32-rounded output) ----------------
__global__ __launch_bounds__(256)
void ln_kernel(const float* __restrict__ x, const float* __restrict__ g,
               const float* __restrict__ bta, float* __restrict__ out)
{
    const int row = blockIdx.x;
    const float* xr = x + (size_t)row * DIM;
    const int tid = threadIdx.x;

    float v[3];
    float s = 0.f, s2 = 0.f;
    #pragma unroll
    for (int k = 0; k < 3; k++) {
        float t = xr[tid + 256 * k];
        v[k] = t; s += t; s2 += t * t;
    }
    #pragma unroll
    for (int off = 16; off; off >>= 1) {
        s  += __shfl_down_sync(0xffffffffu, s,  off);
        s2 += __shfl_down_sync(0xffffffffu, s2, off);
    }
    __shared__ float red[2][8];
    const int wid = tid >> 5, lid = tid & 31;
    if (lid == 0) { red[0][wid] = s; red[1][wid] = s2; }
    __syncthreads();
    __shared__ float s_mu, s_inv;
    if (tid == 0) {
        float ts = 0.f, ts2 = 0.f;
        #pragma unroll
        for (int w = 0; w < 8; w++) { ts += red[0][w]; ts2 += red[1][w]; }
        float mu = ts * (1.0f / DIM);
        float var = ts2 * (1.0f / DIM) - mu * mu;
        s_mu = mu;
        s_inv = rsqrtf(var + 1e-5f);
    }
    __syncthreads();
    const float mu = s_mu, inv = s_inv;
    float* outr = out + (size_t)row * DIM;
    #pragma unroll
    for (int k = 0; k < 3; k++) {
        int c = tid + 256 * k;
        outr[c] = tf32r((v[k] - mu) * inv * g[c] + bta[c]);
    }
}

// ---------------- tensor-core GEMM, 3-stage cp.async pipeline ----------------
// C[M,N] = A[M,K] @ Wt[N,K]^T + bias (+epilogue). A and Wt are pre-rounded tf32.
// EPI: 0 = bias, 1 = bias + residual, 2 = bias + exact GELU. ROUND: tf32-round output.
#define GBM 128
#define GBN 128
#define GBK 32

template<int EPI, int ROUND>
__global__ __launch_bounds__(256)
void gemm_tc(const float* __restrict__ A, const float* __restrict__ Wt,
             const float* __restrict__ bias, const float* __restrict__ res,
             float* __restrict__ C, int M, int N, int K)
{
    extern __shared__ float sm[];
    float* As = sm;                     // 3 x 128x32
    float* Bs = sm + 3 * GBM * GBK;     // 3 x 128x32

    const int tid  = threadIdx.x;
    const int lane = tid & 31, warp = tid >> 5;
    const int wm = warp >> 2, wn = warp & 3;
    const int m0 = blockIdx.y << 7, n0 = blockIdx.x << 7;

    const uint32_t as_base = (uint32_t)__cvta_generic_to_shared(As);
    const uint32_t bs_base = (uint32_t)__cvta_generic_to_shared(Bs);

    float acc[4][4][4];
    #pragma unroll
    for (int i = 0; i < 4; i++)
        #pragma unroll
        for (int j = 0; j < 4; j++)
            #pragma unroll
            for (int r = 0; r < 4; r++) acc[i][j][r] = 0.f;

    #define STAGE(buf, k0)                                                              \
        _Pragma("unroll")                                                               \
        for (int s_ = 0; s_ < 4; s_++) {                                                \
            int idx = s_ * 256 + tid;                                                   \
            int r_ = idx >> 3, c_ = idx & 7;                                            \
            uint32_t sw = ((c_ ^ (r_ & 7)) << 2);                                       \
            CP_ASYNC16(as_base + (((buf) * GBM * GBK + r_ * GBK + sw) << 2),            \
                       A + (size_t)(m0 + r_) * K + (k0) + (c_ << 2));                   \
            CP_ASYNC16(bs_base + (((buf) * GBN * GBK + r_ * GBK + sw) << 2),            \
                       Wt + (size_t)(n0 + r_) * K + (k0) + (c_ << 2));                  \
        }

    STAGE(0, 0)
    CP_COMMIT();
    STAGE(1, GBK)
    CP_COMMIT();

    const int a_row = lane & 15, a_cs = lane >> 4;
    const int b_row = ((lane >> 1) & 8) + (lane & 7), b_cs = (lane >> 3) & 1;
    const int kIters = K >> 5;

    int buf = 0;
    for (int it = 0; it < kIters; it++) {
        CP_WAIT1();
        __syncthreads();   // data of tile `it` visible everywhere; buffer (it+2)%3 free

        if (it + 2 < kIters) { STAGE((it + 2) % 3, (it + 2) << 5) }
        CP_COMMIT();

        const uint32_t ab = as_base + ((buf * GBM * GBK) << 2);
        const uint32_t bb = bs_base + ((buf * GBN * GBK) << 2);

        #pragma unroll
        for (int ks = 0; ks < 4; ks++) {
            uint32_t af[4][4], bf[4][2];
            #pragma unroll
            for (int mt = 0; mt < 4; mt++) {
                int row = (wm << 6) + (mt << 4) + a_row;
                int f4  = (ks << 1) + a_cs;
                uint32_t addr = ab + ((row * GBK + ((f4 ^ (row & 7)) << 2)) << 2);
                LDSM_X4(af[mt][0], af[mt][1], af[mt][2], af[mt][3], addr);
            }
            #pragma unroll
            for (int np = 0; np < 2; np++) {
                int row = (wn << 5) + (np << 4) + b_row;
                int f4  = (ks << 1) + b_cs;
                uint32_t addr = bb + ((row * GBK + ((f4 ^ (row & 7)) << 2)) << 2);
                uint32_t q0, q1, q2, q3;
                LDSM_X4(q0, q1, q2, q3, addr);
                bf[np * 2 + 0][0] = q0; bf[np * 2 + 0][1] = q1;
                bf[np * 2 + 1][0] = q2; bf[np * 2 + 1][1] = q3;
            }
            #pragma unroll
            for (int mt = 0; mt < 4; mt++)
                #pragma unroll
                for (int nt = 0; nt < 4; nt++)
                    MMA_TF32(acc[mt][nt], af[mt], bf[nt]);
        }
        buf++; if (buf == 3) buf = 0;
    }
    #undef STAGE

    const int g = lane >> 2, tg = lane & 3;
    #pragma unroll
    for (int mt = 0; mt < 4; mt++) {
        #pragma unroll
        for (int nt = 0; nt < 4; nt++) {
            int row = m0 + (wm << 6) + (mt << 4) + g;
            int col = n0 + (wn << 5) + (nt << 3) + (tg << 1);
            float b0 = bias[col], b1 = bias[col + 1];
            #pragma unroll
            for (int half = 0; half < 2; half++) {
                int r = row + half * 8;
                float v0 = acc[mt][nt][half * 2 + 0] + b0;
                float v1 = acc[mt][nt][half * 2 + 1] + b1;
                if (EPI == 1) {
                    const float2 rr = *(const float2*)&res[(size_t)r * N + col];
                    v0 += rr.x; v1 += rr.y;
                }
                if (EPI == 2) {
                    v0 = 0.5f * v0 * (1.0f + erff(v0 * 0.70710678118654752f));
                    v1 = 0.5f * v1 * (1.0f + erff(v1 * 0.70710678118654752f));
                }
                if (ROUND) { v0 = tf32r(v0); v1 = tf32r(v1); }
                *(float2*)&C[(size_t)r * N + col] = make_float2(v0, v1);
            }
        }
    }
}

// ---------------- tensor-core flash attention ----------------
// CTA: 256 threads = 8 warps, each warp owns 16 q-rows => Q tile = 128 rows.
// Key tile = 64, double-buffered via cp.async. S = (Q*SCALE)@K^T (tf32 mma),
// online softmax with dual sums lp/lm; mask factorized:
// sigmoid(-bar*(ej-ei)) = 1/(1 + Ej*Fi), Ej=exp(bar*ej) staged per tile,
// Fi=exp(-bar*ei) per q-row. O += P @ V^T with V pre-transposed globally.
#define AQT 128
#define AKT 64

__global__ __launch_bounds__(256)
void attn_tc(const float* __restrict__ qkv, const float* __restrict__ vt,
             const float* __restrict__ elev, const float* __restrict__ barrier,
             float* __restrict__ out)
{
    extern __shared__ float sm[];
    float* Ks  = sm;                        // 2 x 64x64
    float* Vts = sm + 2 * AKT * HD;         // 2 x 64x64
    float* QP  = sm + 4 * AKT * HD;         // 128x64 (Q staging, then per-warp P)
    float* es  = sm + 4 * AKT * HD + AQT * HD;  // 2 x 64 (exp(bar*ej))

    const int bh = blockIdx.x, b = bh / HEADS, h = bh % HEADS;
    const int q0 = blockIdx.y * AQT;
    const int tid = threadIdx.x, lane = tid & 31, warp = tid >> 5;
    const int rowbase = b * NLEN;
    const float bar = *barrier;

    const uint32_t ks_base = (uint32_t)__cvta_generic_to_shared(Ks);
    const uint32_t vt_base = (uint32_t)__cvta_generic_to_shared(Vts);
    const uint32_t qp_base = (uint32_t)__cvta_generic_to_shared(QP);

    // stage Q tile (pre-scaled; values already tf32 so *0.125 is exact)
    #pragma unroll
    for (int it = 0; it < 8; it++) {
        int idx = it * 256 + tid;
        int rr = idx >> 4, cc = idx & 15;
        float4 v = *(const float4*)(qkv + (size_t)(rowbase + q0 + rr) * QKV_N + h * HD + cc * 4);
        v.x *= SCALE; v.y *= SCALE; v.z *= SCALE; v.w *= SCALE;
        *(float4*)(QP + rr * HD + ((cc ^ (rr & 7)) << 2)) = v;
    }

    // stage K/V tile 0 + exp'd elevations (cp.async for K/V)
    #define STAGE_KV(buf, j0)                                                            \
        _Pragma("unroll")                                                                \
        for (int it_ = 0; it_ < 4; it_++) {                                              \
            int idx = it_ * 256 + tid;                                                   \
            int rr = idx >> 4, cc = idx & 15;                                            \
            uint32_t sw = (((buf) * AKT * HD + rr * HD + ((cc ^ (rr & 7)) << 2)) << 2);  \
            CP_ASYNC16(ks_base + sw,                                                     \
                qkv + (size_t)(rowbase + (j0) + rr) * QKV_N + DIM + h * HD + cc * 4);    \
            CP_ASYNC16(vt_base + sw,                                                     \
                vt + (size_t)(bh * HD + rr) * NLEN + (j0) + cc * 4);                     \
        }

    STAGE_KV(0, 0)
    if (tid < AKT) es[tid] = __expf(bar * elev[rowbase + tid]);
    CP_COMMIT();
    __syncthreads();   // Q tile in smem

    const int a_row = lane & 15, a_cs = lane >> 4;
    const int b_row = ((lane >> 1) & 8) + (lane & 7), b_cs = (lane >> 3) & 1;

    // Q fragments (held for the whole kernel); each warp reads only its 16 rows
    uint32_t qa[8][4];
    #pragma unroll
    for (int ks = 0; ks < 8; ks++) {
        int row = (warp << 4) + a_row;
        int f4  = (ks << 1) + a_cs;
        uint32_t addr = qp_base + ((row * HD + ((f4 ^ (row & 7)) << 2)) << 2);
        LDSM_X4(qa[ks][0], qa[ks][1], qa[ks][2], qa[ks][3], addr);
    }

    const int g = lane >> 2, tg = lane & 3;
    const float Fi0 = __expf(-bar * elev[rowbase + q0 + (warp << 4) + g]);
    const float Fi1 = __expf(-bar * elev[rowbase + q0 + (warp << 4) + g + 8]);

    float m0 = -1e30f, m1 = -1e30f;
    float lp0 = 0.f, lm0 = 0.f, lp1 = 0.f, lm1 = 0.f;
    float o[8][4];
    #pragma unroll
    for (int dt = 0; dt < 8; dt++)
        #pragma unroll
        for (int r = 0; r < 4; r++) o[dt][r] = 0.f;

    const int nTiles = NLEN / AKT;
    for (int t = 0; t < nTiles; t++) {
        const int buf = t & 1;
        // stage next tile while this one computes
        if (t + 1 < nTiles) {
            STAGE_KV(buf ^ 1, (t + 1) * AKT)
            if (tid < AKT) es[(buf ^ 1) * AKT + tid] = __expf(bar * elev[rowbase + (t + 1) * AKT + tid]);
        }
        CP_COMMIT();
        CP_WAIT1();
        __syncthreads();   // tile t (K/V via cp.async + es via STS) visible

        const uint32_t kb = ks_base + ((buf * AKT * HD) << 2);
        const uint32_t vb = vt_base + ((buf * AKT * HD) << 2);
        const float* esb = es + buf * AKT;

        // ---- S = Qs @ Ks^T ----
        float s[8][4];
        #pragma unroll
        for (int nt = 0; nt < 8; nt++)
            #pragma unroll
            for (int r = 0; r < 4; r++) s[nt][r] = 0.f;

        #pragma unroll
        for (int ks = 0; ks < 8; ks++) {
            uint32_t bf[8][2];
            #pragma unroll
            for (int np = 0; np < 4; np++) {
                int row = (np << 4) + b_row;
                int f4  = (ks << 1) + b_cs;
                uint32_t addr = kb + ((row * HD + ((f4 ^ (row & 7)) << 2)) << 2);
                uint32_t t0, t1, t2, t3;
                LDSM_X4(t0, t1, t2, t3, addr);
                bf[np * 2 + 0][0] = t0; bf[np * 2 + 0][1] = t1;
                bf[np * 2 + 1][0] = t2; bf[np * 2 + 1][1] = t3;
            }
            #pragma unroll
            for (int nt = 0; nt < 8; nt++) MMA_TF32(s[nt], qa[ks], bf[nt]);
        }

        // ---- online softmax ----
        float r0 = -1e30f, r1 = -1e30f;
        #pragma unroll
        for (int nt = 0; nt < 8; nt++) {
            r0 = fmaxf(r0, fmaxf(s[nt][0], s[nt][1]));
            r1 = fmaxf(r1, fmaxf(s[nt][2], s[nt][3]));
        }
        r0 = fmaxf(r0, __shfl_xor_sync(0xffffffffu, r0, 1));
        r0 = fmaxf(r0, __shfl_xor_sync(0xffffffffu, r0, 2));
        r1 = fmaxf(r1, __shfl_xor_sync(0xffffffffu, r1, 1));
        r1 = fmaxf(r1, __shfl_xor_sync(0xffffffffu, r1, 2));

        float nm0 = fmaxf(m0, r0), nm1 = fmaxf(m1, r1);
        float al0 = __expf(m0 - nm0), al1 = __expf(m1 - nm1);
        m0 = nm0; m1 = nm1;
        lp0 *= al0; lm0 *= al0; lp1 *= al1; lm1 *= al1;
        #pragma unroll
        for (int dt = 0; dt < 8; dt++) {
            o[dt][0] *= al0; o[dt][1] *= al0;
            o[dt][2] *= al1; o[dt][3] *= al1;
        }

        #pragma unroll
        for (int nt = 0; nt < 8; nt++) {
            int c = (nt << 3) + (tg << 1);
            float Ej0 = esb[c], Ej1 = esb[c + 1];
            float mk00 = fminf(fmaxf(frcp(fmaf(Ej0, Fi0, 1.0f)), 1e-6f), 1.0f);
            float mk01 = fminf(fmaxf(frcp(fmaf(Ej1, Fi0, 1.0f)), 1e-6f), 1.0f);
            float mk10 = fminf(fmaxf(frcp(fmaf(Ej0, Fi1, 1.0f)), 1e-6f), 1.0f);
            float mk11 = fminf(fmaxf(frcp(fmaf(Ej1, Fi1, 1.0f)), 1e-6f), 1.0f);

            float p00 = __expf(s[nt][0] - m0), p01 = __expf(s[nt][1] - m0);
            float p10 = __expf(s[nt][2] - m1), p11 = __expf(s[nt][3] - m1);
            lp0 += p00 + p01; lp1 += p10 + p11;
            float pm00 = p00 * mk00, pm01 = p01 * mk01;
            float pm10 = p10 * mk10, pm11 = p11 * mk11;
            lm0 += pm00 + pm01; lm1 += pm10 + pm11;

            int row0 = (warp << 4) + g;
            uint32_t u0 = row0 * HD + (((c >> 2) ^ (row0 & 7)) << 2) + (c & 3);
            *(float2*)(QP + u0) = make_float2(tf32r(pm00), tf32r(pm01));
            int row1 = row0 + 8;
            uint32_t u1 = row1 * HD + (((c >> 2) ^ (row1 & 7)) << 2) + (c & 3);
            *(float2*)(QP + u1) = make_float2(tf32r(pm10), tf32r(pm11));
        }
        __syncwarp();

        // ---- O += P @ Vts^T ----
        #pragma unroll
        for (int ks = 0; ks < 8; ks++) {
            uint32_t pa[4];
            {
                int row = (warp << 4) + a_row;
                int f4  = (ks << 1) + a_cs;
                uint32_t addr = qp_base + ((row * HD + ((f4 ^ (row & 7)) << 2)) << 2);
                LDSM_X4(pa[0], pa[1], pa[2], pa[3], addr);
            }
            uint32_t vf[8][2];
            #pragma unroll
            for (int np = 0; np < 4; np++) {
                int row = (np << 4) + b_row;
                int f4  = (ks << 1) + b_cs;
                uint32_t addr = vb + ((row * HD + ((f4 ^ (row & 7)) << 2)) << 2);
                uint32_t t0, t1, t2, t3;
                LDSM_X4(t0, t1, t2, t3, addr);
                vf[np * 2 + 0][0] = t0; vf[np * 2 + 0][1] = t1;
                vf[np * 2 + 1][0] = t2; vf[np * 2 + 1][1] = t3;
            }
            #pragma unroll
            for (int dt = 0; dt < 8; dt++) MMA_TF32(o[dt], pa, vf[dt]);
        }
        __syncthreads();   // all warps done with tile t before buf^1 is restaged
    }
    #undef STAGE_KV

    // final reduce of lp/lm across the quad
    lp0 += __shfl_xor_sync(0xffffffffu, lp0, 1); lp0 += __shfl_xor_sync(0xffffffffu, lp0, 2);
    lm0 += __shfl_xor_sync(0xffffffffu, lm0, 1); lm0 += __shfl_xor_sync(0xffffffffu, lm0, 2);
    lp1 += __shfl_xor_sync(0xffffffffu, lp1, 1); lp1 += __shfl_xor_sync(0xffffffffu, lp1, 2);
    lm1 += __shfl_xor_sync(0xffffffffu, lm1, 1); lm1 += __shfl_xor_sync(0xffffffffu, lm1, 2);
    const float inv0 = 1.0f / (lm0 + 1e-8f * lp0);
    const float inv1 = 1.0f / (lm1 + 1e-8f * lp1);

    const int r0 = rowbase + q0 + (warp << 4) + g;
    #pragma unroll
    for (int dt = 0; dt < 8; dt++) {
        int col = h * HD + (dt << 3) + (tg << 1);
        *(float2*)&out[(size_t)r0 * DIM + col] =
            make_float2(tf32r(o[dt][0] * inv0), tf32r(o[dt][1] * inv0));
        *(float2*)&out[(size_t)(r0 + 8) * DIM + col] =
            make_float2(tf32r(o[dt][2] * inv1), tf32r(o[dt][3] * inv1));
    }
}

// ---------------- launch ----------------
#define GEMM_SMEM (3 * (GBM * GBK + GBN * GBK) * 4)
#define ATTN_SMEM ((4 * AKT * HD + AQT * HD + 2 * AKT) * 4)

extern "C" void kernel_launch(void* const* d_in, const int* in_sizes, int n_in,
                              void* d_out, int out_size)
{
    const float* x      = (const float*)d_in[0];
    const float* elev   = (const float*)d_in[1];
    const float* qkv_w  = (const float*)d_in[2];
    const float* qkv_b  = (const float*)d_in[3];
    const float* proj_w = (const float*)d_in[4];
    const float* proj_b = (const float*)d_in[5];
    const float* ln1_g  = (const float*)d_in[6];
    const float* ln1_b  = (const float*)d_in[7];
    const float* ln2_g  = (const float*)d_in[8];
    const float* ln2_b  = (const float*)d_in[9];
    const float* fc1_w  = (const float*)d_in[10];
    const float* fc1_b  = (const float*)d_in[11];
    const float* fc2_w  = (const float*)d_in[12];
    const float* fc2_b  = (const float*)d_in[13];
    const float* barrier= (const float*)d_in[14];
    float* out = (float*)d_out;

    const int rows = in_sizes[0] / DIM;     // B*N
    const int B = rows / NLEN;

    float *h, *qkv, *attn, *x2, *ff, *vt, *wtq, *wtp, *wt1, *wt2;
    cudaGetSymbolAddress((void**)&h,    g_h);
    cudaGetSymbolAddress((void**)&qkv,  g_qkv);
    cudaGetSymbolAddress((void**)&attn, g_attn);
    cudaGetSymbolAddress((void**)&x2,   g_x2);
    cudaGetSymbolAddress((void**)&ff,   g_ff);
    cudaGetSymbolAddress((void**)&vt,   g_vt);
    cudaGetSymbolAddress((void**)&wtq,  g_wt_qkv);
    cudaGetSymbolAddress((void**)&wtp,  g_wt_proj);
    cudaGetSymbolAddress((void**)&wt1,  g_wt_fc1);
    cudaGetSymbolAddress((void**)&wt2,  g_wt_fc2);

    cudaFuncSetAttribute(gemm_tc<0,1>, cudaFuncAttributeMaxDynamicSharedMemorySize, GEMM_SMEM);
    cudaFuncSetAttribute(gemm_tc<1,0>, cudaFuncAttributeMaxDynamicSharedMemorySize, GEMM_SMEM);
    cudaFuncSetAttribute(gemm_tc<2,1>, cudaFuncAttributeMaxDynamicSharedMemorySize, GEMM_SMEM);
    cudaFuncSetAttribute(attn_tc,      cudaFuncAttributeMaxDynamicSharedMemorySize, ATTN_SMEM);

    // 0. weight transposes (+ tf32 rounding)
    transpose_tf32<<<dim3(QKV_N / 32, DIM / 32), 256>>>(qkv_w, wtq, DIM, QKV_N);
    transpose_tf32<<<dim3(DIM / 32, DIM / 32), 256>>>(proj_w, wtp, DIM, DIM);
    transpose_tf32<<<dim3(HIDDEN / 32, DIM / 32), 256>>>(fc1_w, wt1, DIM, HIDDEN);
    transpose_tf32<<<dim3(DIM / 32, HIDDEN / 32), 256>>>(fc2_w, wt2, HIDDEN, DIM);

    // 1. LN1 (tf32-rounded out)
    ln_kernel<<<rows, 256>>>(x, ln1_g, ln1_b, h);
    // 2. QKV projection (tf32-rounded out)
    gemm_tc<0,1><<<dim3(QKV_N / 128, rows / 128), 256, GEMM_SMEM>>>(h, wtq, qkv_b, nullptr, qkv, rows, QKV_N, DIM);
    // 3. V transpose for attention PV mma
    transpose_v<<<dim3(NLEN / 32, HD / 32, B * HEADS), 256>>>(qkv, vt);
    // 4. fused masked flash attention (tensor cores)
    attn_tc<<<dim3(B * HEADS, NLEN / AQT), 256, ATTN_SMEM>>>(qkv, vt, elev, barrier, attn);
    // 5. out proj + residual (fp32 out)
    gemm_tc<1,0><<<dim3(DIM / 128, rows / 128), 256, GEMM_SMEM>>>(attn, wtp, proj_b, x, x2, rows, DIM, DIM);
    // 6. LN2 (tf32-rounded out)
    ln_kernel<<<rows, 256>>>(x2, ln2_g, ln2_b, h);
    // 7. FC1 + exact GELU (tf32-rounded out)
    gemm_tc<2,1><<<dim3(HIDDEN / 128, rows / 128), 256, GEMM_SMEM>>>(h, wt1, fc1_b, nullptr, ff, rows, HIDDEN, DIM);
    // 8. FC2 + residual -> output (fp32 out)
    gemm_tc<1,0><<<dim3(DIM / 128, rows / 128), 256, GEMM_SMEM>>>(ff, wt2, fc2_b, x2, out, rows, DIM, HIDDEN);
}

// round 6
// speedup vs baseline: 5.9715x; 1.3926x over previous
#include <cuda_runtime.h>
#include <cuda_fp16.h>
#include <math.h>
#include <stdint.h>

#define DIM 768
#define HEADS 12
#define HD 64
#define HIDDEN 3072
#define QKV_N 2304
#define MAX_ROWS 4096
#define SCALE 0.125f
#define NLEN 2048

// ---------------- scratch (no allocation allowed) ----------------
__device__ __half g_h[MAX_ROWS * DIM];
__device__ __half g_qkv[MAX_ROWS * QKV_N];
__device__ __half g_attn[MAX_ROWS * DIM];
__device__ float  g_x2[MAX_ROWS * DIM];
__device__ __half g_ff[MAX_ROWS * HIDDEN];
__device__ __half g_vt[2 * HEADS * HD * NLEN];   // V transposed: [bh][d][n]
__device__ __half g_wt_qkv[DIM * QKV_N];
__device__ __half g_wt_proj[DIM * DIM];
__device__ __half g_wt_fc1[DIM * HIDDEN];
__device__ __half g_wt_fc2[HIDDEN * DIM];

__device__ __forceinline__ float frcp(float x) {
    float r;
    asm("rcp.approx.f32 %0, %1;" : "=f"(r) : "f"(x));
    return r;
}

#define CP_ASYNC16(dst, src) \
    asm volatile("cp.async.cg.shared.global [%0], [%1], 16;\n" :: "r"(dst), "l"(src))
#define CP_COMMIT() asm volatile("cp.async.commit_group;\n" ::: "memory")
#define CP_WAIT1()  asm volatile("cp.async.wait_group 1;\n" ::: "memory")

#define LDSM_X4(r0, r1, r2, r3, addr) \
    asm volatile("ldmatrix.sync.aligned.m8n8.x4.shared.b16 {%0,%1,%2,%3}, [%4];\n" \
                 : "=r"(r0), "=r"(r1), "=r"(r2), "=r"(r3) : "r"(addr))

#define MMA_F16(d, a, b) \
    asm volatile("mma.sync.aligned.m16n8k16.row.col.f32.f16.f16.f32 " \
                 "{%0,%1,%2,%3}, {%4,%5,%6,%7}, {%8,%9}, {%0,%1,%2,%3};\n" \
                 : "+f"(d[0]), "+f"(d[1]), "+f"(d[2]), "+f"(d[3]) \
                 : "r"(a[0]), "r"(a[1]), "r"(a[2]), "r"(a[3]), "r"(b[0]), "r"(b[1]))

// ---------------- weight transpose + fp16 convert ----------------
__global__ __launch_bounds__(256)
void transpose_h(const float* __restrict__ W, __half* __restrict__ Wt, int K, int N)
{
    __shared__ float t[32][33];
    const int n0 = blockIdx.x * 32, k0 = blockIdx.y * 32;
    const int tx = threadIdx.x & 31, ty = threadIdx.x >> 5;
    #pragma unroll
    for (int i = 0; i < 32; i += 8)
        t[ty + i][tx] = W[(size_t)(k0 + ty + i) * N + n0 + tx];
    __syncthreads();
    #pragma unroll
    for (int i = 0; i < 32; i += 8)
        Wt[(size_t)(n0 + ty + i) * K + k0 + tx] = __float2half_rn(t[tx][ty + i]);
}

// ---------------- V transpose: g_qkv -> g_vt[bh][d][n] (fp16) ----------------
__global__ __launch_bounds__(256)
void transpose_v(const __half* __restrict__ qkv, __half* __restrict__ vt)
{
    __shared__ __half t[32][40];
    const int bh = blockIdx.z;
    const int b = bh / HEADS, h = bh % HEADS;
    const int n0 = blockIdx.x * 32, d0 = blockIdx.y * 32;
    const int tx = threadIdx.x & 31, ty = threadIdx.x >> 5;
    #pragma unroll
    for (int i = 0; i < 32; i += 8)
        t[ty + i][tx] = qkv[(size_t)(b * NLEN + n0 + ty + i) * QKV_N + 2 * DIM + h * HD + d0 + tx];
    __syncthreads();
    #pragma unroll
    for (int i = 0; i < 32; i += 8)
        vt[(size_t)(bh * HD + d0 + ty + i) * NLEN + n0 + tx] = t[tx][ty + i];
}

// ---------------- LayerNorm (fp32 in, fp16 out) ----------------
__global__ __launch_bounds__(256)
void ln_kernel(const float* __restrict__ x, const float* __restrict__ g,
               const float* __restrict__ bta, __half* __restrict__ out)
{
    const int row = blockIdx.x;
    const float* xr = x + (size_t)row * DIM;
    const int tid = threadIdx.x;

    float v[3];
    float s = 0.f, s2 = 0.f;
    #pragma unroll
    for (int k = 0; k < 3; k++) {
        float t = xr[tid + 256 * k];
        v[k] = t; s += t; s2 += t * t;
    }
    #pragma unroll
    for (int off = 16; off; off >>= 1) {
        s  += __shfl_down_sync(0xffffffffu, s,  off);
        s2 += __shfl_down_sync(0xffffffffu, s2, off);
    }
    __shared__ float red[2][8];
    const int wid = tid >> 5, lid = tid & 31;
    if (lid == 0) { red[0][wid] = s; red[1][wid] = s2; }
    __syncthreads();
    __shared__ float s_mu, s_inv;
    if (tid == 0) {
        float ts = 0.f, ts2 = 0.f;
        #pragma unroll
        for (int w = 0; w < 8; w++) { ts += red[0][w]; ts2 += red[1][w]; }
        float mu = ts * (1.0f / DIM);
        float var = ts2 * (1.0f / DIM) - mu * mu;
        s_mu = mu;
        s_inv = rsqrtf(var + 1e-5f);
    }
    __syncthreads();
    const float mu = s_mu, inv = s_inv;
    __half* outr = out + (size_t)row * DIM;
    #pragma unroll
    for (int k = 0; k < 3; k++) {
        int c = tid + 256 * k;
        outr[c] = __float2half_rn((v[k] - mu) * inv * g[c] + bta[c]);
    }
}

// ---------------- fp16 tensor-core GEMM, 3-stage cp.async pipeline ----------------
// C[M,N] = A[M,K] @ Wt[N,K]^T + bias (+epilogue). A, Wt fp16; accum fp32.
// Tile 128x128x64. EPI: 0=bias, 1=bias+residual(fp32), 2=bias+exact GELU.
// OUTH: 1 -> fp16 output, 0 -> fp32 output.
#define GBM 128
#define GBN 128
#define GBK 64
#define GTILE (GBM * GBK * 2)   // bytes per A (or B) stage = 16384

template<int EPI, int OUTH>
__global__ __launch_bounds__(256)
void gemm_tc(const __half* __restrict__ A, const __half* __restrict__ Wt,
             const float* __restrict__ bias, const float* __restrict__ res,
             void* __restrict__ Cout, int M, int N, int K)
{
    extern __shared__ char sm[];
    const int tid  = threadIdx.x;
    const int lane = tid & 31, warp = tid >> 5;
    const int wm = warp >> 2, wn = warp & 3;
    const int m0 = blockIdx.y << 7, n0 = blockIdx.x << 7;

    const uint32_t as_base = (uint32_t)__cvta_generic_to_shared(sm);
    const uint32_t bs_base = as_base + 3 * GTILE;

    float acc[4][4][4];
    #pragma unroll
    for (int i = 0; i < 4; i++)
        #pragma unroll
        for (int j = 0; j < 4; j++)
            #pragma unroll
            for (int r = 0; r < 4; r++) acc[i][j][r] = 0.f;

    #define STAGE(buf, k0)                                                              \
        _Pragma("unroll")                                                               \
        for (int s_ = 0; s_ < 4; s_++) {                                                \
            int idx = s_ * 256 + tid;                                                   \
            int r_ = idx >> 3, c_ = idx & 7;                                            \
            uint32_t sw = (buf) * GTILE + r_ * 128 + ((c_ ^ (r_ & 7)) << 4);            \
            CP_ASYNC16(as_base + sw, A  + (size_t)(m0 + r_) * K + (k0) + c_ * 8);       \
            CP_ASYNC16(bs_base + sw, Wt + (size_t)(n0 + r_) * K + (k0) + c_ * 8);       \
        }

    STAGE(0, 0)
    CP_COMMIT();
    STAGE(1, GBK)
    CP_COMMIT();

    const int a_row = lane & 15, a_hi = lane >> 4;
    const int kIters = K / GBK;

    int buf = 0;
    for (int it = 0; it < kIters; it++) {
        CP_WAIT1();
        __syncthreads();

        if (it + 2 < kIters) { STAGE((it + 2) % 3, (it + 2) * GBK) }
        CP_COMMIT();

        const uint32_t ab = as_base + buf * GTILE;
        const uint32_t bb = bs_base + buf * GTILE;

        #pragma unroll
        for (int ks = 0; ks < 4; ks++) {
            const int f8 = (ks << 1) + a_hi;
            uint32_t af[4][4], bf[4][2];
            #pragma unroll
            for (int mt = 0; mt < 4; mt++) {
                int row = (wm << 6) + (mt << 4) + a_row;
                uint32_t addr = ab + row * 128 + ((f8 ^ (row & 7)) << 4);
                LDSM_X4(af[mt][0], af[mt][1], af[mt][2], af[mt][3], addr);
            }
            #pragma unroll
            for (int np = 0; np < 2; np++) {
                int row = (wn << 5) + (np << 4) + a_row;
                uint32_t addr = bb + row * 128 + ((f8 ^ (row & 7)) << 4);
                uint32_t q0, q1, q2, q3;
                LDSM_X4(q0, q1, q2, q3, addr);
                bf[np * 2 + 0][0] = q0; bf[np * 2 + 0][1] = q2;
                bf[np * 2 + 1][0] = q1; bf[np * 2 + 1][1] = q3;
            }
            #pragma unroll
            for (int mt = 0; mt < 4; mt++)
                #pragma unroll
                for (int nt = 0; nt < 4; nt++)
                    MMA_F16(acc[mt][nt], af[mt], bf[nt]);
        }
        buf++; if (buf == 3) buf = 0;
    }
    #undef STAGE

    const int g = lane >> 2, tg = lane & 3;
    #pragma unroll
    for (int mt = 0; mt < 4; mt++) {
        #pragma unroll
        for (int nt = 0; nt < 4; nt++) {
            int row = m0 + (wm << 6) + (mt << 4) + g;
            int col = n0 + (wn << 5) + (nt << 3) + (tg << 1);
            float b0 = bias[col], b1 = bias[col + 1];
            #pragma unroll
            for (int half = 0; half < 2; half++) {
                int r = row + half * 8;
                float v0 = acc[mt][nt][half * 2 + 0] + b0;
                float v1 = acc[mt][nt][half * 2 + 1] + b1;
                if (EPI == 1) {
                    const float2 rr = *(const float2*)&res[(size_t)r * N + col];
                    v0 += rr.x; v1 += rr.y;
                }
                if (EPI == 2) {
                    v0 = 0.5f * v0 * (1.0f + erff(v0 * 0.70710678118654752f));
                    v1 = 0.5f * v1 * (1.0f + erff(v1 * 0.70710678118654752f));
                }
                if (OUTH) {
                    *(__half2*)((__half*)Cout + (size_t)r * N + col) = __floats2half2_rn(v0, v1);
                } else {
                    *(float2*)((float*)Cout + (size_t)r * N + col) = make_float2(v0, v1);
                }
            }
        }
    }
}

// ---------------- fp16 tensor-core flash attention ----------------
// CTA: 256 threads = 8 warps, each warp 16 q-rows => Q tile 128. Key tile 64,
// double-buffered cp.async. S=(Q*0.125)@K^T fp16 mma (fp32 accum), online
// softmax with dual sums lp/lm; mask = 1/(1+Ej*Fi) factorized sigmoid.
// O += P @ V^T with V pre-transposed. All operands fp16, accum fp32.
#define AQT 128
#define AKT 64
#define KVTILE (AKT * HD * 2)    // 8192 bytes

__global__ __launch_bounds__(256)
void attn_tc(const __half* __restrict__ qkv, const __half* __restrict__ vt,
             const float* __restrict__ elev, const float* __restrict__ barrier,
             __half* __restrict__ out)
{
    extern __shared__ char sm[];
    const uint32_t smb     = (uint32_t)__cvta_generic_to_shared(sm);
    const uint32_t ks_base = smb;                 // 2 x 8192
    const uint32_t vt_base = smb + 2 * KVTILE;    // 2 x 8192
    const uint32_t qp_base = smb + 4 * KVTILE;    // 128*128 = 16384
    char* qp_ptr = sm + 4 * KVTILE;
    float* es = (float*)(sm + 4 * KVTILE + AQT * 128);   // 2 x 64 floats

    const int bh = blockIdx.x, b = bh / HEADS, h = bh % HEADS;
    const int q0 = blockIdx.y * AQT;
    const int tid = threadIdx.x, lane = tid & 31, warp = tid >> 5;
    const int rowbase = b * NLEN;
    const float bar = *barrier;

    // stage Q tile (scaled by 0.125 — exact power of 2 in fp16)
    const __half2 sc2 = __floats2half2_rn(SCALE, SCALE);
    #pragma unroll
    for (int it = 0; it < 4; it++) {
        int idx = it * 256 + tid;
        int rr = idx >> 3, cc = idx & 7;
        uint4 v = *(const uint4*)(qkv + (size_t)(rowbase + q0 + rr) * QKV_N + h * HD + cc * 8);
        __half2* hv = (__half2*)&v;
        hv[0] = __hmul2(hv[0], sc2); hv[1] = __hmul2(hv[1], sc2);
        hv[2] = __hmul2(hv[2], sc2); hv[3] = __hmul2(hv[3], sc2);
        *(uint4*)(qp_ptr + rr * 128 + ((cc ^ (rr & 7)) << 4)) = v;
    }

    #define STAGE_KV(buf, j0)                                                            \
        _Pragma("unroll")                                                                \
        for (int it_ = 0; it_ < 2; it_++) {                                              \
            int idx = it_ * 256 + tid;                                                   \
            int rr = idx >> 3, cc = idx & 7;                                             \
            uint32_t sw = (buf) * KVTILE + rr * 128 + ((cc ^ (rr & 7)) << 4);            \
            CP_ASYNC16(ks_base + sw,                                                     \
                qkv + (size_t)(rowbase + (j0) + rr) * QKV_N + DIM + h * HD + cc * 8);    \
            CP_ASYNC16(vt_base + sw,                                                     \
                vt + (size_t)(bh * HD + rr) * NLEN + (j0) + cc * 8);                     \
        }

    STAGE_KV(0, 0)
    if (tid < AKT) es[tid] = __expf(bar * elev[rowbase + tid]);
    CP_COMMIT();
    __syncthreads();   // Q tile + es[0] visible

    const int a_row = lane & 15, a_hi = lane >> 4;

    // Q fragments for the whole kernel (each warp reads only its 16 rows)
    uint32_t qa[4][4];
    #pragma unroll
    for (int ks = 0; ks < 4; ks++) {
        int row = (warp << 4) + a_row;
        int f8  = (ks << 1) + a_hi;
        uint32_t addr = qp_base + row * 128 + ((f8 ^ (row & 7)) << 4);
        LDSM_X4(qa[ks][0], qa[ks][1], qa[ks][2], qa[ks][3], addr);
    }

    const int g = lane >> 2, tg = lane & 3;
    const float Fi0 = __expf(-bar * elev[rowbase + q0 + (warp << 4) + g]);
    const float Fi1 = __expf(-bar * elev[rowbase + q0 + (warp << 4) + g + 8]);

    float m0 = -1e30f, m1 = -1e30f;
    float lp0 = 0.f, lm0 = 0.f, lp1 = 0.f, lm1 = 0.f;
    float o[8][4];
    #pragma unroll
    for (int dt = 0; dt < 8; dt++)
        #pragma unroll
        for (int r = 0; r < 4; r++) o[dt][r] = 0.f;

    const int nTiles = NLEN / AKT;
    for (int t = 0; t < nTiles; t++) {
        const int buf = t & 1;
        if (t + 1 < nTiles) {
            STAGE_KV(buf ^ 1, (t + 1) * AKT)
            if (tid < AKT) es[(buf ^ 1) * AKT + tid] = __expf(bar * elev[rowbase + (t + 1) * AKT + tid]);
        }
        CP_COMMIT();
        CP_WAIT1();
        __syncthreads();

        const uint32_t kb = ks_base + buf * KVTILE;
        const uint32_t vb = vt_base + buf * KVTILE;
        const float* esb = es + buf * AKT;

        // ---- S = Qs @ Ks^T ----
        float s[8][4];
        #pragma unroll
        for (int nt = 0; nt < 8; nt++)
            #pragma unroll
            for (int r = 0; r < 4; r++) s[nt][r] = 0.f;

        #pragma unroll
        for (int ks = 0; ks < 4; ks++) {
            const int f8 = (ks << 1) + a_hi;
            uint32_t bf[8][2];
            #pragma unroll
            for (int np = 0; np < 4; np++) {
                int row = (np << 4) + a_row;
                uint32_t addr = kb + row * 128 + ((f8 ^ (row & 7)) << 4);
                uint32_t t0, t1, t2, t3;
                LDSM_X4(t0, t1, t2, t3, addr);
                bf[np * 2 + 0][0] = t0; bf[np * 2 + 0][1] = t2;
                bf[np * 2 + 1][0] = t1; bf[np * 2 + 1][1] = t3;
            }
            #pragma unroll
            for (int nt = 0; nt < 8; nt++) MMA_F16(s[nt], qa[ks], bf[nt]);
        }

        // ---- online softmax ----
        float r0 = -1e30f, r1 = -1e30f;
        #pragma unroll
        for (int nt = 0; nt < 8; nt++) {
            r0 = fmaxf(r0, fmaxf(s[nt][0], s[nt][1]));
            r1 = fmaxf(r1, fmaxf(s[nt][2], s[nt][3]));
        }
        r0 = fmaxf(r0, __shfl_xor_sync(0xffffffffu, r0, 1));
        r0 = fmaxf(r0, __shfl_xor_sync(0xffffffffu, r0, 2));
        r1 = fmaxf(r1, __shfl_xor_sync(0xffffffffu, r1, 1));
        r1 = fmaxf(r1, __shfl_xor_sync(0xffffffffu, r1, 2));

        float nm0 = fmaxf(m0, r0), nm1 = fmaxf(m1, r1);
        float al0 = __expf(m0 - nm0), al1 = __expf(m1 - nm1);
        m0 = nm0; m1 = nm1;
        lp0 *= al0; lm0 *= al0; lp1 *= al1; lm1 *= al1;
        #pragma unroll
        for (int dt = 0; dt < 8; dt++) {
            o[dt][0] *= al0; o[dt][1] *= al0;
            o[dt][2] *= al1; o[dt][3] *= al1;
        }

        const int row0 = (warp << 4) + g;
        const int row1 = row0 + 8;
        #pragma unroll
        for (int nt = 0; nt < 8; nt++) {
            int c = (nt << 3) + (tg << 1);
            float Ej0 = esb[c], Ej1 = esb[c + 1];
            float mk00 = fminf(fmaxf(frcp(fmaf(Ej0, Fi0, 1.0f)), 1e-6f), 1.0f);
            float mk01 = fminf(fmaxf(frcp(fmaf(Ej1, Fi0, 1.0f)), 1e-6f), 1.0f);
            float mk10 = fminf(fmaxf(frcp(fmaf(Ej0, Fi1, 1.0f)), 1e-6f), 1.0f);
            float mk11 = fminf(fmaxf(frcp(fmaf(Ej1, Fi1, 1.0f)), 1e-6f), 1.0f);

            float p00 = __expf(s[nt][0] - m0), p01 = __expf(s[nt][1] - m0);
            float p10 = __expf(s[nt][2] - m1), p11 = __expf(s[nt][3] - m1);
            lp0 += p00 + p01; lp1 += p10 + p11;
            float pm00 = p00 * mk00, pm01 = p01 * mk01;
            float pm10 = p10 * mk10, pm11 = p11 * mk11;
            lm0 += pm00 + pm01; lm1 += pm10 + pm11;

            *(__half2*)(qp_ptr + row0 * 128 + (((c >> 3) ^ (row0 & 7)) << 4) + ((c & 7) << 1)) =
                __floats2half2_rn(pm00, pm01);
            *(__half2*)(qp_ptr + row1 * 128 + (((c >> 3) ^ (row1 & 7)) << 4) + ((c & 7) << 1)) =
                __floats2half2_rn(pm10, pm11);
        }
        __syncwarp();

        // ---- O += P @ Vts^T ----
        #pragma unroll
        for (int ks = 0; ks < 4; ks++) {
            const int f8 = (ks << 1) + a_hi;
            uint32_t pa[4];
            {
                int row = (warp << 4) + a_row;
                uint32_t addr = qp_base + row * 128 + ((f8 ^ (row & 7)) << 4);
                LDSM_X4(pa[0], pa[1], pa[2], pa[3], addr);
            }
            uint32_t vf[8][2];
            #pragma unroll
            for (int np = 0; np < 4; np++) {
                int row = (np << 4) + a_row;
                uint32_t addr = vb + row * 128 + ((f8 ^ (row & 7)) << 4);
                uint32_t t0, t1, t2, t3;
                LDSM_X4(t0, t1, t2, t3, addr);
                vf[np * 2 + 0][0] = t0; vf[np * 2 + 0][1] = t2;
                vf[np * 2 + 1][0] = t1; vf[np * 2 + 1][1] = t3;
            }
            #pragma unroll
            for (int dt = 0; dt < 8; dt++) MMA_F16(o[dt], pa, vf[dt]);
        }
        __syncthreads();   // all warps done with tile t before it is restaged
    }
    #undef STAGE_KV

    lp0 += __shfl_xor_sync(0xffffffffu, lp0, 1); lp0 += __shfl_xor_sync(0xffffffffu, lp0, 2);
    lm0 += __shfl_xor_sync(0xffffffffu, lm0, 1); lm0 += __shfl_xor_sync(0xffffffffu, lm0, 2);
    lp1 += __shfl_xor_sync(0xffffffffu, lp1, 1); lp1 += __shfl_xor_sync(0xffffffffu, lp1, 2);
    lm1 += __shfl_xor_sync(0xffffffffu, lm1, 1); lm1 += __shfl_xor_sync(0xffffffffu, lm1, 2);
    const float inv0 = 1.0f / (lm0 + 1e-8f * lp0);
    const float inv1 = 1.0f / (lm1 + 1e-8f * lp1);

    const int r0 = rowbase + q0 + (warp << 4) + g;
    #pragma unroll
    for (int dt = 0; dt < 8; dt++) {
        int col = h * HD + (dt << 3) + (tg << 1);
        *(__half2*)&out[(size_t)r0 * DIM + col] =
            __floats2half2_rn(o[dt][0] * inv0, o[dt][1] * inv0);
        *(__half2*)&out[(size_t)(r0 + 8) * DIM + col] =
            __floats2half2_rn(o[dt][2] * inv1, o[dt][3] * inv1);
    }
}

// ---------------- launch ----------------
#define GEMM_SMEM (6 * GTILE)
#define ATTN_SMEM (4 * KVTILE + AQT * 128 + 2 * AKT * 4)

extern "C" void kernel_launch(void* const* d_in, const int* in_sizes, int n_in,
                              void* d_out, int out_size)
{
    const float* x      = (const float*)d_in[0];
    const float* elev   = (const float*)d_in[1];
    const float* qkv_w  = (const float*)d_in[2];
    const float* qkv_b  = (const float*)d_in[3];
    const float* proj_w = (const float*)d_in[4];
    const float* proj_b = (const float*)d_in[5];
    const float* ln1_g  = (const float*)d_in[6];
    const float* ln1_b  = (const float*)d_in[7];
    const float* ln2_g  = (const float*)d_in[8];
    const float* ln2_b  = (const float*)d_in[9];
    const float* fc1_w  = (const float*)d_in[10];
    const float* fc1_b  = (const float*)d_in[11];
    const float* fc2_w  = (const float*)d_in[12];
    const float* fc2_b  = (const float*)d_in[13];
    const float* barrier= (const float*)d_in[14];
    float* out = (float*)d_out;

    const int rows = in_sizes[0] / DIM;     // B*N
    const int B = rows / NLEN;

    __half *h, *qkv, *attn, *ff, *vt, *wtq, *wtp, *wt1, *wt2;
    float *x2;
    cudaGetSymbolAddress((void**)&h,    g_h);
    cudaGetSymbolAddress((void**)&qkv,  g_qkv);
    cudaGetSymbolAddress((void**)&attn, g_attn);
    cudaGetSymbolAddress((void**)&x2,   g_x2);
    cudaGetSymbolAddress((void**)&ff,   g_ff);
    cudaGetSymbolAddress((void**)&vt,   g_vt);
    cudaGetSymbolAddress((void**)&wtq,  g_wt_qkv);
    cudaGetSymbolAddress((void**)&wtp,  g_wt_proj);
    cudaGetSymbolAddress((void**)&wt1,  g_wt_fc1);
    cudaGetSymbolAddress((void**)&wt2,  g_wt_fc2);

    cudaFuncSetAttribute(gemm_tc<0,1>, cudaFuncAttributeMaxDynamicSharedMemorySize, GEMM_SMEM);
    cudaFuncSetAttribute(gemm_tc<1,0>, cudaFuncAttributeMaxDynamicSharedMemorySize, GEMM_SMEM);
    cudaFuncSetAttribute(gemm_tc<2,1>, cudaFuncAttributeMaxDynamicSharedMemorySize, GEMM_SMEM);
    cudaFuncSetAttribute(attn_tc,      cudaFuncAttributeMaxDynamicSharedMemorySize, ATTN_SMEM);

    // 0. weight transposes + fp16 convert
    transpose_h<<<dim3(QKV_N / 32, DIM / 32), 256>>>(qkv_w, wtq, DIM, QKV_N);
    transpose_h<<<dim3(DIM / 32, DIM / 32), 256>>>(proj_w, wtp, DIM, DIM);
    transpose_h<<<dim3(HIDDEN / 32, DIM / 32), 256>>>(fc1_w, wt1, DIM, HIDDEN);
    transpose_h<<<dim3(DIM / 32, HIDDEN / 32), 256>>>(fc2_w, wt2, HIDDEN, DIM);

    // 1. LN1 (fp16 out)
    ln_kernel<<<rows, 256>>>(x, ln1_g, ln1_b, h);
    // 2. QKV projection (fp16 out)
    gemm_tc<0,1><<<dim3(QKV_N / 128, rows / 128), 256, GEMM_SMEM>>>(h, wtq, qkv_b, nullptr, qkv, rows, QKV_N, DIM);
    // 3. V transpose for attention PV mma
    transpose_v<<<dim3(NLEN / 32, HD / 32, B * HEADS), 256>>>(qkv, vt);
    // 4. fused masked flash attention (fp16 tensor cores)
    attn_tc<<<dim3(B * HEADS, NLEN / AQT), 256, ATTN_SMEM>>>(qkv, vt, elev, barrier, attn);
    // 5. out proj + residual (fp32 out)
    gemm_tc<1,0><<<dim3(DIM / 128, rows / 128), 256, GEMM_SMEM>>>(attn, wtp, proj_b, x, x2, rows, DIM, DIM);
    // 6. LN2 (fp16 out)
    ln_kernel<<<rows, 256>>>(x2, ln2_g, ln2_b, h);
    // 7. FC1 + exact GELU (fp16 out)
    gemm_tc<2,1><<<dim3(HIDDEN / 128, rows / 128), 256, GEMM_SMEM>>>(h, wt1, fc1_b, nullptr, ff, rows, HIDDEN, DIM);
    // 8. FC2 + residual -> output (fp32)
    gemm_tc<1,0><<<dim3(DIM / 128, rows / 128), 256, GEMM_SMEM>>>(ff, wt2, fc2_b, x2, out, rows, DIM, HIDDEN);
}

// round 8
// speedup vs baseline: 6.2266x; 1.0427x over previous
#include <cuda_runtime.h>
#include <cuda_fp16.h>
#include <math.h>
#include <stdint.h>

#define DIM 768
#define HEADS 12
#define HD 64
#define HIDDEN 3072
#define QKV_N 2304
#define MAX_ROWS 4096
#define SCALE 0.125f
#define NLEN 2048

// ---------------- scratch (no allocation allowed) ----------------
__device__ __half g_h[MAX_ROWS * DIM];
__device__ __half g_qkv[MAX_ROWS * QKV_N];
__device__ __half g_attn[MAX_ROWS * DIM];
__device__ float  g_x2[MAX_ROWS * DIM];
__device__ __half g_ff[MAX_ROWS * HIDDEN];
__device__ __half g_vt[2 * HEADS * HD * NLEN];   // V transposed: [bh][d][n]
__device__ __half g_wt_qkv[DIM * QKV_N];
__device__ __half g_wt_proj[DIM * DIM];
__device__ __half g_wt_fc1[DIM * HIDDEN];
__device__ __half g_wt_fc2[HIDDEN * DIM];

__device__ __forceinline__ float frcp(float x) {
    float r;
    asm("rcp.approx.f32 %0, %1;" : "=f"(r) : "f"(x));
    return r;
}

#define CP_ASYNC16(dst, src) \
    asm volatile("cp.async.cg.shared.global [%0], [%1], 16;\n" :: "r"(dst), "l"(src))
#define CP_COMMIT() asm volatile("cp.async.commit_group;\n" ::: "memory")
#define CP_WAIT1()  asm volatile("cp.async.wait_group 1;\n" ::: "memory")
#define CP_WAIT0()  asm volatile("cp.async.wait_group 0;\n" ::: "memory")

#define LDSM_X4(r0, r1, r2, r3, addr) \
    asm volatile("ldmatrix.sync.aligned.m8n8.x4.shared.b16 {%0,%1,%2,%3}, [%4];\n" \
                 : "=r"(r0), "=r"(r1), "=r"(r2), "=r"(r3) : "r"(addr))

#define MMA_F16(d, a, b) \
    asm volatile("mma.sync.aligned.m16n8k16.row.col.f32.f16.f16.f32 " \
                 "{%0,%1,%2,%3}, {%4,%5,%6,%7}, {%8,%9}, {%0,%1,%2,%3};\n" \
                 : "+f"(d[0]), "+f"(d[1]), "+f"(d[2]), "+f"(d[3]) \
                 : "r"(a[0]), "r"(a[1]), "r"(a[2]), "r"(a[3]), "r"(b[0]), "r"(b[1]))

// ---------------- all 4 weight transposes in ONE launch ----------------
// segments (32x32 tiles): qkv 72x24=1728 | proj 24x24=576 | fc1 96x24=2304 | fc2 24x96=2304
__global__ __launch_bounds__(256)
void transpose_all(const float* __restrict__ w0, const float* __restrict__ w1,
                   const float* __restrict__ w2, const float* __restrict__ w3,
                   __half* __restrict__ o0, __half* __restrict__ o1,
                   __half* __restrict__ o2, __half* __restrict__ o3)
{
    int bid = blockIdx.x;
    const float* W; __half* Wt; int K, N;
    if (bid < 1728)      { W = w0; Wt = o0; K = DIM;    N = QKV_N;  }
    else if (bid < 2304) { W = w1; Wt = o1; K = DIM;    N = DIM;    bid -= 1728; }
    else if (bid < 4608) { W = w2; Wt = o2; K = DIM;    N = HIDDEN; bid -= 2304; }
    else                 { W = w3; Wt = o3; K = HIDDEN; N = DIM;    bid -= 4608; }
    const int nb = N / 32;
    const int n0 = (bid % nb) * 32, k0 = (bid / nb) * 32;

    __shared__ float t[32][33];
    const int tx = threadIdx.x & 31, ty = threadIdx.x >> 5;
    #pragma unroll
    for (int i = 0; i < 32; i += 8)
        t[ty + i][tx] = W[(size_t)(k0 + ty + i) * N + n0 + tx];
    __syncthreads();
    #pragma unroll
    for (int i = 0; i < 32; i += 8)
        Wt[(size_t)(n0 + ty + i) * K + k0 + tx] = __float2half_rn(t[tx][ty + i]);
}

// ---------------- V transpose: g_qkv -> g_vt[bh][d][n] (fp16) ----------------
__global__ __launch_bounds__(256)
void transpose_v(const __half* __restrict__ qkv, __half* __restrict__ vt)
{
    __shared__ __half t[32][40];
    const int bh = blockIdx.z;
    const int b = bh / HEADS, h = bh % HEADS;
    const int n0 = blockIdx.x * 32, d0 = blockIdx.y * 32;
    const int tx = threadIdx.x & 31, ty = threadIdx.x >> 5;
    #pragma unroll
    for (int i = 0; i < 32; i += 8)
        t[ty + i][tx] = qkv[(size_t)(b * NLEN + n0 + ty + i) * QKV_N + 2 * DIM + h * HD + d0 + tx];
    __syncthreads();
    #pragma unroll
    for (int i = 0; i < 32; i += 8)
        vt[(size_t)(bh * HD + d0 + ty + i) * NLEN + n0 + tx] = t[tx][ty + i];
}

// ---------------- LayerNorm: warp per row, float4 I/O ----------------
__global__ __launch_bounds__(256)
void ln_kernel(const float* __restrict__ x, const float* __restrict__ g,
               const float* __restrict__ bta, __half* __restrict__ out)
{
    const int lane = threadIdx.x & 31;
    const int row = blockIdx.x * 8 + (threadIdx.x >> 5);
    const float* xr = x + (size_t)row * DIM;

    float4 v[6];
    float s = 0.f, s2 = 0.f;
    #pragma unroll
    for (int i = 0; i < 6; i++) {
        v[i] = *(const float4*)(xr + (i * 32 + lane) * 4);
        s  += v[i].x + v[i].y + v[i].z + v[i].w;
        s2 += v[i].x * v[i].x + v[i].y * v[i].y + v[i].z * v[i].z + v[i].w * v[i].w;
    }
    #pragma unroll
    for (int off = 16; off; off >>= 1) {
        s  += __shfl_xor_sync(0xffffffffu, s,  off);
        s2 += __shfl_xor_sync(0xffffffffu, s2, off);
    }
    const float mu  = s * (1.0f / DIM);
    const float inv = rsqrtf(s2 * (1.0f / DIM) - mu * mu + 1e-5f);

    __half* outr = out + (size_t)row * DIM;
    #pragma unroll
    for (int i = 0; i < 6; i++) {
        int c = (i * 32 + lane) * 4;
        float4 gg = *(const float4*)(g + c);
        float4 bb = *(const float4*)(bta + c);
        __half2 h0 = __floats2half2_rn((v[i].x - mu) * inv * gg.x + bb.x,
                                       (v[i].y - mu) * inv * gg.y + bb.y);
        __half2 h1 = __floats2half2_rn((v[i].z - mu) * inv * gg.z + bb.z,
                                       (v[i].w - mu) * inv * gg.w + bb.w);
        uint2 u;
        u.x = *(uint32_t*)&h0; u.y = *(uint32_t*)&h1;
        *(uint2*)(outr + c) = u;
    }
}

// ---------------- fp16 tensor-core GEMM, 2-stage cp.async, 2 CTAs/SM ----------------
// C[M,N] = A[M,K] @ Wt[N,K]^T + bias (+epilogue). A, Wt fp16; accum fp32.
// Tile 128x128x64. EPI: 0=bias, 1=bias+residual(fp32), 2=bias+exact GELU.
// OUTH: 1 -> fp16 output, 0 -> fp32 output.
#define GBM 128
#define GBN 128
#define GBK 64
#define GTILE (GBM * GBK * 2)   // bytes per A (or B) stage = 16384
#define GEMM_SMEM (4 * GTILE)   // 2 stages x (A + B) = 64 KB

template<int EPI, int OUTH>
__global__ __launch_bounds__(256, 2)
void gemm_tc(const __half* __restrict__ A, const __half* __restrict__ Wt,
             const float* __restrict__ bias, const float* __restrict__ res,
             void* __restrict__ Cout, int M, int N, int K)
{
    extern __shared__ char sm[];
    const int tid  = threadIdx.x;
    const int lane = tid & 31, warp = tid >> 5;
    const int wm = warp >> 2, wn = warp & 3;
    const int m0 = blockIdx.y << 7, n0 = blockIdx.x << 7;

    const uint32_t as_base = (uint32_t)__cvta_generic_to_shared(sm);
    const uint32_t bs_base = as_base + 2 * GTILE;

    float acc[4][4][4];
    #pragma unroll
    for (int i = 0; i < 4; i++)
        #pragma unroll
        for (int j = 0; j < 4; j++)
            #pragma unroll
            for (int r = 0; r < 4; r++) acc[i][j][r] = 0.f;

    #define STAGE(buf, k0)                                                              \
        _Pragma("unroll")                                                               \
        for (int s_ = 0; s_ < 4; s_++) {                                                \
            int idx = s_ * 256 + tid;                                                   \
            int r_ = idx >> 3, c_ = idx & 7;                                            \
            uint32_t sw = (buf) * GTILE + r_ * 128 + ((c_ ^ (r_ & 7)) << 4);            \
            CP_ASYNC16(as_base + sw, A  + (size_t)(m0 + r_) * K + (k0) + c_ * 8);       \
            CP_ASYNC16(bs_base + sw, Wt + (size_t)(n0 + r_) * K + (k0) + c_ * 8);       \
        }

    STAGE(0, 0)
    CP_COMMIT();

    const int a_row = lane & 15, a_hi = lane >> 4;
    const int kIters = K / GBK;

    for (int it = 0; it < kIters; it++) {
        const int buf = it & 1;
        if (it + 1 < kIters) {
            STAGE(buf ^ 1, (it + 1) * GBK)
            CP_COMMIT();
            CP_WAIT1();
        } else {
            CP_WAIT0();
        }
        __syncthreads();   // tile `it` visible everywhere

        const uint32_t ab = as_base + buf * GTILE;
        const uint32_t bb = bs_base + buf * GTILE;

        #pragma unroll
        for (int ks = 0; ks < 4; ks++) {
            const int f8 = (ks << 1) + a_hi;
            uint32_t af[4][4], bf[4][2];
            #pragma unroll
            for (int mt = 0; mt < 4; mt++) {
                int row = (wm << 6) + (mt << 4) + a_row;
                uint32_t addr = ab + row * 128 + ((f8 ^ (row & 7)) << 4);
                LDSM_X4(af[mt][0], af[mt][1], af[mt][2], af[mt][3], addr);
            }
            #pragma unroll
            for (int np = 0; np < 2; np++) {
                int row = (wn << 5) + (np << 4) + a_row;
                uint32_t addr = bb + row * 128 + ((f8 ^ (row & 7)) << 4);
                uint32_t q0, q1, q2, q3;
                LDSM_X4(q0, q1, q2, q3, addr);
                bf[np * 2 + 0][0] = q0; bf[np * 2 + 0][1] = q2;
                bf[np * 2 + 1][0] = q1; bf[np * 2 + 1][1] = q3;
            }
            #pragma unroll
            for (int mt = 0; mt < 4; mt++)
                #pragma unroll
                for (int nt = 0; nt < 4; nt++)
                    MMA_F16(acc[mt][nt], af[mt], bf[nt]);
        }
        __syncthreads();   // all warps done with `buf` before next stage overwrites it
    }
    #undef STAGE

    const int g = lane >> 2, tg = lane & 3;
    #pragma unroll
    for (int mt = 0; mt < 4; mt++) {
        #pragma unroll
        for (int nt = 0; nt < 4; nt++) {
            int row = m0 + (wm << 6) + (mt << 4) + g;
            int col = n0 + (wn << 5) + (nt << 3) + (tg << 1);
            float b0 = bias[col], b1 = bias[col + 1];
            #pragma unroll
            for (int half = 0; half < 2; half++) {
                int r = row + half * 8;
                float v0 = acc[mt][nt][half * 2 + 0] + b0;
                float v1 = acc[mt][nt][half * 2 + 1] + b1;
                if (EPI == 1) {
                    const float2 rr = *(const float2*)&res[(size_t)r * N + col];
                    v0 += rr.x; v1 += rr.y;
                }
                if (EPI == 2) {
                    v0 = 0.5f * v0 * (1.0f + erff(v0 * 0.70710678118654752f));
                    v1 = 0.5f * v1 * (1.0f + erff(v1 * 0.70710678118654752f));
                }
                if (OUTH) {
                    *(__half2*)((__half*)Cout + (size_t)r * N + col) = __floats2half2_rn(v0, v1);
                } else {
                    *(float2*)((float*)Cout + (size_t)r * N + col) = make_float2(v0, v1);
                }
            }
        }
    }
}

// ---------------- fp16 tensor-core flash attention ----------------
// CTA: 256 threads = 8 warps, each warp 16 q-rows => Q tile 128. Key tile 64,
// double-buffered cp.async. S=(Q*0.125)@K^T fp16 mma (fp32 accum), online
// softmax with dual sums lp/lm; mask = 1/(1+Ej*Fi) factorized sigmoid.
// O += P @ V^T with V pre-transposed. All operands fp16, accum fp32.
#define AQT 128
#define AKT 64
#define KVTILE (AKT * HD * 2)    // 8192 bytes

__global__ __launch_bounds__(256)
void attn_tc(const __half* __restrict__ qkv, const __half* __restrict__ vt,
             const float* __restrict__ elev, const float* __restrict__ barrier,
             __half* __restrict__ out)
{
    extern __shared__ char sm[];
    const uint32_t smb     = (uint32_t)__cvta_generic_to_shared(sm);
    const uint32_t ks_base = smb;
    const uint32_t vt_base = smb + 2 * KVTILE;
    const uint32_t qp_base = smb + 4 * KVTILE;
    char* qp_ptr = sm + 4 * KVTILE;
    float* es = (float*)(sm + 4 * KVTILE + AQT * 128);

    const int bh = blockIdx.x, b = bh / HEADS, h = bh % HEADS;
    const int q0 = blockIdx.y * AQT;
    const int tid = threadIdx.x, lane = tid & 31, warp = tid >> 5;
    const int rowbase = b * NLEN;
    const float bar = *barrier;

    const __half2 sc2 = __floats2half2_rn(SCALE, SCALE);
    #pragma unroll
    for (int it = 0; it < 4; it++) {
        int idx = it * 256 + tid;
        int rr = idx >> 3, cc = idx & 7;
        uint4 v = *(const uint4*)(qkv + (size_t)(rowbase + q0 + rr) * QKV_N + h * HD + cc * 8);
        __half2* hv = (__half2*)&v;
        hv[0] = __hmul2(hv[0], sc2); hv[1] = __hmul2(hv[1], sc2);
        hv[2] = __hmul2(hv[2], sc2); hv[3] = __hmul2(hv[3], sc2);
        *(uint4*)(qp_ptr + rr * 128 + ((cc ^ (rr & 7)) << 4)) = v;
    }

    #define STAGE_KV(buf, j0)                                                            \
        _Pragma("unroll")                                                                \
        for (int it_ = 0; it_ < 2; it_++) {                                              \
            int idx = it_ * 256 + tid;                                                   \
            int rr = idx >> 3, cc = idx & 7;                                             \
            uint32_t sw = (buf) * KVTILE + rr * 128 + ((cc ^ (rr & 7)) << 4);            \
            CP_ASYNC16(ks_base + sw,                                                     \
                qkv + (size_t)(rowbase + (j0) + rr) * QKV_N + DIM + h * HD + cc * 8);    \
            CP_ASYNC16(vt_base + sw,                                                     \
                vt + (size_t)(bh * HD + rr) * NLEN + (j0) + cc * 8);                     \
        }

    STAGE_KV(0, 0)
    if (tid < AKT) es[tid] = __expf(bar * elev[rowbase + tid]);
    CP_COMMIT();
    __syncthreads();

    const int a_row = lane & 15, a_hi = lane >> 4;

    uint32_t qa[4][4];
    #pragma unroll
    for (int ks = 0; ks < 4; ks++) {
        int row = (warp << 4) + a_row;
        int f8  = (ks << 1) + a_hi;
        uint32_t addr = qp_base + row * 128 + ((f8 ^ (row & 7)) << 4);
        LDSM_X4(qa[ks][0], qa[ks][1], qa[ks][2], qa[ks][3], addr);
    }

    const int g = lane >> 2, tg = lane & 3;
    const float Fi0 = __expf(-bar * elev[rowbase + q0 + (warp << 4) + g]);
    const float Fi1 = __expf(-bar * elev[rowbase + q0 + (warp << 4) + g + 8]);

    float m0 = -1e30f, m1 = -1e30f;
    float lp0 = 0.f, lm0 = 0.f, lp1 = 0.f, lm1 = 0.f;
    float o[8][4];
    #pragma unroll
    for (int dt = 0; dt < 8; dt++)
        #pragma unroll
        for (int r = 0; r < 4; r++) o[dt][r] = 0.f;

    const int nTiles = NLEN / AKT;
    for (int t = 0; t < nTiles; t++) {
        const int buf = t & 1;
        if (t + 1 < nTiles) {
            STAGE_KV(buf ^ 1, (t + 1) * AKT)
            if (tid < AKT) es[(buf ^ 1) * AKT + tid] = __expf(bar * elev[rowbase + (t + 1) * AKT + tid]);
        }
        CP_COMMIT();
        CP_WAIT1();
        __syncthreads();

        const uint32_t kb = ks_base + buf * KVTILE;
        const uint32_t vb = vt_base + buf * KVTILE;
        const float* esb = es + buf * AKT;

        float s[8][4];
        #pragma unroll
        for (int nt = 0; nt < 8; nt++)
            #pragma unroll
            for (int r = 0; r < 4; r++) s[nt][r] = 0.f;

        #pragma unroll
        for (int ks = 0; ks < 4; ks++) {
            const int f8 = (ks << 1) + a_hi;
            uint32_t bf[8][2];
            #pragma unroll
            for (int np = 0; np < 4; np++) {
                int row = (np << 4) + a_row;
                uint32_t addr = kb + row * 128 + ((f8 ^ (row & 7)) << 4);
                uint32_t t0, t1, t2, t3;
                LDSM_X4(t0, t1, t2, t3, addr);
                bf[np * 2 + 0][0] = t0; bf[np * 2 + 0][1] = t2;
                bf[np * 2 + 1][0] = t1; bf[np * 2 + 1][1] = t3;
            }
            #pragma unroll
            for (int nt = 0; nt < 8; nt++) MMA_F16(s[nt], qa[ks], bf[nt]);
        }

        float r0 = -1e30f, r1 = -1e30f;
        #pragma unroll
        for (int nt = 0; nt < 8; nt++) {
            r0 = fmaxf(r0, fmaxf(s[nt][0], s[nt][1]));
            r1 = fmaxf(r1, fmaxf(s[nt][2], s[nt][3]));
        }
        r0 = fmaxf(r0, __shfl_xor_sync(0xffffffffu, r0, 1));
        r0 = fmaxf(r0, __shfl_xor_sync(0xffffffffu, r0, 2));
        r1 = fmaxf(r1, __shfl_xor_sync(0xffffffffu, r1, 1));
        r1 = fmaxf(r1, __shfl_xor_sync(0xffffffffu, r1, 2));

        float nm0 = fmaxf(m0, r0), nm1 = fmaxf(m1, r1);
        float al0 = __expf(m0 - nm0), al1 = __expf(m1 - nm1);
        m0 = nm0; m1 = nm1;
        lp0 *= al0; lm0 *= al0; lp1 *= al1; lm1 *= al1;
        #pragma unroll
        for (int dt = 0; dt < 8; dt++) {
            o[dt][0] *= al0; o[dt][1] *= al0;
            o[dt][2] *= al1; o[dt][3] *= al1;
        }

        const int row0 = (warp << 4) + g;
        const int row1 = row0 + 8;
        #pragma unroll
        for (int nt = 0; nt < 8; nt++) {
            int c = (nt << 3) + (tg << 1);
            float Ej0 = esb[c], Ej1 = esb[c + 1];
            float mk00 = fminf(fmaxf(frcp(fmaf(Ej0, Fi0, 1.0f)), 1e-6f), 1.0f);
            float mk01 = fminf(fmaxf(frcp(fmaf(Ej1, Fi0, 1.0f)), 1e-6f), 1.0f);
            float mk10 = fminf(fmaxf(frcp(fmaf(Ej0, Fi1, 1.0f)), 1e-6f), 1.0f);
            float mk11 = fminf(fmaxf(frcp(fmaf(Ej1, Fi1, 1.0f)), 1e-6f), 1.0f);

            float p00 = __expf(s[nt][0] - m0), p01 = __expf(s[nt][1] - m0);
            float p10 = __expf(s[nt][2] - m1), p11 = __expf(s[nt][3] - m1);
            lp0 += p00 + p01; lp1 += p10 + p11;
            float pm00 = p00 * mk00, pm01 = p01 * mk01;
            float pm10 = p10 * mk10, pm11 = p11 * mk11;
            lm0 += pm00 + pm01; lm1 += pm10 + pm11;

            *(__half2*)(qp_ptr + row0 * 128 + (((c >> 3) ^ (row0 & 7)) << 4) + ((c & 7) << 1)) =
                __floats2half2_rn(pm00, pm01);
            *(__half2*)(qp_ptr + row1 * 128 + (((c >> 3) ^ (row1 & 7)) << 4) + ((c & 7) << 1)) =
                __floats2half2_rn(pm10, pm11);
        }
        __syncwarp();

        #pragma unroll
        for (int ks = 0; ks < 4; ks++) {
            const int f8 = (ks << 1) + a_hi;
            uint32_t pa[4];
            {
                int row = (warp << 4) + a_row;
                uint32_t addr = qp_base + row * 128 + ((f8 ^ (row & 7)) << 4);
                LDSM_X4(pa[0], pa[1], pa[2], pa[3], addr);
            }
            uint32_t vf[8][2];
            #pragma unroll
            for (int np = 0; np < 4; np++) {
                int row = (np << 4) + a_row;
                uint32_t addr = vb + row * 128 + ((f8 ^ (row & 7)) << 4);
                uint32_t t0, t1, t2, t3;
                LDSM_X4(t0, t1, t2, t3, addr);
                vf[np * 2 + 0][0] = t0; vf[np * 2 + 0][1] = t2;
                vf[np * 2 + 1][0] = t1; vf[np * 2 + 1][1] = t3;
            }
            #pragma unroll
            for (int dt = 0; dt < 8; dt++) MMA_F16(o[dt], pa, vf[dt]);
        }
        __syncthreads();
    }
    #undef STAGE_KV

    lp0 += __shfl_xor_sync(0xffffffffu, lp0, 1); lp0 += __shfl_xor_sync(0xffffffffu, lp0, 2);
    lm0 += __shfl_xor_sync(0xffffffffu, lm0, 1); lm0 += __shfl_xor_sync(0xffffffffu, lm0, 2);
    lp1 += __shfl_xor_sync(0xffffffffu, lp1, 1); lp1 += __shfl_xor_sync(0xffffffffu, lp1, 2);
    lm1 += __shfl_xor_sync(0xffffffffu, lm1, 1); lm1 += __shfl_xor_sync(0xffffffffu, lm1, 2);
    const float inv0 = 1.0f / (lm0 + 1e-8f * lp0);
    const float inv1 = 1.0f / (lm1 + 1e-8f * lp1);

    const int r0 = rowbase + q0 + (warp << 4) + g;
    #pragma unroll
    for (int dt = 0; dt < 8; dt++) {
        int col = h * HD + (dt << 3) + (tg << 1);
        *(__half2*)&out[(size_t)r0 * DIM + col] =
            __floats2half2_rn(o[dt][0] * inv0, o[dt][1] * inv0);
        *(__half2*)&out[(size_t)(r0 + 8) * DIM + col] =
            __floats2half2_rn(o[dt][2] * inv1, o[dt][3] * inv1);
    }
}

// ---------------- launch ----------------
#define ATTN_SMEM (4 * KVTILE + AQT * 128 + 2 * AKT * 4)

extern "C" void kernel_launch(void* const* d_in, const int* in_sizes, int n_in,
                              void* d_out, int out_size)
{
    const float* x      = (const float*)d_in[0];
    const float* elev   = (const float*)d_in[1];
    const float* qkv_w  = (const float*)d_in[2];
    const float* qkv_b  = (const float*)d_in[3];
    const float* proj_w = (const float*)d_in[4];
    const float* proj_b = (const float*)d_in[5];
    const float* ln1_g  = (const float*)d_in[6];
    const float* ln1_b  = (const float*)d_in[7];
    const float* ln2_g  = (const float*)d_in[8];
    const float* ln2_b  = (const float*)d_in[9];
    const float* fc1_w  = (const float*)d_in[10];
    const float* fc1_b  = (const float*)d_in[11];
    const float* fc2_w  = (const float*)d_in[12];
    const float* fc2_b  = (const float*)d_in[13];
    const float* barrier= (const float*)d_in[14];
    float* out = (float*)d_out;

    const int rows = in_sizes[0] / DIM;     // B*N
    const int B = rows / NLEN;

    __half *h, *qkv, *attn, *ff, *vt, *wtq, *wtp, *wt1, *wt2;
    float *x2;
    cudaGetSymbolAddress((void**)&h,    g_h);
    cudaGetSymbolAddress((void**)&qkv,  g_qkv);
    cudaGetSymbolAddress((void**)&attn, g_attn);
    cudaGetSymbolAddress((void**)&x2,   g_x2);
    cudaGetSymbolAddress((void**)&ff,   g_ff);
    cudaGetSymbolAddress((void**)&vt,   g_vt);
    cudaGetSymbolAddress((void**)&wtq,  g_wt_qkv);
    cudaGetSymbolAddress((void**)&wtp,  g_wt_proj);
    cudaGetSymbolAddress((void**)&wt1,  g_wt_fc1);
    cudaGetSymbolAddress((void**)&wt2,  g_wt_fc2);

    cudaFuncSetAttribute(gemm_tc<0,1>, cudaFuncAttributeMaxDynamicSharedMemorySize, GEMM_SMEM);
    cudaFuncSetAttribute(gemm_tc<1,0>, cudaFuncAttributeMaxDynamicSharedMemorySize, GEMM_SMEM);
    cudaFuncSetAttribute(gemm_tc<2,1>, cudaFuncAttributeMaxDynamicSharedMemorySize, GEMM_SMEM);
    cudaFuncSetAttribute(attn_tc,      cudaFuncAttributeMaxDynamicSharedMemorySize, ATTN_SMEM);

    // 0. all weight transposes (+ fp16 convert), one launch
    transpose_all<<<6912, 256>>>(qkv_w, proj_w, fc1_w, fc2_w, wtq, wtp, wt1, wt2);

    // 1. LN1 (fp16 out)
    ln_kernel<<<rows / 8, 256>>>(x, ln1_g, ln1_b, h);
    // 2. QKV projection (fp16 out)
    gemm_tc<0,1><<<dim3(QKV_N / 128, rows / 128), 256, GEMM_SMEM>>>(h, wtq, qkv_b, nullptr, qkv, rows, QKV_N, DIM);
    // 3. V transpose for attention PV mma
    transpose_v<<<dim3(NLEN / 32, HD / 32, B * HEADS), 256>>>(qkv, vt);
    // 4. fused masked flash attention (fp16 tensor cores)
    attn_tc<<<dim3(B * HEADS, NLEN / AQT), 256, ATTN_SMEM>>>(qkv, vt, elev, barrier, attn);
    // 5. out proj + residual (fp32 out)
    gemm_tc<1,0><<<dim3(DIM / 128, rows / 128), 256, GEMM_SMEM>>>(attn, wtp, proj_b, x, x2, rows, DIM, DIM);
    // 6. LN2 (fp16 out)
    ln_kernel<<<rows / 8, 256>>>(x2, ln2_g, ln2_b, h);
    // 7. FC1 + exact GELU (fp16 out)
    gemm_tc<2,1><<<dim3(HIDDEN / 128, rows / 128), 256, GEMM_SMEM>>>(h, wt1, fc1_b, nullptr, ff, rows, HIDDEN, DIM);
    // 8. FC2 + residual -> output (fp32)
    gemm_tc<1,0><<<dim3(DIM / 128, rows / 128), 256, GEMM_SMEM>>>(ff, wt2, fc2_b, x2, out, rows, DIM, HIDDEN);
}

// round 9
// speedup vs baseline: 6.6003x; 1.0600x over previous
#include <cuda_runtime.h>
#include <cuda_fp16.h>
#include <math.h>
#include <stdint.h>

#define DIM 768
#define HEADS 12
#define HD 64
#define HIDDEN 3072
#define QKV_N 2304
#define MAX_ROWS 4096
#define SCALE 0.125f
#define NLEN 2048

// ---------------- scratch (no allocation allowed) ----------------
__device__ __half g_h[MAX_ROWS * DIM];
__device__ __half g_qkv[MAX_ROWS * QKV_N];
__device__ __half g_attn[MAX_ROWS * DIM];
__device__ float  g_x2[MAX_ROWS * DIM];
__device__ __half g_ff[MAX_ROWS * HIDDEN];
__device__ __half g_vt[2 * HEADS * HD * NLEN];   // V transposed: [bh][d][n]
__device__ __half g_wt_qkv[DIM * QKV_N];
__device__ __half g_wt_proj[DIM * DIM];
__device__ __half g_wt_fc1[DIM * HIDDEN];
__device__ __half g_wt_fc2[HIDDEN * DIM];

__device__ __forceinline__ float frcp(float x) {
    float r;
    asm("rcp.approx.f32 %0, %1;" : "=f"(r) : "f"(x));
    return r;
}

#define CP_ASYNC16(dst, src) \
    asm volatile("cp.async.cg.shared.global [%0], [%1], 16;\n" :: "r"(dst), "l"(src))
#define CP_COMMIT() asm volatile("cp.async.commit_group;\n" ::: "memory")
#define CP_WAIT1()  asm volatile("cp.async.wait_group 1;\n" ::: "memory")

#define LDSM_X4(r0, r1, r2, r3, addr) \
    asm volatile("ldmatrix.sync.aligned.m8n8.x4.shared.b16 {%0,%1,%2,%3}, [%4];\n" \
                 : "=r"(r0), "=r"(r1), "=r"(r2), "=r"(r3) : "r"(addr))

#define MMA_F16(d, a, b) \
    asm volatile("mma.sync.aligned.m16n8k16.row.col.f32.f16.f16.f32 " \
                 "{%0,%1,%2,%3}, {%4,%5,%6,%7}, {%8,%9}, {%0,%1,%2,%3};\n" \
                 : "+f"(d[0]), "+f"(d[1]), "+f"(d[2]), "+f"(d[3]) \
                 : "r"(a[0]), "r"(a[1]), "r"(a[2]), "r"(a[3]), "r"(b[0]), "r"(b[1]))

// ---------------- all 4 weight transposes in ONE launch ----------------
__global__ __launch_bounds__(256)
void transpose_all(const float* __restrict__ w0, const float* __restrict__ w1,
                   const float* __restrict__ w2, const float* __restrict__ w3,
                   __half* __restrict__ o0, __half* __restrict__ o1,
                   __half* __restrict__ o2, __half* __restrict__ o3)
{
    int bid = blockIdx.x;
    const float* W; __half* Wt; int K, N;
    if (bid < 1728)      { W = w0; Wt = o0; K = DIM;    N = QKV_N;  }
    else if (bid < 2304) { W = w1; Wt = o1; K = DIM;    N = DIM;    bid -= 1728; }
    else if (bid < 4608) { W = w2; Wt = o2; K = DIM;    N = HIDDEN; bid -= 2304; }
    else                 { W = w3; Wt = o3; K = HIDDEN; N = DIM;    bid -= 4608; }
    const int nb = N / 32;
    const int n0 = (bid % nb) * 32, k0 = (bid / nb) * 32;

    __shared__ float t[32][33];
    const int tx = threadIdx.x & 31, ty = threadIdx.x >> 5;
    #pragma unroll
    for (int i = 0; i < 32; i += 8)
        t[ty + i][tx] = W[(size_t)(k0 + ty + i) * N + n0 + tx];
    __syncthreads();
    #pragma unroll
    for (int i = 0; i < 32; i += 8)
        Wt[(size_t)(n0 + ty + i) * K + k0 + tx] = __float2half_rn(t[tx][ty + i]);
}

// ---------------- V transpose: g_qkv -> g_vt[bh][d][n] (fp16) ----------------
__global__ __launch_bounds__(256)
void transpose_v(const __half* __restrict__ qkv, __half* __restrict__ vt)
{
    __shared__ __half t[32][40];
    const int bh = blockIdx.z;
    const int b = bh / HEADS, h = bh % HEADS;
    const int n0 = blockIdx.x * 32, d0 = blockIdx.y * 32;
    const int tx = threadIdx.x & 31, ty = threadIdx.x >> 5;
    #pragma unroll
    for (int i = 0; i < 32; i += 8)
        t[ty + i][tx] = qkv[(size_t)(b * NLEN + n0 + ty + i) * QKV_N + 2 * DIM + h * HD + d0 + tx];
    __syncthreads();
    #pragma unroll
    for (int i = 0; i < 32; i += 8)
        vt[(size_t)(bh * HD + d0 + ty + i) * NLEN + n0 + tx] = t[tx][ty + i];
}

// ---------------- LayerNorm: warp per row, float4 I/O ----------------
__global__ __launch_bounds__(256)
void ln_kernel(const float* __restrict__ x, const float* __restrict__ g,
               const float* __restrict__ bta, __half* __restrict__ out)
{
    const int lane = threadIdx.x & 31;
    const int row = blockIdx.x * 8 + (threadIdx.x >> 5);
    const float* xr = x + (size_t)row * DIM;

    float4 v[6];
    float s = 0.f, s2 = 0.f;
    #pragma unroll
    for (int i = 0; i < 6; i++) {
        v[i] = *(const float4*)(xr + (i * 32 + lane) * 4);
        s  += v[i].x + v[i].y + v[i].z + v[i].w;
        s2 += v[i].x * v[i].x + v[i].y * v[i].y + v[i].z * v[i].z + v[i].w * v[i].w;
    }
    #pragma unroll
    for (int off = 16; off; off >>= 1) {
        s  += __shfl_xor_sync(0xffffffffu, s,  off);
        s2 += __shfl_xor_sync(0xffffffffu, s2, off);
    }
    const float mu  = s * (1.0f / DIM);
    const float inv = rsqrtf(s2 * (1.0f / DIM) - mu * mu + 1e-5f);

    __half* outr = out + (size_t)row * DIM;
    #pragma unroll
    for (int i = 0; i < 6; i++) {
        int c = (i * 32 + lane) * 4;
        float4 gg = *(const float4*)(g + c);
        float4 bb = *(const float4*)(bta + c);
        __half2 h0 = __floats2half2_rn((v[i].x - mu) * inv * gg.x + bb.x,
                                       (v[i].y - mu) * inv * gg.y + bb.y);
        __half2 h1 = __floats2half2_rn((v[i].z - mu) * inv * gg.z + bb.z,
                                       (v[i].w - mu) * inv * gg.w + bb.w);
        uint2 u;
        u.x = *(uint32_t*)&h0; u.y = *(uint32_t*)&h1;
        *(uint2*)(outr + c) = u;
    }
}

// ---------------- fp16 tensor-core GEMM, 3-stage cp.async, 2 CTAs/SM ----------------
// C[M,N] = A[M,K] @ Wt[N,K]^T + bias (+epilogue). A, Wt fp16; accum fp32.
// Tile 128x128x64, 3 smem stages (96KB), ONE __syncthreads per k-iter.
// EPI: 0=bias, 1=bias+residual(fp32), 2=bias+exact GELU. OUTH: fp16/fp32 out.
#define GBM 128
#define GBN 128
#define GBK 64
#define GTILE (GBM * GBK * 2)       // bytes per A (or B) stage = 16384
#define GEMM_SMEM (6 * GTILE)       // 3 stages x (A + B) = 96 KB

template<int EPI, int OUTH>
__global__ __launch_bounds__(256, 2)
void gemm_tc(const __half* __restrict__ A, const __half* __restrict__ Wt,
             const float* __restrict__ bias, const float* __restrict__ res,
             void* __restrict__ Cout, int M, int N, int K)
{
    extern __shared__ char sm[];
    const int tid  = threadIdx.x;
    const int lane = tid & 31, warp = tid >> 5;
    const int wm = warp >> 2, wn = warp & 3;
    const int m0 = blockIdx.y << 7, n0 = blockIdx.x << 7;

    const uint32_t as_base = (uint32_t)__cvta_generic_to_shared(sm);
    const uint32_t bs_base = as_base + 3 * GTILE;

    float acc[4][4][4];
    #pragma unroll
    for (int i = 0; i < 4; i++)
        #pragma unroll
        for (int j = 0; j < 4; j++)
            #pragma unroll
            for (int r = 0; r < 4; r++) acc[i][j][r] = 0.f;

    #define STAGE(buf, k0)                                                              \
        _Pragma("unroll")                                                               \
        for (int s_ = 0; s_ < 4; s_++) {                                                \
            int idx = s_ * 256 + tid;                                                   \
            int r_ = idx >> 3, c_ = idx & 7;                                            \
            uint32_t sw = (buf) * GTILE + r_ * 128 + ((c_ ^ (r_ & 7)) << 4);            \
            CP_ASYNC16(as_base + sw, A  + (size_t)(m0 + r_) * K + (k0) + c_ * 8);       \
            CP_ASYNC16(bs_base + sw, Wt + (size_t)(n0 + r_) * K + (k0) + c_ * 8);       \
        }

    STAGE(0, 0)
    CP_COMMIT();
    STAGE(1, GBK)
    CP_COMMIT();

    const int a_row = lane & 15, a_hi = lane >> 4;
    const int kIters = K / GBK;

    int buf = 0;
    for (int it = 0; it < kIters; it++) {
        CP_WAIT1();        // tile `it` complete (exactly one newer group may be pending)
        __syncthreads();   // visibility; also: all threads finished consuming buf (it-1)%3

        if (it + 2 < kIters) { STAGE((it + 2) % 3, (it + 2) * GBK) }
        CP_COMMIT();       // unconditional: keeps group count = 1 per iteration

        const uint32_t ab = as_base + buf * GTILE;
        const uint32_t bb = bs_base + buf * GTILE;

        #pragma unroll
        for (int ks = 0; ks < 4; ks++) {
            const int f8 = (ks << 1) + a_hi;
            uint32_t af[4][4], bf[4][2];
            #pragma unroll
            for (int mt = 0; mt < 4; mt++) {
                int row = (wm << 6) + (mt << 4) + a_row;
                uint32_t addr = ab + row * 128 + ((f8 ^ (row & 7)) << 4);
                LDSM_X4(af[mt][0], af[mt][1], af[mt][2], af[mt][3], addr);
            }
            #pragma unroll
            for (int np = 0; np < 2; np++) {
                int row = (wn << 5) + (np << 4) + a_row;
                uint32_t addr = bb + row * 128 + ((f8 ^ (row & 7)) << 4);
                uint32_t q0, q1, q2, q3;
                LDSM_X4(q0, q1, q2, q3, addr);
                bf[np * 2 + 0][0] = q0; bf[np * 2 + 0][1] = q2;
                bf[np * 2 + 1][0] = q1; bf[np * 2 + 1][1] = q3;
            }
            #pragma unroll
            for (int mt = 0; mt < 4; mt++)
                #pragma unroll
                for (int nt = 0; nt < 4; nt++)
                    MMA_F16(acc[mt][nt], af[mt], bf[nt]);
        }
        buf++; if (buf == 3) buf = 0;
    }
    #undef STAGE

    const int g = lane >> 2, tg = lane & 3;
    #pragma unroll
    for (int mt = 0; mt < 4; mt++) {
        #pragma unroll
        for (int nt = 0; nt < 4; nt++) {
            int row = m0 + (wm << 6) + (mt << 4) + g;
            int col = n0 + (wn << 5) + (nt << 3) + (tg << 1);
            float b0 = bias[col], b1 = bias[col + 1];
            #pragma unroll
            for (int half = 0; half < 2; half++) {
                int r = row + half * 8;
                float v0 = acc[mt][nt][half * 2 + 0] + b0;
                float v1 = acc[mt][nt][half * 2 + 1] + b1;
                if (EPI == 1) {
                    const float2 rr = *(const float2*)&res[(size_t)r * N + col];
                    v0 += rr.x; v1 += rr.y;
                }
                if (EPI == 2) {
                    v0 = 0.5f * v0 * (1.0f + erff(v0 * 0.70710678118654752f));
                    v1 = 0.5f * v1 * (1.0f + erff(v1 * 0.70710678118654752f));
                }
                if (OUTH) {
                    *(__half2*)((__half*)Cout + (size_t)r * N + col) = __floats2half2_rn(v0, v1);
                } else {
                    *(float2*)((float*)Cout + (size_t)r * N + col) = make_float2(v0, v1);
                }
            }
        }
    }
}

// ---------------- fp16 tensor-core flash attention ----------------
// CTA: 128 threads = 4 warps, each warp 16 q-rows => Q tile 64 (smaller CTAs ->
// ~3 CTAs/SM co-resident, no wave-quantization tail). Key tile 64, double-buffered
// cp.async. S=(Q*0.125)@K^T fp16 mma (fp32 accum), online softmax with dual sums
// lp/lm; mask = 1/(1+Ej*Fi) factorized sigmoid. O += P @ V^T (V pre-transposed).
#define AQT 64
#define ATHREADS 128
#define AKT 64
#define KVTILE (AKT * HD * 2)    // 8192 bytes

__global__ __launch_bounds__(ATHREADS)
void attn_tc(const __half* __restrict__ qkv, const __half* __restrict__ vt,
             const float* __restrict__ elev, const float* __restrict__ barrier,
             __half* __restrict__ out)
{
    extern __shared__ char sm[];
    const uint32_t smb     = (uint32_t)__cvta_generic_to_shared(sm);
    const uint32_t ks_base = smb;
    const uint32_t vt_base = smb + 2 * KVTILE;
    const uint32_t qp_base = smb + 4 * KVTILE;
    char* qp_ptr = sm + 4 * KVTILE;
    float* es = (float*)(sm + 4 * KVTILE + AQT * 128);

    const int bh = blockIdx.x, b = bh / HEADS, h = bh % HEADS;
    const int q0 = blockIdx.y * AQT;
    const int tid = threadIdx.x, lane = tid & 31, warp = tid >> 5;
    const int rowbase = b * NLEN;
    const float bar = *barrier;

    const __half2 sc2 = __floats2half2_rn(SCALE, SCALE);
    #pragma unroll
    for (int it = 0; it < 4; it++) {
        int idx = it * ATHREADS + tid;
        int rr = idx >> 3, cc = idx & 7;
        uint4 v = *(const uint4*)(qkv + (size_t)(rowbase + q0 + rr) * QKV_N + h * HD + cc * 8);
        __half2* hv = (__half2*)&v;
        hv[0] = __hmul2(hv[0], sc2); hv[1] = __hmul2(hv[1], sc2);
        hv[2] = __hmul2(hv[2], sc2); hv[3] = __hmul2(hv[3], sc2);
        *(uint4*)(qp_ptr + rr * 128 + ((cc ^ (rr & 7)) << 4)) = v;
    }

    #define STAGE_KV(buf, j0)                                                            \
        _Pragma("unroll")                                                                \
        for (int it_ = 0; it_ < 4; it_++) {                                              \
            int idx = it_ * ATHREADS + tid;                                              \
            int rr = idx >> 3, cc = idx & 7;                                             \
            uint32_t sw = (buf) * KVTILE + rr * 128 + ((cc ^ (rr & 7)) << 4);            \
            CP_ASYNC16(ks_base + sw,                                                     \
                qkv + (size_t)(rowbase + (j0) + rr) * QKV_N + DIM + h * HD + cc * 8);    \
            CP_ASYNC16(vt_base + sw,                                                     \
                vt + (size_t)(bh * HD + rr) * NLEN + (j0) + cc * 8);                     \
        }

    STAGE_KV(0, 0)
    if (tid < AKT) es[tid] = __expf(bar * elev[rowbase + tid]);
    CP_COMMIT();
    __syncthreads();

    const int a_row = lane & 15, a_hi = lane >> 4;

    uint32_t qa[4][4];
    #pragma unroll
    for (int ks = 0; ks < 4; ks++) {
        int row = (warp << 4) + a_row;
        int f8  = (ks << 1) + a_hi;
        uint32_t addr = qp_base + row * 128 + ((f8 ^ (row & 7)) << 4);
        LDSM_X4(qa[ks][0], qa[ks][1], qa[ks][2], qa[ks][3], addr);
    }

    const int g = lane >> 2, tg = lane & 3;
    const float Fi0 = __expf(-bar * elev[rowbase + q0 + (warp << 4) + g]);
    const float Fi1 = __expf(-bar * elev[rowbase + q0 + (warp << 4) + g + 8]);

    float m0 = -1e30f, m1 = -1e30f;
    float lp0 = 0.f, lm0 = 0.f, lp1 = 0.f, lm1 = 0.f;
    float o[8][4];
    #pragma unroll
    for (int dt = 0; dt < 8; dt++)
        #pragma unroll
        for (int r = 0; r < 4; r++) o[dt][r] = 0.f;

    const int nTiles = NLEN / AKT;
    for (int t = 0; t < nTiles; t++) {
        const int buf = t & 1;
        if (t + 1 < nTiles) {
            STAGE_KV(buf ^ 1, (t + 1) * AKT)
            if (tid < AKT) es[(buf ^ 1) * AKT + tid] = __expf(bar * elev[rowbase + (t + 1) * AKT + tid]);
        }
        CP_COMMIT();
        CP_WAIT1();
        __syncthreads();

        const uint32_t kb = ks_base + buf * KVTILE;
        const uint32_t vb = vt_base + buf * KVTILE;
        const float* esb = es + buf * AKT;

        float s[8][4];
        #pragma unroll
        for (int nt = 0; nt < 8; nt++)
            #pragma unroll
            for (int r = 0; r < 4; r++) s[nt][r] = 0.f;

        #pragma unroll
        for (int ks = 0; ks < 4; ks++) {
            const int f8 = (ks << 1) + a_hi;
            uint32_t bf[8][2];
            #pragma unroll
            for (int np = 0; np < 4; np++) {
                int row = (np << 4) + a_row;
                uint32_t addr = kb + row * 128 + ((f8 ^ (row & 7)) << 4);
                uint32_t t0, t1, t2, t3;
                LDSM_X4(t0, t1, t2, t3, addr);
                bf[np * 2 + 0][0] = t0; bf[np * 2 + 0][1] = t2;
                bf[np * 2 + 1][0] = t1; bf[np * 2 + 1][1] = t3;
            }
            #pragma unroll
            for (int nt = 0; nt < 8; nt++) MMA_F16(s[nt], qa[ks], bf[nt]);
        }

        float r0 = -1e30f, r1 = -1e30f;
        #pragma unroll
        for (int nt = 0; nt < 8; nt++) {
            r0 = fmaxf(r0, fmaxf(s[nt][0], s[nt][1]));
            r1 = fmaxf(r1, fmaxf(s[nt][2], s[nt][3]));
        }
        r0 = fmaxf(r0, __shfl_xor_sync(0xffffffffu, r0, 1));
        r0 = fmaxf(r0, __shfl_xor_sync(0xffffffffu, r0, 2));
        r1 = fmaxf(r1, __shfl_xor_sync(0xffffffffu, r1, 1));
        r1 = fmaxf(r1, __shfl_xor_sync(0xffffffffu, r1, 2));

        float nm0 = fmaxf(m0, r0), nm1 = fmaxf(m1, r1);
        float al0 = __expf(m0 - nm0), al1 = __expf(m1 - nm1);
        m0 = nm0; m1 = nm1;
        lp0 *= al0; lm0 *= al0; lp1 *= al1; lm1 *= al1;
        #pragma unroll
        for (int dt = 0; dt < 8; dt++) {
            o[dt][0] *= al0; o[dt][1] *= al0;
            o[dt][2] *= al1; o[dt][3] *= al1;
        }

        const int row0 = (warp << 4) + g;
        const int row1 = row0 + 8;
        #pragma unroll
        for (int nt = 0; nt < 8; nt++) {
            int c = (nt << 3) + (tg << 1);
            float Ej0 = esb[c], Ej1 = esb[c + 1];
            float mk00 = fminf(fmaxf(frcp(fmaf(Ej0, Fi0, 1.0f)), 1e-6f), 1.0f);
            float mk01 = fminf(fmaxf(frcp(fmaf(Ej1, Fi0, 1.0f)), 1e-6f), 1.0f);
            float mk10 = fminf(fmaxf(frcp(fmaf(Ej0, Fi1, 1.0f)), 1e-6f), 1.0f);
            float mk11 = fminf(fmaxf(frcp(fmaf(Ej1, Fi1, 1.0f)), 1e-6f), 1.0f);

            float p00 = __expf(s[nt][0] - m0), p01 = __expf(s[nt][1] - m0);
            float p10 = __expf(s[nt][2] - m1), p11 = __expf(s[nt][3] - m1);
            lp0 += p00 + p01; lp1 += p10 + p11;
            float pm00 = p00 * mk00, pm01 = p01 * mk01;
            float pm10 = p10 * mk10, pm11 = p11 * mk11;
            lm0 += pm00 + pm01; lm1 += pm10 + pm11;

            *(__half2*)(qp_ptr + row0 * 128 + (((c >> 3) ^ (row0 & 7)) << 4) + ((c & 7) << 1)) =
                __floats2half2_rn(pm00, pm01);
            *(__half2*)(qp_ptr + row1 * 128 + (((c >> 3) ^ (row1 & 7)) << 4) + ((c & 7) << 1)) =
                __floats2half2_rn(pm10, pm11);
        }
        __syncwarp();

        #pragma unroll
        for (int ks = 0; ks < 4; ks++) {
            const int f8 = (ks << 1) + a_hi;
            uint32_t pa[4];
            {
                int row = (warp << 4) + a_row;
                uint32_t addr = qp_base + row * 128 + ((f8 ^ (row & 7)) << 4);
                LDSM_X4(pa[0], pa[1], pa[2], pa[3], addr);
            }
            uint32_t vf[8][2];
            #pragma unroll
            for (int np = 0; np < 4; np++) {
                int row = (np << 4) + a_row;
                uint32_t addr = vb + row * 128 + ((f8 ^ (row & 7)) << 4);
                uint32_t t0, t1, t2, t3;
                LDSM_X4(t0, t1, t2, t3, addr);
                vf[np * 2 + 0][0] = t0; vf[np * 2 + 0][1] = t2;
                vf[np * 2 + 1][0] = t1; vf[np * 2 + 1][1] = t3;
            }
            #pragma unroll
            for (int dt = 0; dt < 8; dt++) MMA_F16(o[dt], pa, vf[dt]);
        }
        __syncthreads();
    }
    #undef STAGE_KV

    lp0 += __shfl_xor_sync(0xffffffffu, lp0, 1); lp0 += __shfl_xor_sync(0xffffffffu, lp0, 2);
    lm0 += __shfl_xor_sync(0xffffffffu, lm0, 1); lm0 += __shfl_xor_sync(0xffffffffu, lm0, 2);
    lp1 += __shfl_xor_sync(0xffffffffu, lp1, 1); lp1 += __shfl_xor_sync(0xffffffffu, lp1, 2);
    lm1 += __shfl_xor_sync(0xffffffffu, lm1, 1); lm1 += __shfl_xor_sync(0xffffffffu, lm1, 2);
    const float inv0 = 1.0f / (lm0 + 1e-8f * lp0);
    const float inv1 = 1.0f / (lm1 + 1e-8f * lp1);

    const int r0 = rowbase + q0 + (warp << 4) + g;
    #pragma unroll
    for (int dt = 0; dt < 8; dt++) {
        int col = h * HD + (dt << 3) + (tg << 1);
        *(__half2*)&out[(size_t)r0 * DIM + col] =
            __floats2half2_rn(o[dt][0] * inv0, o[dt][1] * inv0);
        *(__half2*)&out[(size_t)(r0 + 8) * DIM + col] =
            __floats2half2_rn(o[dt][2] * inv1, o[dt][3] * inv1);
    }
}

// ---------------- launch ----------------
#define ATTN_SMEM (4 * KVTILE + AQT * 128 + 2 * AKT * 4)

extern "C" void kernel_launch(void* const* d_in, const int* in_sizes, int n_in,
                              void* d_out, int out_size)
{
    const float* x      = (const float*)d_in[0];
    const float* elev   = (const float*)d_in[1];
    const float* qkv_w  = (const float*)d_in[2];
    const float* qkv_b  = (const float*)d_in[3];
    const float* proj_w = (const float*)d_in[4];
    const float* proj_b = (const float*)d_in[5];
    const float* ln1_g  = (const float*)d_in[6];
    const float* ln1_b  = (const float*)d_in[7];
    const float* ln2_g  = (const float*)d_in[8];
    const float* ln2_b  = (const float*)d_in[9];
    const float* fc1_w  = (const float*)d_in[10];
    const float* fc1_b  = (const float*)d_in[11];
    const float* fc2_w  = (const float*)d_in[12];
    const float* fc2_b  = (const float*)d_in[13];
    const float* barrier= (const float*)d_in[14];
    float* out = (float*)d_out;

    const int rows = in_sizes[0] / DIM;     // B*N
    const int B = rows / NLEN;

    __half *h, *qkv, *attn, *ff, *vt, *wtq, *wtp, *wt1, *wt2;
    float *x2;
    cudaGetSymbolAddress((void**)&h,    g_h);
    cudaGetSymbolAddress((void**)&qkv,  g_qkv);
    cudaGetSymbolAddress((void**)&attn, g_attn);
    cudaGetSymbolAddress((void**)&x2,   g_x2);
    cudaGetSymbolAddress((void**)&ff,   g_ff);
    cudaGetSymbolAddress((void**)&vt,   g_vt);
    cudaGetSymbolAddress((void**)&wtq,  g_wt_qkv);
    cudaGetSymbolAddress((void**)&wtp,  g_wt_proj);
    cudaGetSymbolAddress((void**)&wt1,  g_wt_fc1);
    cudaGetSymbolAddress((void**)&wt2,  g_wt_fc2);

    cudaFuncSetAttribute(gemm_tc<0,1>, cudaFuncAttributeMaxDynamicSharedMemorySize, GEMM_SMEM);
    cudaFuncSetAttribute(gemm_tc<1,0>, cudaFuncAttributeMaxDynamicSharedMemorySize, GEMM_SMEM);
    cudaFuncSetAttribute(gemm_tc<2,1>, cudaFuncAttributeMaxDynamicSharedMemorySize, GEMM_SMEM);
    cudaFuncSetAttribute(attn_tc,      cudaFuncAttributeMaxDynamicSharedMemorySize, ATTN_SMEM);

    // 0. all weight transposes (+ fp16 convert), one launch
    transpose_all<<<6912, 256>>>(qkv_w, proj_w, fc1_w, fc2_w, wtq, wtp, wt1, wt2);

    // 1. LN1 (fp16 out)
    ln_kernel<<<rows / 8, 256>>>(x, ln1_g, ln1_b, h);
    // 2. QKV projection (fp16 out)
    gemm_tc<0,1><<<dim3(QKV_N / 128, rows / 128), 256, GEMM_SMEM>>>(h, wtq, qkv_b, nullptr, qkv, rows, QKV_N, DIM);
    // 3. V transpose for attention PV mma
    transpose_v<<<dim3(NLEN / 32, HD / 32, B * HEADS), 256>>>(qkv, vt);
    // 4. fused masked flash attention (fp16 tensor cores)
    attn_tc<<<dim3(B * HEADS, NLEN / AQT), ATHREADS, ATTN_SMEM>>>(qkv, vt, elev, barrier, attn);
    // 5. out proj + residual (fp32 out)
    gemm_tc<1,0><<<dim3(DIM / 128, rows / 128), 256, GEMM_SMEM>>>(attn, wtp, proj_b, x, x2, rows, DIM, DIM);
    // 6. LN2 (fp16 out)
    ln_kernel<<<rows / 8, 256>>>(x2, ln2_g, ln2_b, h);
    // 7. FC1 + exact GELU (fp16 out)
    gemm_tc<2,1><<<dim3(HIDDEN / 128, rows / 128), 256, GEMM_SMEM>>>(h, wt1, fc1_b, nullptr, ff, rows, HIDDEN, DIM);
    // 8. FC2 + residual -> output (fp32)
    gemm_tc<1,0><<<dim3(DIM / 128, rows / 128), 256, GEMM_SMEM>>>(ff, wt2, fc2_b, x2, out, rows, DIM, HIDDEN);
}

// round 10
// speedup vs baseline: 6.9663x; 1.0555x over previous
#include <cuda_runtime.h>
#include <cuda_fp16.h>
#include <math.h>
#include <stdint.h>

#define DIM 768
#define HEADS 12
#define HD 64
#define HIDDEN 3072
#define QKV_N 2304
#define MAX_ROWS 4096
#define SCALE 0.125f
#define NLEN 2048

// ---------------- scratch (no allocation allowed) ----------------
__device__ __half g_h[MAX_ROWS * DIM];
__device__ __half g_qkv[MAX_ROWS * QKV_N];
__device__ __half g_attn[MAX_ROWS * DIM];
__device__ float  g_x2[MAX_ROWS * DIM];
__device__ __half g_ff[MAX_ROWS * HIDDEN];
__device__ __half g_wt_qkv[DIM * QKV_N];
__device__ __half g_wt_proj[DIM * DIM];
__device__ __half g_wt_fc1[DIM * HIDDEN];
__device__ __half g_wt_fc2[HIDDEN * DIM];

__device__ __forceinline__ float frcp(float x) {
    float r;
    asm("rcp.approx.f32 %0, %1;" : "=f"(r) : "f"(x));
    return r;
}

#define CP_ASYNC16(dst, src) \
    asm volatile("cp.async.cg.shared.global [%0], [%1], 16;\n" :: "r"(dst), "l"(src))
#define CP_COMMIT() asm volatile("cp.async.commit_group;\n" ::: "memory")
#define CP_WAIT1()  asm volatile("cp.async.wait_group 1;\n" ::: "memory")

#define LDSM_X4(r0, r1, r2, r3, addr) \
    asm volatile("ldmatrix.sync.aligned.m8n8.x4.shared.b16 {%0,%1,%2,%3}, [%4];\n" \
                 : "=r"(r0), "=r"(r1), "=r"(r2), "=r"(r3) : "r"(addr))

#define LDSM_X4_T(r0, r1, r2, r3, addr) \
    asm volatile("ldmatrix.sync.aligned.m8n8.x4.trans.shared.b16 {%0,%1,%2,%3}, [%4];\n" \
                 : "=r"(r0), "=r"(r1), "=r"(r2), "=r"(r3) : "r"(addr))

#define MMA_F16(d, a, b) \
    asm volatile("mma.sync.aligned.m16n8k16.row.col.f32.f16.f16.f32 " \
                 "{%0,%1,%2,%3}, {%4,%5,%6,%7}, {%8,%9}, {%0,%1,%2,%3};\n" \
                 : "+f"(d[0]), "+f"(d[1]), "+f"(d[2]), "+f"(d[3]) \
                 : "r"(a[0]), "r"(a[1]), "r"(a[2]), "r"(a[3]), "r"(b[0]), "r"(b[1]))

// ---------------- all 4 weight transposes in ONE launch ----------------
__global__ __launch_bounds__(256)
void transpose_all(const float* __restrict__ w0, const float* __restrict__ w1,
                   const float* __restrict__ w2, const float* __restrict__ w3,
                   __half* __restrict__ o0, __half* __restrict__ o1,
                   __half* __restrict__ o2, __half* __restrict__ o3)
{
    int bid = blockIdx.x;
    const float* W; __half* Wt; int K, N;
    if (bid < 1728)      { W = w0; Wt = o0; K = DIM;    N = QKV_N;  }
    else if (bid < 2304) { W = w1; Wt = o1; K = DIM;    N = DIM;    bid -= 1728; }
    else if (bid < 4608) { W = w2; Wt = o2; K = DIM;    N = HIDDEN; bid -= 2304; }
    else                 { W = w3; Wt = o3; K = HIDDEN; N = DIM;    bid -= 4608; }
    const int nb = N / 32;
    const int n0 = (bid % nb) * 32, k0 = (bid / nb) * 32;

    __shared__ float t[32][33];
    const int tx = threadIdx.x & 31, ty = threadIdx.x >> 5;
    #pragma unroll
    for (int i = 0; i < 32; i += 8)
        t[ty + i][tx] = W[(size_t)(k0 + ty + i) * N + n0 + tx];
    __syncthreads();
    #pragma unroll
    for (int i = 0; i < 32; i += 8)
        Wt[(size_t)(n0 + ty + i) * K + k0 + tx] = __float2half_rn(t[tx][ty + i]);
}

// ---------------- LayerNorm: warp per row, float4 I/O ----------------
__global__ __launch_bounds__(256)
void ln_kernel(const float* __restrict__ x, const float* __restrict__ g,
               const float* __restrict__ bta, __half* __restrict__ out)
{
    const int lane = threadIdx.x & 31;
    const int row = blockIdx.x * 8 + (threadIdx.x >> 5);
    const float* xr = x + (size_t)row * DIM;

    float4 v[6];
    float s = 0.f, s2 = 0.f;
    #pragma unroll
    for (int i = 0; i < 6; i++) {
        v[i] = *(const float4*)(xr + (i * 32 + lane) * 4);
        s  += v[i].x + v[i].y + v[i].z + v[i].w;
        s2 += v[i].x * v[i].x + v[i].y * v[i].y + v[i].z * v[i].z + v[i].w * v[i].w;
    }
    #pragma unroll
    for (int off = 16; off; off >>= 1) {
        s  += __shfl_xor_sync(0xffffffffu, s,  off);
        s2 += __shfl_xor_sync(0xffffffffu, s2, off);
    }
    const float mu  = s * (1.0f / DIM);
    const float inv = rsqrtf(s2 * (1.0f / DIM) - mu * mu + 1e-5f);

    __half* outr = out + (size_t)row * DIM;
    #pragma unroll
    for (int i = 0; i < 6; i++) {
        int c = (i * 32 + lane) * 4;
        float4 gg = *(const float4*)(g + c);
        float4 bb = *(const float4*)(bta + c);
        __half2 h0 = __floats2half2_rn((v[i].x - mu) * inv * gg.x + bb.x,
                                       (v[i].y - mu) * inv * gg.y + bb.y);
        __half2 h1 = __floats2half2_rn((v[i].z - mu) * inv * gg.z + bb.z,
                                       (v[i].w - mu) * inv * gg.w + bb.w);
        uint2 u;
        u.x = *(uint32_t*)&h0; u.y = *(uint32_t*)&h1;
        *(uint2*)(outr + c) = u;
    }
}

// ---------------- fp16 tensor-core GEMM, 3-stage cp.async, 2 CTAs/SM ----------------
#define GBM 128
#define GBN 128
#define GBK 64
#define GTILE (GBM * GBK * 2)       // bytes per A (or B) stage = 16384
#define GEMM_SMEM (6 * GTILE)       // 3 stages x (A + B) = 96 KB

template<int EPI, int OUTH>
__global__ __launch_bounds__(256, 2)
void gemm_tc(const __half* __restrict__ A, const __half* __restrict__ Wt,
             const float* __restrict__ bias, const float* __restrict__ res,
             void* __restrict__ Cout, int M, int N, int K)
{
    extern __shared__ char sm[];
    const int tid  = threadIdx.x;
    const int lane = tid & 31, warp = tid >> 5;
    const int wm = warp >> 2, wn = warp & 3;
    const int m0 = blockIdx.y << 7, n0 = blockIdx.x << 7;

    const uint32_t as_base = (uint32_t)__cvta_generic_to_shared(sm);
    const uint32_t bs_base = as_base + 3 * GTILE;

    float acc[4][4][4];
    #pragma unroll
    for (int i = 0; i < 4; i++)
        #pragma unroll
        for (int j = 0; j < 4; j++)
            #pragma unroll
            for (int r = 0; r < 4; r++) acc[i][j][r] = 0.f;

    #define STAGE(buf, k0)                                                              \
        _Pragma("unroll")                                                               \
        for (int s_ = 0; s_ < 4; s_++) {                                                \
            int idx = s_ * 256 + tid;                                                   \
            int r_ = idx >> 3, c_ = idx & 7;                                            \
            uint32_t sw = (buf) * GTILE + r_ * 128 + ((c_ ^ (r_ & 7)) << 4);            \
            CP_ASYNC16(as_base + sw, A  + (size_t)(m0 + r_) * K + (k0) + c_ * 8);       \
            CP_ASYNC16(bs_base + sw, Wt + (size_t)(n0 + r_) * K + (k0) + c_ * 8);       \
        }

    STAGE(0, 0)
    CP_COMMIT();
    STAGE(1, GBK)
    CP_COMMIT();

    const int a_row = lane & 15, a_hi = lane >> 4;
    const int kIters = K / GBK;

    int buf = 0;
    for (int it = 0; it < kIters; it++) {
        CP_WAIT1();
        __syncthreads();

        if (it + 2 < kIters) { STAGE((it + 2) % 3, (it + 2) * GBK) }
        CP_COMMIT();

        const uint32_t ab = as_base + buf * GTILE;
        const uint32_t bb = bs_base + buf * GTILE;

        #pragma unroll
        for (int ks = 0; ks < 4; ks++) {
            const int f8 = (ks << 1) + a_hi;
            uint32_t af[4][4], bf[4][2];
            #pragma unroll
            for (int mt = 0; mt < 4; mt++) {
                int row = (wm << 6) + (mt << 4) + a_row;
                uint32_t addr = ab + row * 128 + ((f8 ^ (row & 7)) << 4);
                LDSM_X4(af[mt][0], af[mt][1], af[mt][2], af[mt][3], addr);
            }
            #pragma unroll
            for (int np = 0; np < 2; np++) {
                int row = (wn << 5) + (np << 4) + a_row;
                uint32_t addr = bb + row * 128 + ((f8 ^ (row & 7)) << 4);
                uint32_t q0, q1, q2, q3;
                LDSM_X4(q0, q1, q2, q3, addr);
                bf[np * 2 + 0][0] = q0; bf[np * 2 + 0][1] = q2;
                bf[np * 2 + 1][0] = q1; bf[np * 2 + 1][1] = q3;
            }
            #pragma unroll
            for (int mt = 0; mt < 4; mt++)
                #pragma unroll
                for (int nt = 0; nt < 4; nt++)
                    MMA_F16(acc[mt][nt], af[mt], bf[nt]);
        }
        buf++; if (buf == 3) buf = 0;
    }
    #undef STAGE

    const int g = lane >> 2, tg = lane & 3;
    #pragma unroll
    for (int mt = 0; mt < 4; mt++) {
        #pragma unroll
        for (int nt = 0; nt < 4; nt++) {
            int row = m0 + (wm << 6) + (mt << 4) + g;
            int col = n0 + (wn << 5) + (nt << 3) + (tg << 1);
            float b0 = bias[col], b1 = bias[col + 1];
            #pragma unroll
            for (int half = 0; half < 2; half++) {
                int r = row + half * 8;
                float v0 = acc[mt][nt][half * 2 + 0] + b0;
                float v1 = acc[mt][nt][half * 2 + 1] + b1;
                if (EPI == 1) {
                    const float2 rr = *(const float2*)&res[(size_t)r * N + col];
                    v0 += rr.x; v1 += rr.y;
                }
                if (EPI == 2) {
                    v0 = 0.5f * v0 * (1.0f + erff(v0 * 0.70710678118654752f));
                    v1 = 0.5f * v1 * (1.0f + erff(v1 * 0.70710678118654752f));
                }
                if (OUTH) {
                    *(__half2*)((__half*)Cout + (size_t)r * N + col) = __floats2half2_rn(v0, v1);
                } else {
                    *(float2*)((float*)Cout + (size_t)r * N + col) = make_float2(v0, v1);
                }
            }
        }
    }
}

// ---------------- fp16 tensor-core flash attention ----------------
// CTA: 128 threads = 4 warps, each warp 16 q-rows => Q tile 64. Key tile 64,
// 3-stage cp.async pipeline with ONE __syncthreads per tile. V is staged
// K-major straight from qkv and its PV B-fragments loaded via ldmatrix.trans
// (no global V transpose). S=(Q*0.125)@K^T fp16 mma, online softmax with dual
// sums lp/lm; mask = 1/(1+Ej*Fi) factorized sigmoid (clamps provably dead).
#define AQT 64
#define ATHREADS 128
#define AKT 64
#define KVTILE (AKT * HD * 2)    // 8192 bytes per operand per stage

__global__ __launch_bounds__(ATHREADS)
void attn_tc(const __half* __restrict__ qkv,
             const float* __restrict__ elev, const float* __restrict__ barrier,
             __half* __restrict__ out)
{
    extern __shared__ char sm[];
    const uint32_t smb     = (uint32_t)__cvta_generic_to_shared(sm);
    const uint32_t ks_base = smb;                     // 3 x 8192 (K)
    const uint32_t vs_base = smb + 3 * KVTILE;        // 3 x 8192 (V, K-major j rows)
    const uint32_t qp_base = smb + 6 * KVTILE;        // 64 x 128B (Q then P)
    char* qp_ptr = sm + 6 * KVTILE;
    float* es = (float*)(sm + 6 * KVTILE + AQT * 128);   // 3 x 64 floats

    const int bh = blockIdx.x, b = bh / HEADS, h = bh % HEADS;
    const int q0 = blockIdx.y * AQT;
    const int tid = threadIdx.x, lane = tid & 31, warp = tid >> 5;
    const int rowbase = b * NLEN;
    const float bar = *barrier;

    // stage Q tile (scaled by 0.125 — exact power of 2 in fp16)
    const __half2 sc2 = __floats2half2_rn(SCALE, SCALE);
    #pragma unroll
    for (int it = 0; it < 4; it++) {
        int idx = it * ATHREADS + tid;
        int rr = idx >> 3, cc = idx & 7;
        uint4 v = *(const uint4*)(qkv + (size_t)(rowbase + q0 + rr) * QKV_N + h * HD + cc * 8);
        __half2* hv = (__half2*)&v;
        hv[0] = __hmul2(hv[0], sc2); hv[1] = __hmul2(hv[1], sc2);
        hv[2] = __hmul2(hv[2], sc2); hv[3] = __hmul2(hv[3], sc2);
        *(uint4*)(qp_ptr + rr * 128 + ((cc ^ (rr & 7)) << 4)) = v;
    }

    // K and V both staged K-major (rows = j, 128B = 64 fp16 per row)
    #define STAGE_KV(buf, j0)                                                            \
        _Pragma("unroll")                                                                \
        for (int it_ = 0; it_ < 4; it_++) {                                              \
            int idx = it_ * ATHREADS + tid;                                              \
            int rr = idx >> 3, cc = idx & 7;                                             \
            uint32_t sw = (buf) * KVTILE + rr * 128 + ((cc ^ (rr & 7)) << 4);            \
            CP_ASYNC16(ks_base + sw,                                                     \
                qkv + (size_t)(rowbase + (j0) + rr) * QKV_N + DIM + h * HD + cc * 8);    \
            CP_ASYNC16(vs_base + sw,                                                     \
                qkv + (size_t)(rowbase + (j0) + rr) * QKV_N + 2 * DIM + h * HD + cc * 8);\
        }

    STAGE_KV(0, 0)
    if (tid < AKT) es[tid] = __expf(bar * elev[rowbase + tid]);
    CP_COMMIT();
    STAGE_KV(1, AKT)
    if (tid < AKT) es[AKT + tid] = __expf(bar * elev[rowbase + AKT + tid]);
    CP_COMMIT();
    __syncthreads();   // Q tile visible

    const int a_row = lane & 15, a_hi = lane >> 4;

    uint32_t qa[4][4];
    #pragma unroll
    for (int ks = 0; ks < 4; ks++) {
        int row = (warp << 4) + a_row;
        int f8  = (ks << 1) + a_hi;
        uint32_t addr = qp_base + row * 128 + ((f8 ^ (row & 7)) << 4);
        LDSM_X4(qa[ks][0], qa[ks][1], qa[ks][2], qa[ks][3], addr);
    }

    // trans-ldsm lane addressing for V: j-row and 16B d-unit per lane
    const int vt_jrow = (lane & 7) + ((lane >> 3) & 1) * 8;   // 0..15 within chunk
    const int vt_dhi  = (lane >> 4) & 1;                      // 0/1 -> d block

    const int g = lane >> 2, tg = lane & 3;
    const float Fi0 = __expf(-bar * elev[rowbase + q0 + (warp << 4) + g]);
    const float Fi1 = __expf(-bar * elev[rowbase + q0 + (warp << 4) + g + 8]);

    float m0 = -1e30f, m1 = -1e30f;
    float lp0 = 0.f, lm0 = 0.f, lp1 = 0.f, lm1 = 0.f;
    float o[8][4];
    #pragma unroll
    for (int dt = 0; dt < 8; dt++)
        #pragma unroll
        for (int r = 0; r < 4; r++) o[dt][r] = 0.f;

    const int nTiles = NLEN / AKT;
    int buf = 0;
    for (int t = 0; t < nTiles; t++) {
        CP_WAIT1();        // tile t complete (one newer group may be pending)
        __syncthreads();   // visibility + all threads done with slot (t-1)%3

        if (t + 2 < nTiles) {
            STAGE_KV((t + 2) % 3, (t + 2) * AKT)
            if (tid < AKT) es[((t + 2) % 3) * AKT + tid] =
                __expf(bar * elev[rowbase + (t + 2) * AKT + tid]);
        }
        CP_COMMIT();       // unconditional: one group per iteration

        const uint32_t kb = ks_base + buf * KVTILE;
        const uint32_t vb = vs_base + buf * KVTILE;
        const float* esb = es + buf * AKT;

        // ---- S = Qs @ Ks^T ----
        float s[8][4];
        #pragma unroll
        for (int nt = 0; nt < 8; nt++)
            #pragma unroll
            for (int r = 0; r < 4; r++) s[nt][r] = 0.f;

        #pragma unroll
        for (int ks = 0; ks < 4; ks++) {
            const int f8 = (ks << 1) + a_hi;
            uint32_t bf[8][2];
            #pragma unroll
            for (int np = 0; np < 4; np++) {
                int row = (np << 4) + a_row;
                uint32_t addr = kb + row * 128 + ((f8 ^ (row & 7)) << 4);
                uint32_t t0, t1, t2, t3;
                LDSM_X4(t0, t1, t2, t3, addr);
                bf[np * 2 + 0][0] = t0; bf[np * 2 + 0][1] = t2;
                bf[np * 2 + 1][0] = t1; bf[np * 2 + 1][1] = t3;
            }
            #pragma unroll
            for (int nt = 0; nt < 8; nt++) MMA_F16(s[nt], qa[ks], bf[nt]);
        }

        // ---- online softmax ----
        float r0 = -1e30f, r1 = -1e30f;
        #pragma unroll
        for (int nt = 0; nt < 8; nt++) {
            r0 = fmaxf(r0, fmaxf(s[nt][0], s[nt][1]));
            r1 = fmaxf(r1, fmaxf(s[nt][2], s[nt][3]));
        }
        r0 = fmaxf(r0, __shfl_xor_sync(0xffffffffu, r0, 1));
        r0 = fmaxf(r0, __shfl_xor_sync(0xffffffffu, r0, 2));
        r1 = fmaxf(r1, __shfl_xor_sync(0xffffffffu, r1, 1));
        r1 = fmaxf(r1, __shfl_xor_sync(0xffffffffu, r1, 2));

        float nm0 = fmaxf(m0, r0), nm1 = fmaxf(m1, r1);
        float al0 = __expf(m0 - nm0), al1 = __expf(m1 - nm1);
        m0 = nm0; m1 = nm1;
        lp0 *= al0; lm0 *= al0; lp1 *= al1; lm1 *= al1;
        #pragma unroll
        for (int dt = 0; dt < 8; dt++) {
            o[dt][0] *= al0; o[dt][1] *= al0;
            o[dt][2] *= al1; o[dt][3] *= al1;
        }

        const int row0 = (warp << 4) + g;
        const int row1 = row0 + 8;
        #pragma unroll
        for (int nt = 0; nt < 8; nt++) {
            int c = (nt << 3) + (tg << 1);
            float Ej0 = esb[c], Ej1 = esb[c + 1];
            // sigmoid in [0.047, 0.953] for |bar*diff|<=3: clamps can never bind
            float mk00 = frcp(fmaf(Ej0, Fi0, 1.0f));
            float mk01 = frcp(fmaf(Ej1, Fi0, 1.0f));
            float mk10 = frcp(fmaf(Ej0, Fi1, 1.0f));
            float mk11 = frcp(fmaf(Ej1, Fi1, 1.0f));

            float p00 = __expf(s[nt][0] - m0), p01 = __expf(s[nt][1] - m0);
            float p10 = __expf(s[nt][2] - m1), p11 = __expf(s[nt][3] - m1);
            lp0 += p00 + p01; lp1 += p10 + p11;
            float pm00 = p00 * mk00, pm01 = p01 * mk01;
            float pm10 = p10 * mk10, pm11 = p11 * mk11;
            lm0 += pm00 + pm01; lm1 += pm10 + pm11;

            *(__half2*)(qp_ptr + row0 * 128 + (((c >> 3) ^ (row0 & 7)) << 4) + ((c & 7) << 1)) =
                __floats2half2_rn(pm00, pm01);
            *(__half2*)(qp_ptr + row1 * 128 + (((c >> 3) ^ (row1 & 7)) << 4) + ((c & 7) << 1)) =
                __floats2half2_rn(pm10, pm11);
        }
        __syncwarp();

        // ---- O += P @ V^T : V fragments via ldmatrix.trans from K-major V ----
        #pragma unroll
        for (int ks = 0; ks < 4; ks++) {
            const int f8 = (ks << 1) + a_hi;
            uint32_t pa[4];
            {
                int row = (warp << 4) + a_row;
                uint32_t addr = qp_base + row * 128 + ((f8 ^ (row & 7)) << 4);
                LDSM_X4(pa[0], pa[1], pa[2], pa[3], addr);
            }
            const int jrow = (ks << 4) + vt_jrow;     // source row (j) for this lane
            uint32_t vf[8][2];
            #pragma unroll
            for (int np = 0; np < 4; np++) {
                // lane's 16B unit: d block np*2 + vt_dhi, swizzled by j-row
                int u = (np << 1) + vt_dhi;
                uint32_t addr = vb + jrow * 128 + ((u ^ (jrow & 7)) << 4);
                uint32_t t0, t1, t2, t3;
                LDSM_X4_T(t0, t1, t2, t3, addr);
                // trans tiles: t0=(d0-7,j0-7) t1=(d0-7,j8-15) t2=(d8-15,j0-7) t3=(d8-15,j8-15)
                vf[np * 2 + 0][0] = t0; vf[np * 2 + 0][1] = t1;
                vf[np * 2 + 1][0] = t2; vf[np * 2 + 1][1] = t3;
            }
            #pragma unroll
            for (int dt = 0; dt < 8; dt++) MMA_F16(o[dt], pa, vf[dt]);
        }
        buf++; if (buf == 3) buf = 0;
    }
    #undef STAGE_KV

    lp0 += __shfl_xor_sync(0xffffffffu, lp0, 1); lp0 += __shfl_xor_sync(0xffffffffu, lp0, 2);
    lm0 += __shfl_xor_sync(0xffffffffu, lm0, 1); lm0 += __shfl_xor_sync(0xffffffffu, lm0, 2);
    lp1 += __shfl_xor_sync(0xffffffffu, lp1, 1); lp1 += __shfl_xor_sync(0xffffffffu, lp1, 2);
    lm1 += __shfl_xor_sync(0xffffffffu, lm1, 1); lm1 += __shfl_xor_sync(0xffffffffu, lm1, 2);
    const float inv0 = 1.0f / (lm0 + 1e-8f * lp0);
    const float inv1 = 1.0f / (lm1 + 1e-8f * lp1);

    const int r0 = rowbase + q0 + (warp << 4) + g;
    #pragma unroll
    for (int dt = 0; dt < 8; dt++) {
        int col = h * HD + (dt << 3) + (tg << 1);
        *(__half2*)&out[(size_t)r0 * DIM + col] =
            __floats2half2_rn(o[dt][0] * inv0, o[dt][1] * inv0);
        *(__half2*)&out[(size_t)(r0 + 8) * DIM + col] =
            __floats2half2_rn(o[dt][2] * inv1, o[dt][3] * inv1);
    }
}

// ---------------- launch ----------------
#define ATTN_SMEM (6 * KVTILE + AQT * 128 + 3 * AKT * 4)

extern "C" void kernel_launch(void* const* d_in, const int* in_sizes, int n_in,
                              void* d_out, int out_size)
{
    const float* x      = (const float*)d_in[0];
    const float* elev   = (const float*)d_in[1];
    const float* qkv_w  = (const float*)d_in[2];
    const float* qkv_b  = (const float*)d_in[3];
    const float* proj_w = (const float*)d_in[4];
    const float* proj_b = (const float*)d_in[5];
    const float* ln1_g  = (const float*)d_in[6];
    const float* ln1_b  = (const float*)d_in[7];
    const float* ln2_g  = (const float*)d_in[8];
    const float* ln2_b  = (const float*)d_in[9];
    const float* fc1_w  = (const float*)d_in[10];
    const float* fc1_b  = (const float*)d_in[11];
    const float* fc2_w  = (const float*)d_in[12];
    const float* fc2_b  = (const float*)d_in[13];
    const float* barrier= (const float*)d_in[14];
    float* out = (float*)d_out;

    const int rows = in_sizes[0] / DIM;     // B*N
    const int B = rows / NLEN;

    __half *h, *qkv, *attn, *ff, *wtq, *wtp, *wt1, *wt2;
    float *x2;
    cudaGetSymbolAddress((void**)&h,    g_h);
    cudaGetSymbolAddress((void**)&qkv,  g_qkv);
    cudaGetSymbolAddress((void**)&attn, g_attn);
    cudaGetSymbolAddress((void**)&x2,   g_x2);
    cudaGetSymbolAddress((void**)&ff,   g_ff);
    cudaGetSymbolAddress((void**)&wtq,  g_wt_qkv);
    cudaGetSymbolAddress((void**)&wtp,  g_wt_proj);
    cudaGetSymbolAddress((void**)&wt1,  g_wt_fc1);
    cudaGetSymbolAddress((void**)&wt2,  g_wt_fc2);

    cudaFuncSetAttribute(gemm_tc<0,1>, cudaFuncAttributeMaxDynamicSharedMemorySize, GEMM_SMEM);
    cudaFuncSetAttribute(gemm_tc<1,0>, cudaFuncAttributeMaxDynamicSharedMemorySize, GEMM_SMEM);
    cudaFuncSetAttribute(gemm_tc<2,1>, cudaFuncAttributeMaxDynamicSharedMemorySize, GEMM_SMEM);
    cudaFuncSetAttribute(attn_tc,      cudaFuncAttributeMaxDynamicSharedMemorySize, ATTN_SMEM);

    // 0. all weight transposes (+ fp16 convert), one launch
    transpose_all<<<6912, 256>>>(qkv_w, proj_w, fc1_w, fc2_w, wtq, wtp, wt1, wt2);

    // 1. LN1 (fp16 out)
    ln_kernel<<<rows / 8, 256>>>(x, ln1_g, ln1_b, h);
    // 2. QKV projection (fp16 out)
    gemm_tc<0,1><<<dim3(QKV_N / 128, rows / 128), 256, GEMM_SMEM>>>(h, wtq, qkv_b, nullptr, qkv, rows, QKV_N, DIM);
    // 3. fused masked flash attention (fp16 tensor cores, V transposed in-kernel)
    attn_tc<<<dim3(B * HEADS, NLEN / AQT), ATHREADS, ATTN_SMEM>>>(qkv, elev, barrier, attn);
    // 4. out proj + residual (fp32 out)
    gemm_tc<1,0><<<dim3(DIM / 128, rows / 128), 256, GEMM_SMEM>>>(attn, wtp, proj_b, x, x2, rows, DIM, DIM);
    // 5. LN2 (fp16 out)
    ln_kernel<<<rows / 8, 256>>>(x2, ln2_g, ln2_b, h);
    // 6. FC1 + exact GELU (fp16 out)
    gemm_tc<2,1><<<dim3(HIDDEN / 128, rows / 128), 256, GEMM_SMEM>>>(h, wt1, fc1_b, nullptr, ff, rows, HIDDEN, DIM);
    // 7. FC2 + residual -> output (fp32)
    gemm_tc<1,0><<<dim3(DIM / 128, rows / 128), 256, GEMM_SMEM>>>(ff, wt2, fc2_b, x2, out, rows, DIM, HIDDEN);
}

// round 11
// speedup vs baseline: 7.2042x; 1.0342x over previous
#include <cuda_runtime.h>
#include <cuda_fp16.h>
#include <math.h>
#include <stdint.h>

#define DIM 768
#define HEADS 12
#define HD 64
#define HIDDEN 3072
#define QKV_N 2304
#define MAX_ROWS 4096
#define SCALE 0.125f
#define NLEN 2048

// ---------------- scratch (no allocation allowed) ----------------
__device__ __half g_h[MAX_ROWS * DIM];
__device__ __half g_qkv[MAX_ROWS * QKV_N];
__device__ __half g_attn[MAX_ROWS * DIM];
__device__ float  g_x2[MAX_ROWS * DIM];
__device__ __half g_ff[MAX_ROWS * HIDDEN];
__device__ __half g_wt_qkv[DIM * QKV_N];
__device__ __half g_wt_proj[DIM * DIM];
__device__ __half g_wt_fc1[DIM * HIDDEN];
__device__ __half g_wt_fc2[HIDDEN * DIM];

__device__ __forceinline__ float frcp(float x) {
    float r;
    asm("rcp.approx.f32 %0, %1;" : "=f"(r) : "f"(x));
    return r;
}
__device__ __forceinline__ float fex2(float x) {
    float r;
    asm("ex2.approx.f32 %0, %1;" : "=f"(r) : "f"(x));
    return r;
}

#define CP_ASYNC16(dst, src) \
    asm volatile("cp.async.cg.shared.global [%0], [%1], 16;\n" :: "r"(dst), "l"(src))
#define CP_COMMIT() asm volatile("cp.async.commit_group;\n" ::: "memory")
#define CP_WAIT1()  asm volatile("cp.async.wait_group 1;\n" ::: "memory")

#define LDSM_X4(r0, r1, r2, r3, addr) \
    asm volatile("ldmatrix.sync.aligned.m8n8.x4.shared.b16 {%0,%1,%2,%3}, [%4];\n" \
                 : "=r"(r0), "=r"(r1), "=r"(r2), "=r"(r3) : "r"(addr))

#define LDSM_X4_T(r0, r1, r2, r3, addr) \
    asm volatile("ldmatrix.sync.aligned.m8n8.x4.trans.shared.b16 {%0,%1,%2,%3}, [%4];\n" \
                 : "=r"(r0), "=r"(r1), "=r"(r2), "=r"(r3) : "r"(addr))

#define MMA_F16(d, a, b) \
    asm volatile("mma.sync.aligned.m16n8k16.row.col.f32.f16.f16.f32 " \
                 "{%0,%1,%2,%3}, {%4,%5,%6,%7}, {%8,%9}, {%0,%1,%2,%3};\n" \
                 : "+f"(d[0]), "+f"(d[1]), "+f"(d[2]), "+f"(d[3]) \
                 : "r"(a[0]), "r"(a[1]), "r"(a[2]), "r"(a[3]), "r"(b[0]), "r"(b[1]))

// ---------------- all 4 weight transposes in ONE launch ----------------
__global__ __launch_bounds__(256)
void transpose_all(const float* __restrict__ w0, const float* __restrict__ w1,
                   const float* __restrict__ w2, const float* __restrict__ w3,
                   __half* __restrict__ o0, __half* __restrict__ o1,
                   __half* __restrict__ o2, __half* __restrict__ o3)
{
    int bid = blockIdx.x;
    const float* W; __half* Wt; int K, N;
    if (bid < 1728)      { W = w0; Wt = o0; K = DIM;    N = QKV_N;  }
    else if (bid < 2304) { W = w1; Wt = o1; K = DIM;    N = DIM;    bid -= 1728; }
    else if (bid < 4608) { W = w2; Wt = o2; K = DIM;    N = HIDDEN; bid -= 2304; }
    else                 { W = w3; Wt = o3; K = HIDDEN; N = DIM;    bid -= 4608; }
    const int nb = N / 32;
    const int n0 = (bid % nb) * 32, k0 = (bid / nb) * 32;

    __shared__ float t[32][33];
    const int tx = threadIdx.x & 31, ty = threadIdx.x >> 5;
    #pragma unroll
    for (int i = 0; i < 32; i += 8)
        t[ty + i][tx] = W[(size_t)(k0 + ty + i) * N + n0 + tx];
    __syncthreads();
    #pragma unroll
    for (int i = 0; i < 32; i += 8)
        Wt[(size_t)(n0 + ty + i) * K + k0 + tx] = __float2half_rn(t[tx][ty + i]);
}

// ---------------- LayerNorm: warp per row, float4 I/O ----------------
__global__ __launch_bounds__(256)
void ln_kernel(const float* __restrict__ x, const float* __restrict__ g,
               const float* __restrict__ bta, __half* __restrict__ out)
{
    const int lane = threadIdx.x & 31;
    const int row = blockIdx.x * 8 + (threadIdx.x >> 5);
    const float* xr = x + (size_t)row * DIM;

    float4 v[6];
    float s = 0.f, s2 = 0.f;
    #pragma unroll
    for (int i = 0; i < 6; i++) {
        v[i] = *(const float4*)(xr + (i * 32 + lane) * 4);
        s  += v[i].x + v[i].y + v[i].z + v[i].w;
        s2 += v[i].x * v[i].x + v[i].y * v[i].y + v[i].z * v[i].z + v[i].w * v[i].w;
    }
    #pragma unroll
    for (int off = 16; off; off >>= 1) {
        s  += __shfl_xor_sync(0xffffffffu, s,  off);
        s2 += __shfl_xor_sync(0xffffffffu, s2, off);
    }
    const float mu  = s * (1.0f / DIM);
    const float inv = rsqrtf(s2 * (1.0f / DIM) - mu * mu + 1e-5f);

    __half* outr = out + (size_t)row * DIM;
    #pragma unroll
    for (int i = 0; i < 6; i++) {
        int c = (i * 32 + lane) * 4;
        float4 gg = *(const float4*)(g + c);
        float4 bb = *(const float4*)(bta + c);
        __half2 h0 = __floats2half2_rn((v[i].x - mu) * inv * gg.x + bb.x,
                                       (v[i].y - mu) * inv * gg.y + bb.y);
        __half2 h1 = __floats2half2_rn((v[i].z - mu) * inv * gg.z + bb.z,
                                       (v[i].w - mu) * inv * gg.w + bb.w);
        uint2 u;
        u.x = *(uint32_t*)&h0; u.y = *(uint32_t*)&h1;
        *(uint2*)(outr + c) = u;
    }
}

// ---------------- fp16 tensor-core GEMM, 3-stage cp.async, 2 CTAs/SM ----------------
#define GBM 128
#define GBN 128
#define GBK 64
#define GTILE (GBM * GBK * 2)       // bytes per A (or B) stage = 16384
#define GEMM_SMEM (6 * GTILE)       // 3 stages x (A + B) = 96 KB

template<int EPI, int OUTH>
__global__ __launch_bounds__(256, 2)
void gemm_tc(const __half* __restrict__ A, const __half* __restrict__ Wt,
             const float* __restrict__ bias, const float* __restrict__ res,
             void* __restrict__ Cout, int M, int N, int K)
{
    extern __shared__ char sm[];
    const int tid  = threadIdx.x;
    const int lane = tid & 31, warp = tid >> 5;
    const int wm = warp >> 2, wn = warp & 3;
    const int m0 = blockIdx.y << 7, n0 = blockIdx.x << 7;

    const uint32_t as_base = (uint32_t)__cvta_generic_to_shared(sm);
    const uint32_t bs_base = as_base + 3 * GTILE;

    float acc[4][4][4];
    #pragma unroll
    for (int i = 0; i < 4; i++)
        #pragma unroll
        for (int j = 0; j < 4; j++)
            #pragma unroll
            for (int r = 0; r < 4; r++) acc[i][j][r] = 0.f;

    #define STAGE(buf, k0)                                                              \
        _Pragma("unroll")                                                               \
        for (int s_ = 0; s_ < 4; s_++) {                                                \
            int idx = s_ * 256 + tid;                                                   \
            int r_ = idx >> 3, c_ = idx & 7;                                            \
            uint32_t sw = (buf) * GTILE + r_ * 128 + ((c_ ^ (r_ & 7)) << 4);            \
            CP_ASYNC16(as_base + sw, A  + (size_t)(m0 + r_) * K + (k0) + c_ * 8);       \
            CP_ASYNC16(bs_base + sw, Wt + (size_t)(n0 + r_) * K + (k0) + c_ * 8);       \
        }

    STAGE(0, 0)
    CP_COMMIT();
    STAGE(1, GBK)
    CP_COMMIT();

    const int a_row = lane & 15, a_hi = lane >> 4;
    const int kIters = K / GBK;

    int buf = 0;
    for (int it = 0; it < kIters; it++) {
        CP_WAIT1();
        __syncthreads();

        if (it + 2 < kIters) { STAGE((it + 2) % 3, (it + 2) * GBK) }
        CP_COMMIT();

        const uint32_t ab = as_base + buf * GTILE;
        const uint32_t bb = bs_base + buf * GTILE;

        #pragma unroll
        for (int ks = 0; ks < 4; ks++) {
            const int f8 = (ks << 1) + a_hi;
            uint32_t af[4][4], bf[4][2];
            #pragma unroll
            for (int mt = 0; mt < 4; mt++) {
                int row = (wm << 6) + (mt << 4) + a_row;
                uint32_t addr = ab + row * 128 + ((f8 ^ (row & 7)) << 4);
                LDSM_X4(af[mt][0], af[mt][1], af[mt][2], af[mt][3], addr);
            }
            #pragma unroll
            for (int np = 0; np < 2; np++) {
                int row = (wn << 5) + (np << 4) + a_row;
                uint32_t addr = bb + row * 128 + ((f8 ^ (row & 7)) << 4);
                uint32_t q0, q1, q2, q3;
                LDSM_X4(q0, q1, q2, q3, addr);
                bf[np * 2 + 0][0] = q0; bf[np * 2 + 0][1] = q2;
                bf[np * 2 + 1][0] = q1; bf[np * 2 + 1][1] = q3;
            }
            #pragma unroll
            for (int mt = 0; mt < 4; mt++)
                #pragma unroll
                for (int nt = 0; nt < 4; nt++)
                    MMA_F16(acc[mt][nt], af[mt], bf[nt]);
        }
        buf++; if (buf == 3) buf = 0;
    }
    #undef STAGE

    const int g = lane >> 2, tg = lane & 3;
    #pragma unroll
    for (int mt = 0; mt < 4; mt++) {
        #pragma unroll
        for (int nt = 0; nt < 4; nt++) {
            int row = m0 + (wm << 6) + (mt << 4) + g;
            int col = n0 + (wn << 5) + (nt << 3) + (tg << 1);
            float b0 = bias[col], b1 = bias[col + 1];
            #pragma unroll
            for (int half = 0; half < 2; half++) {
                int r = row + half * 8;
                float v0 = acc[mt][nt][half * 2 + 0] + b0;
                float v1 = acc[mt][nt][half * 2 + 1] + b1;
                if (EPI == 1) {
                    const float2 rr = *(const float2*)&res[(size_t)r * N + col];
                    v0 += rr.x; v1 += rr.y;
                }
                if (EPI == 2) {
                    v0 = 0.5f * v0 * (1.0f + erff(v0 * 0.70710678118654752f));
                    v1 = 0.5f * v1 * (1.0f + erff(v1 * 0.70710678118654752f));
                }
                if (OUTH) {
                    *(__half2*)((__half*)Cout + (size_t)r * N + col) = __floats2half2_rn(v0, v1);
                } else {
                    *(float2*)((float*)Cout + (size_t)r * N + col) = make_float2(v0, v1);
                }
            }
        }
    }
}

// ---------------- fp16 tensor-core flash attention ----------------
// CTA: 128 threads = 4 warps, each warp 16 q-rows => Q tile 64. Key tile 64,
// 3-stage cp.async pipeline, ONE __syncthreads per tile. V staged K-major and
// its PV B-fragments loaded via ldmatrix.trans (no global V transpose).
// Q pre-scaled by SCALE*log2e so all softmax exps are bare ex2.approx.
// KEY TRICK: P never touches smem — the S-mma C-fragment layout (rows g/g+8,
// cols 2tg..2tg+1 of each n8 tile) IS the A-fragment layout of the PV mma
// (S n-tile nt -> PV k-tile nt/2, half nt&1), so pm is packed straight into
// PV A-registers.
#define AQT 64
#define ATHREADS 128
#define AKT 64
#define KVTILE (AKT * HD * 2)    // 8192 bytes per operand per stage

__global__ __launch_bounds__(ATHREADS)
void attn_tc(const __half* __restrict__ qkv,
             const float* __restrict__ elev, const float* __restrict__ barrier,
             __half* __restrict__ out)
{
    extern __shared__ char sm[];
    const uint32_t smb     = (uint32_t)__cvta_generic_to_shared(sm);
    const uint32_t ks_base = smb;                     // 3 x 8192 (K)
    const uint32_t vs_base = smb + 3 * KVTILE;        // 3 x 8192 (V, K-major j rows)
    const uint32_t qp_base = smb + 6 * KVTILE;        // 64 x 128B (Q staging)
    char* qp_ptr = sm + 6 * KVTILE;
    float* es = (float*)(sm + 6 * KVTILE + AQT * 128);   // 3 x 64 floats

    const int bh = blockIdx.x, b = bh / HEADS, h = bh % HEADS;
    const int q0 = blockIdx.y * AQT;
    const int tid = threadIdx.x, lane = tid & 31, warp = tid >> 5;
    const int rowbase = b * NLEN;
    const float bar = *barrier;

    // stage Q tile, pre-scaled by SCALE*log2(e)  (exp2 softmax domain)
    const __half2 sc2 = __floats2half2_rn(SCALE * 1.4426950408889634f,
                                          SCALE * 1.4426950408889634f);
    #pragma unroll
    for (int it = 0; it < 4; it++) {
        int idx = it * ATHREADS + tid;
        int rr = idx >> 3, cc = idx & 7;
        uint4 v = *(const uint4*)(qkv + (size_t)(rowbase + q0 + rr) * QKV_N + h * HD + cc * 8);
        __half2* hv = (__half2*)&v;
        hv[0] = __hmul2(hv[0], sc2); hv[1] = __hmul2(hv[1], sc2);
        hv[2] = __hmul2(hv[2], sc2); hv[3] = __hmul2(hv[3], sc2);
        *(uint4*)(qp_ptr + rr * 128 + ((cc ^ (rr & 7)) << 4)) = v;
    }

    // K and V both staged K-major (rows = j, 128B = 64 fp16 per row)
    #define STAGE_KV(buf, j0)                                                            \
        _Pragma("unroll")                                                                \
        for (int it_ = 0; it_ < 4; it_++) {                                              \
            int idx = it_ * ATHREADS + tid;                                              \
            int rr = idx >> 3, cc = idx & 7;                                             \
            uint32_t sw = (buf) * KVTILE + rr * 128 + ((cc ^ (rr & 7)) << 4);            \
            CP_ASYNC16(ks_base + sw,                                                     \
                qkv + (size_t)(rowbase + (j0) + rr) * QKV_N + DIM + h * HD + cc * 8);    \
            CP_ASYNC16(vs_base + sw,                                                     \
                qkv + (size_t)(rowbase + (j0) + rr) * QKV_N + 2 * DIM + h * HD + cc * 8);\
        }

    STAGE_KV(0, 0)
    if (tid < AKT) es[tid] = __expf(bar * elev[rowbase + tid]);
    CP_COMMIT();
    STAGE_KV(1, AKT)
    if (tid < AKT) es[AKT + tid] = __expf(bar * elev[rowbase + AKT + tid]);
    CP_COMMIT();
    __syncthreads();   // Q tile visible

    const int a_row = lane & 15, a_hi = lane >> 4;

    uint32_t qa[4][4];
    #pragma unroll
    for (int ks = 0; ks < 4; ks++) {
        int row = (warp << 4) + a_row;
        int f8  = (ks << 1) + a_hi;
        uint32_t addr = qp_base + row * 128 + ((f8 ^ (row & 7)) << 4);
        LDSM_X4(qa[ks][0], qa[ks][1], qa[ks][2], qa[ks][3], addr);
    }

    // trans-ldsm lane addressing for V: j-row and 16B d-unit per lane
    const int vt_jrow = (lane & 7) + ((lane >> 3) & 1) * 8;   // 0..15 within chunk
    const int vt_dhi  = (lane >> 4) & 1;                      // 0/1 -> d block

    const int g = lane >> 2, tg = lane & 3;
    const float Fi0 = __expf(-bar * elev[rowbase + q0 + (warp << 4) + g]);
    const float Fi1 = __expf(-bar * elev[rowbase + q0 + (warp << 4) + g + 8]);

    float m0 = -1e30f, m1 = -1e30f;
    float lp0 = 0.f, lm0 = 0.f, lp1 = 0.f, lm1 = 0.f;
    float o[8][4];
    #pragma unroll
    for (int dt = 0; dt < 8; dt++)
        #pragma unroll
        for (int r = 0; r < 4; r++) o[dt][r] = 0.f;

    const int nTiles = NLEN / AKT;
    int buf = 0;
    for (int t = 0; t < nTiles; t++) {
        CP_WAIT1();        // tile t complete (one newer group may be pending)
        __syncthreads();   // visibility + all threads done with slot (t-1)%3

        if (t + 2 < nTiles) {
            STAGE_KV((t + 2) % 3, (t + 2) * AKT)
            if (tid < AKT) es[((t + 2) % 3) * AKT + tid] =
                __expf(bar * elev[rowbase + (t + 2) * AKT + tid]);
        }
        CP_COMMIT();       // unconditional: one group per iteration

        const uint32_t kb = ks_base + buf * KVTILE;
        const uint32_t vb = vs_base + buf * KVTILE;
        const float* esb = es + buf * AKT;

        // ---- S = Qs @ Ks^T  (exp2 domain) ----
        float s[8][4];
        #pragma unroll
        for (int nt = 0; nt < 8; nt++)
            #pragma unroll
            for (int r = 0; r < 4; r++) s[nt][r] = 0.f;

        #pragma unroll
        for (int ks = 0; ks < 4; ks++) {
            const int f8 = (ks << 1) + a_hi;
            uint32_t bf[8][2];
            #pragma unroll
            for (int np = 0; np < 4; np++) {
                int row = (np << 4) + a_row;
                uint32_t addr = kb + row * 128 + ((f8 ^ (row & 7)) << 4);
                uint32_t t0, t1, t2, t3;
                LDSM_X4(t0, t1, t2, t3, addr);
                bf[np * 2 + 0][0] = t0; bf[np * 2 + 0][1] = t2;
                bf[np * 2 + 1][0] = t1; bf[np * 2 + 1][1] = t3;
            }
            #pragma unroll
            for (int nt = 0; nt < 8; nt++) MMA_F16(s[nt], qa[ks], bf[nt]);
        }

        // ---- online softmax (base-2) ----
        float r0 = -1e30f, r1 = -1e30f;
        #pragma unroll
        for (int nt = 0; nt < 8; nt++) {
            r0 = fmaxf(r0, fmaxf(s[nt][0], s[nt][1]));
            r1 = fmaxf(r1, fmaxf(s[nt][2], s[nt][3]));
        }
        r0 = fmaxf(r0, __shfl_xor_sync(0xffffffffu, r0, 1));
        r0 = fmaxf(r0, __shfl_xor_sync(0xffffffffu, r0, 2));
        r1 = fmaxf(r1, __shfl_xor_sync(0xffffffffu, r1, 1));
        r1 = fmaxf(r1, __shfl_xor_sync(0xffffffffu, r1, 2));

        float nm0 = fmaxf(m0, r0), nm1 = fmaxf(m1, r1);
        float al0 = fex2(m0 - nm0), al1 = fex2(m1 - nm1);
        m0 = nm0; m1 = nm1;
        lp0 *= al0; lm0 *= al0; lp1 *= al1; lm1 *= al1;
        #pragma unroll
        for (int dt = 0; dt < 8; dt++) {
            o[dt][0] *= al0; o[dt][1] *= al0;
            o[dt][2] *= al1; o[dt][3] *= al1;
        }

        // P packed directly into PV A-fragments (no smem round trip)
        uint32_t pa[4][4];
        #pragma unroll
        for (int nt = 0; nt < 8; nt++) {
            int c = (nt << 3) + (tg << 1);
            float Ej0 = esb[c], Ej1 = esb[c + 1];
            // sigmoid in [0.047, 0.953] for |bar*diff|<=3: clamps can never bind
            float mk00 = frcp(fmaf(Ej0, Fi0, 1.0f));
            float mk01 = frcp(fmaf(Ej1, Fi0, 1.0f));
            float mk10 = frcp(fmaf(Ej0, Fi1, 1.0f));
            float mk11 = frcp(fmaf(Ej1, Fi1, 1.0f));

            float p00 = fex2(s[nt][0] - m0), p01 = fex2(s[nt][1] - m0);
            float p10 = fex2(s[nt][2] - m1), p11 = fex2(s[nt][3] - m1);
            lp0 += p00 + p01; lp1 += p10 + p11;
            float pm00 = p00 * mk00, pm01 = p01 * mk01;
            float pm10 = p10 * mk10, pm11 = p11 * mk11;
            lm0 += pm00 + pm01; lm1 += pm10 + pm11;

            const int ks = nt >> 1, hi = (nt & 1) << 1;
            __half2 h0 = __floats2half2_rn(pm00, pm01);   // row g
            __half2 h1 = __floats2half2_rn(pm10, pm11);   // row g+8
            pa[ks][hi + 0] = *(uint32_t*)&h0;
            pa[ks][hi + 1] = *(uint32_t*)&h1;
        }

        // ---- O += P @ V^T : V fragments via ldmatrix.trans from K-major V ----
        #pragma unroll
        for (int ks = 0; ks < 4; ks++) {
            const int jrow = (ks << 4) + vt_jrow;     // source row (j) for this lane
            uint32_t vf[8][2];
            #pragma unroll
            for (int np = 0; np < 4; np++) {
                int u = (np << 1) + vt_dhi;
                uint32_t addr = vb + jrow * 128 + ((u ^ (jrow & 7)) << 4);
                uint32_t t0, t1, t2, t3;
                LDSM_X4_T(t0, t1, t2, t3, addr);
                vf[np * 2 + 0][0] = t0; vf[np * 2 + 0][1] = t1;
                vf[np * 2 + 1][0] = t2; vf[np * 2 + 1][1] = t3;
            }
            #pragma unroll
            for (int dt = 0; dt < 8; dt++) MMA_F16(o[dt], pa[ks], vf[dt]);
        }
        buf++; if (buf == 3) buf = 0;
    }
    #undef STAGE_KV

    lp0 += __shfl_xor_sync(0xffffffffu, lp0, 1); lp0 += __shfl_xor_sync(0xffffffffu, lp0, 2);
    lm0 += __shfl_xor_sync(0xffffffffu, lm0, 1); lm0 += __shfl_xor_sync(0xffffffffu, lm0, 2);
    lp1 += __shfl_xor_sync(0xffffffffu, lp1, 1); lp1 += __shfl_xor_sync(0xffffffffu, lp1, 2);
    lm1 += __shfl_xor_sync(0xffffffffu, lm1, 1); lm1 += __shfl_xor_sync(0xffffffffu, lm1, 2);
    const float inv0 = 1.0f / (lm0 + 1e-8f * lp0);
    const float inv1 = 1.0f / (lm1 + 1e-8f * lp1);

    const int r0 = rowbase + q0 + (warp << 4) + g;
    #pragma unroll
    for (int dt = 0; dt < 8; dt++) {
        int col = h * HD + (dt << 3) + (tg << 1);
        *(__half2*)&out[(size_t)r0 * DIM + col] =
            __floats2half2_rn(o[dt][0] * inv0, o[dt][1] * inv0);
        *(__half2*)&out[(size_t)(r0 + 8) * DIM + col] =
            __floats2half2_rn(o[dt][2] * inv1, o[dt][3] * inv1);
    }
}

// ---------------- launch ----------------
#define ATTN_SMEM (6 * KVTILE + AQT * 128 + 3 * AKT * 4)

extern "C" void kernel_launch(void* const* d_in, const int* in_sizes, int n_in,
                              void* d_out, int out_size)
{
    const float* x      = (const float*)d_in[0];
    const float* elev   = (const float*)d_in[1];
    const float* qkv_w  = (const float*)d_in[2];
    const float* qkv_b  = (const float*)d_in[3];
    const float* proj_w = (const float*)d_in[4];
    const float* proj_b = (const float*)d_in[5];
    const float* ln1_g  = (const float*)d_in[6];
    const float* ln1_b  = (const float*)d_in[7];
    const float* ln2_g  = (const float*)d_in[8];
    const float* ln2_b  = (const float*)d_in[9];
    const float* fc1_w  = (const float*)d_in[10];
    const float* fc1_b  = (const float*)d_in[11];
    const float* fc2_w  = (const float*)d_in[12];
    const float* fc2_b  = (const float*)d_in[13];
    const float* barrier= (const float*)d_in[14];
    float* out = (float*)d_out;

    const int rows = in_sizes[0] / DIM;     // B*N
    const int B = rows / NLEN;

    __half *h, *qkv, *attn, *ff, *wtq, *wtp, *wt1, *wt2;
    float *x2;
    cudaGetSymbolAddress((void**)&h,    g_h);
    cudaGetSymbolAddress((void**)&qkv,  g_qkv);
    cudaGetSymbolAddress((void**)&attn, g_attn);
    cudaGetSymbolAddress((void**)&x2,   g_x2);
    cudaGetSymbolAddress((void**)&ff,   g_ff);
    cudaGetSymbolAddress((void**)&wtq,  g_wt_qkv);
    cudaGetSymbolAddress((void**)&wtp,  g_wt_proj);
    cudaGetSymbolAddress((void**)&wt1,  g_wt_fc1);
    cudaGetSymbolAddress((void**)&wt2,  g_wt_fc2);

    cudaFuncSetAttribute(gemm_tc<0,1>, cudaFuncAttributeMaxDynamicSharedMemorySize, GEMM_SMEM);
    cudaFuncSetAttribute(gemm_tc<1,0>, cudaFuncAttributeMaxDynamicSharedMemorySize, GEMM_SMEM);
    cudaFuncSetAttribute(gemm_tc<2,1>, cudaFuncAttributeMaxDynamicSharedMemorySize, GEMM_SMEM);
    cudaFuncSetAttribute(attn_tc,      cudaFuncAttributeMaxDynamicSharedMemorySize, ATTN_SMEM);

    // 0. all weight transposes (+ fp16 convert), one launch
    transpose_all<<<6912, 256>>>(qkv_w, proj_w, fc1_w, fc2_w, wtq, wtp, wt1, wt2);

    // 1. LN1 (fp16 out)
    ln_kernel<<<rows / 8, 256>>>(x, ln1_g, ln1_b, h);
    // 2. QKV projection (fp16 out)
    gemm_tc<0,1><<<dim3(QKV_N / 128, rows / 128), 256, GEMM_SMEM>>>(h, wtq, qkv_b, nullptr, qkv, rows, QKV_N, DIM);
    // 3. fused masked flash attention (fp16 tensor cores, P in registers)
    attn_tc<<<dim3(B * HEADS, NLEN / AQT), ATHREADS, ATTN_SMEM>>>(qkv, elev, barrier, attn);
    // 4. out proj + residual (fp32 out)
    gemm_tc<1,0><<<dim3(DIM / 128, rows / 128), 256, GEMM_SMEM>>>(attn, wtp, proj_b, x, x2, rows, DIM, DIM);
    // 5. LN2 (fp16 out)
    ln_kernel<<<rows / 8, 256>>>(x2, ln2_g, ln2_b, h);
    // 6. FC1 + exact GELU (fp16 out)
    gemm_tc<2,1><<<dim3(HIDDEN / 128, rows / 128), 256, GEMM_SMEM>>>(h, wt1, fc1_b, nullptr, ff, rows, HIDDEN, DIM);
    // 7. FC2 + residual -> output (fp32)
    gemm_tc<1,0><<<dim3(DIM / 128, rows / 128), 256, GEMM_SMEM>>>(ff, wt2, fc2_b, x2, out, rows, DIM, HIDDEN);
}

// round 12
// speedup vs baseline: 7.6809x; 1.0662x over previous
#include <cuda_runtime.h>
#include <cuda_fp16.h>
#include <math.h>
#include <stdint.h>

#define DIM 768
#define HEADS 12
#define HD 64
#define HIDDEN 3072
#define QKV_N 2304
#define MAX_ROWS 4096
#define SCALE 0.125f
#define NLEN 2048

// ---------------- scratch (no allocation allowed) ----------------
__device__ __half g_h[MAX_ROWS * DIM];
__device__ __half g_qkv[MAX_ROWS * QKV_N];
__device__ __half g_attn[MAX_ROWS * DIM];
__device__ float  g_x2[MAX_ROWS * DIM];
__device__ __half g_ff[MAX_ROWS * HIDDEN];
__device__ __half g_wt_qkv[DIM * QKV_N];
__device__ __half g_wt_proj[DIM * DIM];
__device__ __half g_wt_fc1[DIM * HIDDEN];
__device__ __half g_wt_fc2[HIDDEN * DIM];

__device__ __forceinline__ float fex2(float x) {
    float r;
    asm("ex2.approx.f32 %0, %1;" : "=f"(r) : "f"(x));
    return r;
}

#define CP_ASYNC16(dst, src) \
    asm volatile("cp.async.cg.shared.global [%0], [%1], 16;\n" :: "r"(dst), "l"(src))
#define CP_COMMIT() asm volatile("cp.async.commit_group;\n" ::: "memory")
#define CP_WAIT1()  asm volatile("cp.async.wait_group 1;\n" ::: "memory")

#define LDSM_X4(r0, r1, r2, r3, addr) \
    asm volatile("ldmatrix.sync.aligned.m8n8.x4.shared.b16 {%0,%1,%2,%3}, [%4];\n" \
                 : "=r"(r0), "=r"(r1), "=r"(r2), "=r"(r3) : "r"(addr))

#define LDSM_X4_T(r0, r1, r2, r3, addr) \
    asm volatile("ldmatrix.sync.aligned.m8n8.x4.trans.shared.b16 {%0,%1,%2,%3}, [%4];\n" \
                 : "=r"(r0), "=r"(r1), "=r"(r2), "=r"(r3) : "r"(addr))

#define MMA_F16(d, a, b) \
    asm volatile("mma.sync.aligned.m16n8k16.row.col.f32.f16.f16.f32 " \
                 "{%0,%1,%2,%3}, {%4,%5,%6,%7}, {%8,%9}, {%0,%1,%2,%3};\n" \
                 : "+f"(d[0]), "+f"(d[1]), "+f"(d[2]), "+f"(d[3]) \
                 : "r"(a[0]), "r"(a[1]), "r"(a[2]), "r"(a[3]), "r"(b[0]), "r"(b[1]))

// ---------------- all 4 weight transposes in ONE launch ----------------
__global__ __launch_bounds__(256)
void transpose_all(const float* __restrict__ w0, const float* __restrict__ w1,
                   const float* __restrict__ w2, const float* __restrict__ w3,
                   __half* __restrict__ o0, __half* __restrict__ o1,
                   __half* __restrict__ o2, __half* __restrict__ o3)
{
    int bid = blockIdx.x;
    const float* W; __half* Wt; int K, N;
    if (bid < 1728)      { W = w0; Wt = o0; K = DIM;    N = QKV_N;  }
    else if (bid < 2304) { W = w1; Wt = o1; K = DIM;    N = DIM;    bid -= 1728; }
    else if (bid < 4608) { W = w2; Wt = o2; K = DIM;    N = HIDDEN; bid -= 2304; }
    else                 { W = w3; Wt = o3; K = HIDDEN; N = DIM;    bid -= 4608; }
    const int nb = N / 32;
    const int n0 = (bid % nb) * 32, k0 = (bid / nb) * 32;

    __shared__ float t[32][33];
    const int tx = threadIdx.x & 31, ty = threadIdx.x >> 5;
    #pragma unroll
    for (int i = 0; i < 32; i += 8)
        t[ty + i][tx] = W[(size_t)(k0 + ty + i) * N + n0 + tx];
    __syncthreads();
    #pragma unroll
    for (int i = 0; i < 32; i += 8)
        Wt[(size_t)(n0 + ty + i) * K + k0 + tx] = __float2half_rn(t[tx][ty + i]);
}

// ---------------- LayerNorm: warp per row, float4 I/O ----------------
__global__ __launch_bounds__(256)
void ln_kernel(const float* __restrict__ x, const float* __restrict__ g,
               const float* __restrict__ bta, __half* __restrict__ out)
{
    const int lane = threadIdx.x & 31;
    const int row = blockIdx.x * 8 + (threadIdx.x >> 5);
    const float* xr = x + (size_t)row * DIM;

    float4 v[6];
    float s = 0.f, s2 = 0.f;
    #pragma unroll
    for (int i = 0; i < 6; i++) {
        v[i] = *(const float4*)(xr + (i * 32 + lane) * 4);
        s  += v[i].x + v[i].y + v[i].z + v[i].w;
        s2 += v[i].x * v[i].x + v[i].y * v[i].y + v[i].z * v[i].z + v[i].w * v[i].w;
    }
    #pragma unroll
    for (int off = 16; off; off >>= 1) {
        s  += __shfl_xor_sync(0xffffffffu, s,  off);
        s2 += __shfl_xor_sync(0xffffffffu, s2, off);
    }
    const float mu  = s * (1.0f / DIM);
    const float inv = rsqrtf(s2 * (1.0f / DIM) - mu * mu + 1e-5f);

    __half* outr = out + (size_t)row * DIM;
    #pragma unroll
    for (int i = 0; i < 6; i++) {
        int c = (i * 32 + lane) * 4;
        float4 gg = *(const float4*)(g + c);
        float4 bb = *(const float4*)(bta + c);
        __half2 h0 = __floats2half2_rn((v[i].x - mu) * inv * gg.x + bb.x,
                                       (v[i].y - mu) * inv * gg.y + bb.y);
        __half2 h1 = __floats2half2_rn((v[i].z - mu) * inv * gg.z + bb.z,
                                       (v[i].w - mu) * inv * gg.w + bb.w);
        uint2 u;
        u.x = *(uint32_t*)&h0; u.y = *(uint32_t*)&h1;
        *(uint2*)(outr + c) = u;
    }
}

// ---------------- fp16 tensor-core GEMM, 3-stage cp.async, 2 CTAs/SM ----------------
#define GBM 128
#define GBN 128
#define GBK 64
#define GTILE (GBM * GBK * 2)       // bytes per A (or B) stage = 16384
#define GEMM_SMEM (6 * GTILE)       // 3 stages x (A + B) = 96 KB

template<int EPI, int OUTH>
__global__ __launch_bounds__(256, 2)
void gemm_tc(const __half* __restrict__ A, const __half* __restrict__ Wt,
             const float* __restrict__ bias, const float* __restrict__ res,
             void* __restrict__ Cout, int M, int N, int K)
{
    extern __shared__ char sm[];
    const int tid  = threadIdx.x;
    const int lane = tid & 31, warp = tid >> 5;
    const int wm = warp >> 2, wn = warp & 3;
    const int m0 = blockIdx.y << 7, n0 = blockIdx.x << 7;

    const uint32_t as_base = (uint32_t)__cvta_generic_to_shared(sm);
    const uint32_t bs_base = as_base + 3 * GTILE;

    float acc[4][4][4];
    #pragma unroll
    for (int i = 0; i < 4; i++)
        #pragma unroll
        for (int j = 0; j < 4; j++)
            #pragma unroll
            for (int r = 0; r < 4; r++) acc[i][j][r] = 0.f;

    #define STAGE(buf, k0)                                                              \
        _Pragma("unroll")                                                               \
        for (int s_ = 0; s_ < 4; s_++) {                                                \
            int idx = s_ * 256 + tid;                                                   \
            int r_ = idx >> 3, c_ = idx & 7;                                            \
            uint32_t sw = (buf) * GTILE + r_ * 128 + ((c_ ^ (r_ & 7)) << 4);            \
            CP_ASYNC16(as_base + sw, A  + (size_t)(m0 + r_) * K + (k0) + c_ * 8);       \
            CP_ASYNC16(bs_base + sw, Wt + (size_t)(n0 + r_) * K + (k0) + c_ * 8);       \
        }

    STAGE(0, 0)
    CP_COMMIT();
    STAGE(1, GBK)
    CP_COMMIT();

    const int a_row = lane & 15, a_hi = lane >> 4;
    const int kIters = K / GBK;

    int buf = 0;
    for (int it = 0; it < kIters; it++) {
        CP_WAIT1();
        __syncthreads();

        if (it + 2 < kIters) { STAGE((it + 2) % 3, (it + 2) * GBK) }
        CP_COMMIT();

        const uint32_t ab = as_base + buf * GTILE;
        const uint32_t bb = bs_base + buf * GTILE;

        #pragma unroll
        for (int ks = 0; ks < 4; ks++) {
            const int f8 = (ks << 1) + a_hi;
            uint32_t af[4][4], bf[4][2];
            #pragma unroll
            for (int mt = 0; mt < 4; mt++) {
                int row = (wm << 6) + (mt << 4) + a_row;
                uint32_t addr = ab + row * 128 + ((f8 ^ (row & 7)) << 4);
                LDSM_X4(af[mt][0], af[mt][1], af[mt][2], af[mt][3], addr);
            }
            #pragma unroll
            for (int np = 0; np < 2; np++) {
                int row = (wn << 5) + (np << 4) + a_row;
                uint32_t addr = bb + row * 128 + ((f8 ^ (row & 7)) << 4);
                uint32_t q0, q1, q2, q3;
                LDSM_X4(q0, q1, q2, q3, addr);
                bf[np * 2 + 0][0] = q0; bf[np * 2 + 0][1] = q2;
                bf[np * 2 + 1][0] = q1; bf[np * 2 + 1][1] = q3;
            }
            #pragma unroll
            for (int mt = 0; mt < 4; mt++)
                #pragma unroll
                for (int nt = 0; nt < 4; nt++)
                    MMA_F16(acc[mt][nt], af[mt], bf[nt]);
        }
        buf++; if (buf == 3) buf = 0;
    }
    #undef STAGE

    const int g = lane >> 2, tg = lane & 3;
    #pragma unroll
    for (int mt = 0; mt < 4; mt++) {
        #pragma unroll
        for (int nt = 0; nt < 4; nt++) {
            int row = m0 + (wm << 6) + (mt << 4) + g;
            int col = n0 + (wn << 5) + (nt << 3) + (tg << 1);
            float b0 = bias[col], b1 = bias[col + 1];
            #pragma unroll
            for (int half = 0; half < 2; half++) {
                int r = row + half * 8;
                float v0 = acc[mt][nt][half * 2 + 0] + b0;
                float v1 = acc[mt][nt][half * 2 + 1] + b1;
                if (EPI == 1) {
                    const float2 rr = *(const float2*)&res[(size_t)r * N + col];
                    v0 += rr.x; v1 += rr.y;
                }
                if (EPI == 2) {
                    v0 = 0.5f * v0 * (1.0f + erff(v0 * 0.70710678118654752f));
                    v1 = 0.5f * v1 * (1.0f + erff(v1 * 0.70710678118654752f));
                }
                if (OUTH) {
                    *(__half2*)((__half*)Cout + (size_t)r * N + col) = __floats2half2_rn(v0, v1);
                } else {
                    *(float2*)((float*)Cout + (size_t)r * N + col) = make_float2(v0, v1);
                }
            }
        }
    }
}

// ---------------- fp16 tensor-core flash attention ----------------
// CTA: 128 threads = 4 warps, warp = 16 q-rows => Q tile 64. Key tile 64,
// 3-stage cp.async, ONE __syncthreads per tile. V B-fragments via
// ldmatrix.trans from K-major V. Q pre-scaled by SCALE*log2e (exp2 domain).
// P is computed entirely in half2 (h2exp2 for p, h2rcp for the sigmoid mask)
// and packed straight into PV A-registers. Row-sums lm obtained by an extra
// MMA against a ones-fragment (fp32 accum, no scalar adds, no reductions).
// lp term dropped: mask>=0.047 => 1e-8*lp <= 2.2e-7*lm (negligible).
#define AQT 64
#define ATHREADS 128
#define AKT 64
#define KVTILE (AKT * HD * 2)    // 8192 bytes per operand per stage

__global__ __launch_bounds__(ATHREADS)
void attn_tc(const __half* __restrict__ qkv,
             const float* __restrict__ elev, const float* __restrict__ barrier,
             __half* __restrict__ out)
{
    extern __shared__ char sm[];
    const uint32_t smb     = (uint32_t)__cvta_generic_to_shared(sm);
    const uint32_t ks_base = smb;                     // 3 x 8192 (K)
    const uint32_t vs_base = smb + 3 * KVTILE;        // 3 x 8192 (V, K-major)
    const uint32_t qp_base = smb + 6 * KVTILE;        // 64 x 128B (Q staging)
    char* qp_ptr = sm + 6 * KVTILE;
    __half* es = (__half*)(sm + 6 * KVTILE + AQT * 128);   // 3 x 64 halfs

    const int bh = blockIdx.x, b = bh / HEADS, h = bh % HEADS;
    const int q0 = blockIdx.y * AQT;
    const int tid = threadIdx.x, lane = tid & 31, warp = tid >> 5;
    const int rowbase = b * NLEN;
    const float bar = *barrier;

    // stage Q tile, pre-scaled by SCALE*log2(e)
    const __half2 sc2 = __floats2half2_rn(SCALE * 1.4426950408889634f,
                                          SCALE * 1.4426950408889634f);
    #pragma unroll
    for (int it = 0; it < 4; it++) {
        int idx = it * ATHREADS + tid;
        int rr = idx >> 3, cc = idx & 7;
        uint4 v = *(const uint4*)(qkv + (size_t)(rowbase + q0 + rr) * QKV_N + h * HD + cc * 8);
        __half2* hv = (__half2*)&v;
        hv[0] = __hmul2(hv[0], sc2); hv[1] = __hmul2(hv[1], sc2);
        hv[2] = __hmul2(hv[2], sc2); hv[3] = __hmul2(hv[3], sc2);
        *(uint4*)(qp_ptr + rr * 128 + ((cc ^ (rr & 7)) << 4)) = v;
    }

    #define STAGE_KV(buf, j0)                                                            \
        _Pragma("unroll")                                                                \
        for (int it_ = 0; it_ < 4; it_++) {                                              \
            int idx = it_ * ATHREADS + tid;                                              \
            int rr = idx >> 3, cc = idx & 7;                                             \
            uint32_t sw = (buf) * KVTILE + rr * 128 + ((cc ^ (rr & 7)) << 4);            \
            CP_ASYNC16(ks_base + sw,                                                     \
                qkv + (size_t)(rowbase + (j0) + rr) * QKV_N + DIM + h * HD + cc * 8);    \
            CP_ASYNC16(vs_base + sw,                                                     \
                qkv + (size_t)(rowbase + (j0) + rr) * QKV_N + 2 * DIM + h * HD + cc * 8);\
        }

    STAGE_KV(0, 0)
    if (tid < AKT) es[tid] = __float2half_rn(__expf(bar * elev[rowbase + tid]));
    CP_COMMIT();
    STAGE_KV(1, AKT)
    if (tid < AKT) es[AKT + tid] = __float2half_rn(__expf(bar * elev[rowbase + AKT + tid]));
    CP_COMMIT();
    __syncthreads();   // Q tile visible

    const int a_row = lane & 15, a_hi = lane >> 4;

    uint32_t qa[4][4];
    #pragma unroll
    for (int ks = 0; ks < 4; ks++) {
        int row = (warp << 4) + a_row;
        int f8  = (ks << 1) + a_hi;
        uint32_t addr = qp_base + row * 128 + ((f8 ^ (row & 7)) << 4);
        LDSM_X4(qa[ks][0], qa[ks][1], qa[ks][2], qa[ks][3], addr);
    }

    // trans-ldsm lane addressing for V
    const int vt_jrow = (lane & 7) + ((lane >> 3) & 1) * 8;
    const int vt_dhi  = (lane >> 4) & 1;

    const int g = lane >> 2, tg = lane & 3;
    const float Fi0f = __expf(-bar * elev[rowbase + q0 + (warp << 4) + g]);
    const float Fi1f = __expf(-bar * elev[rowbase + q0 + (warp << 4) + g + 8]);
    const __half2 Fi0 = __floats2half2_rn(Fi0f, Fi0f);
    const __half2 Fi1 = __floats2half2_rn(Fi1f, Fi1f);
    const __half2 one2 = __floats2half2_rn(1.0f, 1.0f);
    uint32_t ones_bf[2];
    ones_bf[0] = ones_bf[1] = 0x3C003C00u;   // half2(1,1)

    float m0 = -1e30f, m1 = -1e30f;
    float o[8][4];
    #pragma unroll
    for (int dt = 0; dt < 8; dt++)
        #pragma unroll
        for (int r = 0; r < 4; r++) o[dt][r] = 0.f;
    float lacc[4] = {0.f, 0.f, 0.f, 0.f};     // row-sum fragment (lm)

    const int nTiles = NLEN / AKT;
    int buf = 0;
    for (int t = 0; t < nTiles; t++) {
        CP_WAIT1();
        __syncthreads();

        if (t + 2 < nTiles) {
            STAGE_KV((t + 2) % 3, (t + 2) * AKT)
            if (tid < AKT) es[((t + 2) % 3) * AKT + tid] =
                __float2half_rn(__expf(bar * elev[rowbase + (t + 2) * AKT + tid]));
        }
        CP_COMMIT();

        const uint32_t kb = ks_base + buf * KVTILE;
        const uint32_t vb = vs_base + buf * KVTILE;
        const __half* esb = es + buf * AKT;

        // ---- S = Qs @ Ks^T  (exp2 domain) ----
        float s[8][4];
        #pragma unroll
        for (int nt = 0; nt < 8; nt++)
            #pragma unroll
            for (int r = 0; r < 4; r++) s[nt][r] = 0.f;

        #pragma unroll
        for (int ks = 0; ks < 4; ks++) {
            const int f8 = (ks << 1) + a_hi;
            uint32_t bf[8][2];
            #pragma unroll
            for (int np = 0; np < 4; np++) {
                int row = (np << 4) + a_row;
                uint32_t addr = kb + row * 128 + ((f8 ^ (row & 7)) << 4);
                uint32_t t0, t1, t2, t3;
                LDSM_X4(t0, t1, t2, t3, addr);
                bf[np * 2 + 0][0] = t0; bf[np * 2 + 0][1] = t2;
                bf[np * 2 + 1][0] = t1; bf[np * 2 + 1][1] = t3;
            }
            #pragma unroll
            for (int nt = 0; nt < 8; nt++) MMA_F16(s[nt], qa[ks], bf[nt]);
        }

        // ---- online softmax (base-2, half2 math) ----
        float r0 = -1e30f, r1 = -1e30f;
        #pragma unroll
        for (int nt = 0; nt < 8; nt++) {
            r0 = fmaxf(r0, fmaxf(s[nt][0], s[nt][1]));
            r1 = fmaxf(r1, fmaxf(s[nt][2], s[nt][3]));
        }
        r0 = fmaxf(r0, __shfl_xor_sync(0xffffffffu, r0, 1));
        r0 = fmaxf(r0, __shfl_xor_sync(0xffffffffu, r0, 2));
        r1 = fmaxf(r1, __shfl_xor_sync(0xffffffffu, r1, 1));
        r1 = fmaxf(r1, __shfl_xor_sync(0xffffffffu, r1, 2));

        float nm0 = fmaxf(m0, r0), nm1 = fmaxf(m1, r1);
        float al0 = fex2(m0 - nm0), al1 = fex2(m1 - nm1);
        m0 = nm0; m1 = nm1;
        // skip rescale when no thread's max changed (al==1 exactly)
        if (!__all_sync(0xffffffffu, (al0 == 1.0f) && (al1 == 1.0f))) {
            #pragma unroll
            for (int dt = 0; dt < 8; dt++) {
                o[dt][0] *= al0; o[dt][1] *= al0;
                o[dt][2] *= al1; o[dt][3] *= al1;
            }
            lacc[0] *= al0; lacc[1] *= al0;
            lacc[2] *= al1; lacc[3] *= al1;
        }

        // P packed directly into PV A-fragments (half2 exp + half2 mask)
        uint32_t pa[4][4];
        #pragma unroll
        for (int nt = 0; nt < 8; nt++) {
            int c = (nt << 3) + (tg << 1);
            __half2 Ej = *(const __half2*)(esb + c);
            __half2 mk0 = h2rcp(__hfma2(Ej, Fi0, one2));
            __half2 mk1 = h2rcp(__hfma2(Ej, Fi1, one2));
            __half2 p0 = h2exp2(__floats2half2_rn(s[nt][0] - m0, s[nt][1] - m0));
            __half2 p1 = h2exp2(__floats2half2_rn(s[nt][2] - m1, s[nt][3] - m1));
            __half2 pm0 = __hmul2(p0, mk0);
            __half2 pm1 = __hmul2(p1, mk1);
            const int ks = nt >> 1, hi = (nt & 1) << 1;
            pa[ks][hi + 0] = *(uint32_t*)&pm0;
            pa[ks][hi + 1] = *(uint32_t*)&pm1;
        }

        // ---- lm += P @ ones  (row sums via tensor core) ----
        #pragma unroll
        for (int ks = 0; ks < 4; ks++) MMA_F16(lacc, pa[ks], ones_bf);

        // ---- O += P @ V^T ----
        #pragma unroll
        for (int ks = 0; ks < 4; ks++) {
            const int jrow = (ks << 4) + vt_jrow;
            uint32_t vf[8][2];
            #pragma unroll
            for (int np = 0; np < 4; np++) {
                int u = (np << 1) + vt_dhi;
                uint32_t addr = vb + jrow * 128 + ((u ^ (jrow & 7)) << 4);
                uint32_t t0, t1, t2, t3;
                LDSM_X4_T(t0, t1, t2, t3, addr);
                vf[np * 2 + 0][0] = t0; vf[np * 2 + 0][1] = t1;
                vf[np * 2 + 1][0] = t2; vf[np * 2 + 1][1] = t3;
            }
            #pragma unroll
            for (int dt = 0; dt < 8; dt++) MMA_F16(o[dt], pa[ks], vf[dt]);
        }
        buf++; if (buf == 3) buf = 0;
    }
    #undef STAGE_KV

    // lacc[0]/lacc[2] hold the full row sums (every column identical)
    const float inv0 = 1.0f / lacc[0];
    const float inv1 = 1.0f / lacc[2];

    const int r0 = rowbase + q0 + (warp << 4) + g;
    #pragma unroll
    for (int dt = 0; dt < 8; dt++) {
        int col = h * HD + (dt << 3) + (tg << 1);
        *(__half2*)&out[(size_t)r0 * DIM + col] =
            __floats2half2_rn(o[dt][0] * inv0, o[dt][1] * inv0);
        *(__half2*)&out[(size_t)(r0 + 8) * DIM + col] =
            __floats2half2_rn(o[dt][2] * inv1, o[dt][3] * inv1);
    }
}

// ---------------- launch ----------------
#define ATTN_SMEM (6 * KVTILE + AQT * 128 + 3 * AKT * 2)

extern "C" void kernel_launch(void* const* d_in, const int* in_sizes, int n_in,
                              void* d_out, int out_size)
{
    const float* x      = (const float*)d_in[0];
    const float* elev   = (const float*)d_in[1];
    const float* qkv_w  = (const float*)d_in[2];
    const float* qkv_b  = (const float*)d_in[3];
    const float* proj_w = (const float*)d_in[4];
    const float* proj_b = (const float*)d_in[5];
    const float* ln1_g  = (const float*)d_in[6];
    const float* ln1_b  = (const float*)d_in[7];
    const float* ln2_g  = (const float*)d_in[8];
    const float* ln2_b  = (const float*)d_in[9];
    const float* fc1_w  = (const float*)d_in[10];
    const float* fc1_b  = (const float*)d_in[11];
    const float* fc2_w  = (const float*)d_in[12];
    const float* fc2_b  = (const float*)d_in[13];
    const float* barrier= (const float*)d_in[14];
    float* out = (float*)d_out;

    const int rows = in_sizes[0] / DIM;     // B*N
    const int B = rows / NLEN;

    __half *h, *qkv, *attn, *ff, *wtq, *wtp, *wt1, *wt2;
    float *x2;
    cudaGetSymbolAddress((void**)&h,    g_h);
    cudaGetSymbolAddress((void**)&qkv,  g_qkv);
    cudaGetSymbolAddress((void**)&attn, g_attn);
    cudaGetSymbolAddress((void**)&x2,   g_x2);
    cudaGetSymbolAddress((void**)&ff,   g_ff);
    cudaGetSymbolAddress((void**)&wtq,  g_wt_qkv);
    cudaGetSymbolAddress((void**)&wtp,  g_wt_proj);
    cudaGetSymbolAddress((void**)&wt1,  g_wt_fc1);
    cudaGetSymbolAddress((void**)&wt2,  g_wt_fc2);

    cudaFuncSetAttribute(gemm_tc<0,1>, cudaFuncAttributeMaxDynamicSharedMemorySize, GEMM_SMEM);
    cudaFuncSetAttribute(gemm_tc<1,0>, cudaFuncAttributeMaxDynamicSharedMemorySize, GEMM_SMEM);
    cudaFuncSetAttribute(gemm_tc<2,1>, cudaFuncAttributeMaxDynamicSharedMemorySize, GEMM_SMEM);
    cudaFuncSetAttribute(attn_tc,      cudaFuncAttributeMaxDynamicSharedMemorySize, ATTN_SMEM);

    // 0. all weight transposes (+ fp16 convert), one launch
    transpose_all<<<6912, 256>>>(qkv_w, proj_w, fc1_w, fc2_w, wtq, wtp, wt1, wt2);

    // 1. LN1 (fp16 out)
    ln_kernel<<<rows / 8, 256>>>(x, ln1_g, ln1_b, h);
    // 2. QKV projection (fp16 out)
    gemm_tc<0,1><<<dim3(QKV_N / 128, rows / 128), 256, GEMM_SMEM>>>(h, wtq, qkv_b, nullptr, qkv, rows, QKV_N, DIM);
    // 3. fused masked flash attention (fp16 tensor cores, P in registers)
    attn_tc<<<dim3(B * HEADS, NLEN / AQT), ATHREADS, ATTN_SMEM>>>(qkv, elev, barrier, attn);
    // 4. out proj + residual (fp32 out)
    gemm_tc<1,0><<<dim3(DIM / 128, rows / 128), 256, GEMM_SMEM>>>(attn, wtp, proj_b, x, x2, rows, DIM, DIM);
    // 5. LN2 (fp16 out)
    ln_kernel<<<rows / 8, 256>>>(x2, ln2_g, ln2_b, h);
    // 6. FC1 + exact GELU (fp16 out)
    gemm_tc<2,1><<<dim3(HIDDEN / 128, rows / 128), 256, GEMM_SMEM>>>(h, wt1, fc1_b, nullptr, ff, rows, HIDDEN, DIM);
    // 7. FC2 + residual -> output (fp32)
    gemm_tc<1,0><<<dim3(DIM / 128, rows / 128), 256, GEMM_SMEM>>>(ff, wt2, fc2_b, x2, out, rows, DIM, HIDDEN);
}